// round 1
// baseline (speedup 1.0000x reference)
#include <cuda_runtime.h>
#include <math.h>

// ---------------------------------------------------------------------------
// SiglipEncoderLayer: B=8, S=1024, E=768, H=12, D=64, I=3072, fp32
// Round 1: correct SIMT fp32 baseline.
//   ln1 -> QKV gemms -> scores (QK^T*scale+mask) -> softmax -> PV -> O-proj
//   (+res) -> ln2 -> MLP gemm (gelu) -> MLP gemm (+res) -> out
// ---------------------------------------------------------------------------

#define BB   8
#define SS   1024
#define EE   768
#define HH   12
#define DD   64
#define II   3072
#define MROWS (BB*SS)          // 8192
#define EPSF 1e-6f
#define SCALE_F 0.125f          // 64^-0.5

// ---- scratch (device globals; no allocation allowed) ----------------------
__device__ float g_h [MROWS*EE];
__device__ float g_q [MROWS*EE];
__device__ float g_k [MROWS*EE];
__device__ float g_v [MROWS*EE];
__device__ float g_o [MROWS*EE];
__device__ float g_x [MROWS*EE];
__device__ float g_h2[MROWS*EE];
__device__ float g_m [(size_t)MROWS*II];
__device__ float g_sc[(size_t)BB*HH*SS*SS];   // 402 MB scores/probs

// ---------------------------------------------------------------------------
__device__ __forceinline__ float gelu_tanh(float x) {
    float x3 = x * x * x;
    float t  = tanhf(0.7978845608028654f * (x + 0.044715f * x3));
    return 0.5f * x * (1.0f + t);
}

// ---------------------------------------------------------------------------
// LayerNorm: one block (256 thr) per row of E=768
// ---------------------------------------------------------------------------
__global__ void ln_kernel(const float* __restrict__ x,
                          const float* __restrict__ g,
                          const float* __restrict__ b,
                          float* __restrict__ out) {
    int row = blockIdx.x;
    const float* xr = x + (size_t)row * EE;
    float* orow = out + (size_t)row * EE;

    float s = 0.f, s2 = 0.f;
    for (int i = threadIdx.x; i < EE; i += 256) {
        float v = xr[i];
        s += v; s2 += v * v;
    }
    __shared__ float rs[8], rs2[8];
    #pragma unroll
    for (int o = 16; o > 0; o >>= 1) {
        s  += __shfl_xor_sync(0xFFFFFFFFu, s,  o);
        s2 += __shfl_xor_sync(0xFFFFFFFFu, s2, o);
    }
    if ((threadIdx.x & 31) == 0) { rs[threadIdx.x >> 5] = s; rs2[threadIdx.x >> 5] = s2; }
    __syncthreads();
    float ts = 0.f, ts2 = 0.f;
    #pragma unroll
    for (int i = 0; i < 8; i++) { ts += rs[i]; ts2 += rs2[i]; }
    float mean = ts * (1.0f / EE);
    float var  = ts2 * (1.0f / EE) - mean * mean;
    float inv  = rsqrtf(var + EPSF);
    for (int i = threadIdx.x; i < EE; i += 256) {
        orow[i] = (xr[i] - mean) * inv * g[i] + b[i];
    }
}

// ---------------------------------------------------------------------------
// GEMM: C[M,N] = act(A[M,K] @ W[K,N] + bias) (+ res). 128x128x16 tiles,
// 256 threads, 8x8 per thread. M%128==0, N%128==0, K%16==0 guaranteed.
// ---------------------------------------------------------------------------
template<int ACT>
__global__ __launch_bounds__(256, 2)
void gemm_kernel(const float* __restrict__ A, const float* __restrict__ W,
                 const float* __restrict__ bias, const float* __restrict__ res,
                 float* __restrict__ C, int M, int N, int K) {
    const int BM = 128, BN = 128, BK = 16;
    __shared__ float As[BK][BM];
    __shared__ float Bs[BK][BN];

    int tid = threadIdx.x;
    int tx = tid & 15, ty = tid >> 4;
    int row0 = blockIdx.y * BM, col0 = blockIdx.x * BN;

    float acc[8][8];
    #pragma unroll
    for (int i = 0; i < 8; i++)
        #pragma unroll
        for (int j = 0; j < 8; j++) acc[i][j] = 0.f;

    for (int k0 = 0; k0 < K; k0 += BK) {
        // A tile: 128x16 floats = 512 float4; 2 per thread
        #pragma unroll
        for (int l = 0; l < 2; l++) {
            int f  = tid + l * 256;
            int r  = f >> 2;
            int kc = (f & 3) * 4;
            float4 v = *reinterpret_cast<const float4*>(
                &A[(size_t)(row0 + r) * K + k0 + kc]);
            As[kc + 0][r] = v.x; As[kc + 1][r] = v.y;
            As[kc + 2][r] = v.z; As[kc + 3][r] = v.w;
        }
        // W tile: 16x128 floats = 512 float4; 2 per thread
        #pragma unroll
        for (int l = 0; l < 2; l++) {
            int f  = tid + l * 256;
            int r  = f >> 5;
            int nc = (f & 31) * 4;
            *reinterpret_cast<float4*>(&Bs[r][nc]) =
                *reinterpret_cast<const float4*>(
                    &W[(size_t)(k0 + r) * N + col0 + nc]);
        }
        __syncthreads();
        #pragma unroll
        for (int k = 0; k < BK; k++) {
            float a[8], bb[8];
            #pragma unroll
            for (int i = 0; i < 8; i++) a[i]  = As[k][ty * 8 + i];
            #pragma unroll
            for (int j = 0; j < 8; j++) bb[j] = Bs[k][tx * 8 + j];
            #pragma unroll
            for (int i = 0; i < 8; i++)
                #pragma unroll
                for (int j = 0; j < 8; j++)
                    acc[i][j] += a[i] * bb[j];
        }
        __syncthreads();
    }

    // epilogue
    #pragma unroll
    for (int i = 0; i < 8; i++) {
        int r = row0 + ty * 8 + i;
        #pragma unroll
        for (int j = 0; j < 8; j += 4) {
            int c = col0 + tx * 8 + j;
            float4 o;
            float* po = &o.x;
            #pragma unroll
            for (int t = 0; t < 4; t++) {
                float val = acc[i][j + t] + bias[c + t];
                if (ACT == 1) val = gelu_tanh(val);
                po[t] = val;
            }
            if (res) {
                float4 rv = *reinterpret_cast<const float4*>(
                    &res[(size_t)r * N + c]);
                o.x += rv.x; o.y += rv.y; o.z += rv.z; o.w += rv.w;
            }
            *reinterpret_cast<float4*>(&C[(size_t)r * N + c]) = o;
        }
    }
}

// ---------------------------------------------------------------------------
// scores[bh,q,k] = scale * dot(Q[b,q,h,:], K[b,k,h,:]) + mask[b,q,k]
// grid: (S/64 [k-tile], S/64 [q-tile], B*H); 256 thr; 4x4 per thread
// ---------------------------------------------------------------------------
__global__ __launch_bounds__(256)
void scores_kernel(const float* __restrict__ Q, const float* __restrict__ K,
                   const float* __restrict__ mask, float* __restrict__ sc) {
    int bh = blockIdx.z;
    int b = bh / HH, h = bh - b * HH;
    int q0 = blockIdx.y * 64, k0 = blockIdx.x * 64;

    __shared__ float Qs[64][65];   // [d][q]
    __shared__ float Ks[64][65];   // [d][k]

    int tid = threadIdx.x;
    int tx = tid & 15, ty = tid >> 4;
    const size_t base = ((size_t)b * SS) * EE + (size_t)h * DD;

    #pragma unroll
    for (int l = 0; l < 4; l++) {
        int f  = tid + l * 256;
        int r  = f >> 4;
        int dc = (f & 15) * 4;
        float4 qv = *reinterpret_cast<const float4*>(
            &Q[base + (size_t)(q0 + r) * EE + dc]);
        Qs[dc + 0][r] = qv.x; Qs[dc + 1][r] = qv.y;
        Qs[dc + 2][r] = qv.z; Qs[dc + 3][r] = qv.w;
        float4 kv = *reinterpret_cast<const float4*>(
            &K[base + (size_t)(k0 + r) * EE + dc]);
        Ks[dc + 0][r] = kv.x; Ks[dc + 1][r] = kv.y;
        Ks[dc + 2][r] = kv.z; Ks[dc + 3][r] = kv.w;
    }
    __syncthreads();

    float acc[4][4];
    #pragma unroll
    for (int i = 0; i < 4; i++)
        #pragma unroll
        for (int j = 0; j < 4; j++) acc[i][j] = 0.f;

    #pragma unroll 8
    for (int d = 0; d < 64; d++) {
        float qa[4], kb[4];
        #pragma unroll
        for (int i = 0; i < 4; i++) qa[i] = Qs[d][ty * 4 + i];
        #pragma unroll
        for (int j = 0; j < 4; j++) kb[j] = Ks[d][tx * 4 + j];
        #pragma unroll
        for (int i = 0; i < 4; i++)
            #pragma unroll
            for (int j = 0; j < 4; j++)
                acc[i][j] += qa[i] * kb[j];
    }

    #pragma unroll
    for (int i = 0; i < 4; i++) {
        int qi = q0 + ty * 4 + i;
        size_t srow = ((size_t)bh * SS + qi) * SS;
        size_t mrow = ((size_t)b  * SS + qi) * SS;
        float4 mv = *reinterpret_cast<const float4*>(&mask[mrow + k0 + tx * 4]);
        float4 ov;
        ov.x = acc[i][0] * SCALE_F + mv.x;
        ov.y = acc[i][1] * SCALE_F + mv.y;
        ov.z = acc[i][2] * SCALE_F + mv.z;
        ov.w = acc[i][3] * SCALE_F + mv.w;
        *reinterpret_cast<float4*>(&sc[srow + k0 + tx * 4]) = ov;
    }
}

// ---------------------------------------------------------------------------
// row softmax over S=1024; one block (256 thr, 1 float4/thread) per row
// ---------------------------------------------------------------------------
__global__ __launch_bounds__(256)
void softmax_kernel(float* __restrict__ sc) {
    size_t row = blockIdx.x;
    float4* r = reinterpret_cast<float4*>(sc + row * (size_t)SS);
    float4 v = r[threadIdx.x];

    __shared__ float redm[8], reds[8];
    float m = fmaxf(fmaxf(v.x, v.y), fmaxf(v.z, v.w));
    #pragma unroll
    for (int o = 16; o > 0; o >>= 1) m = fmaxf(m, __shfl_xor_sync(0xFFFFFFFFu, m, o));
    if ((threadIdx.x & 31) == 0) redm[threadIdx.x >> 5] = m;
    __syncthreads();
    m = redm[0];
    #pragma unroll
    for (int i = 1; i < 8; i++) m = fmaxf(m, redm[i]);

    float4 e;
    e.x = __expf(v.x - m); e.y = __expf(v.y - m);
    e.z = __expf(v.z - m); e.w = __expf(v.w - m);
    float s = e.x + e.y + e.z + e.w;
    #pragma unroll
    for (int o = 16; o > 0; o >>= 1) s += __shfl_xor_sync(0xFFFFFFFFu, s, o);
    if ((threadIdx.x & 31) == 0) reds[threadIdx.x >> 5] = s;
    __syncthreads();
    s = 0.f;
    #pragma unroll
    for (int i = 0; i < 8; i++) s += reds[i];
    float inv = 1.0f / s;
    e.x *= inv; e.y *= inv; e.z *= inv; e.w *= inv;
    r[threadIdx.x] = e;
}

// ---------------------------------------------------------------------------
// O[b,q,h,:] = P[bh,q,:] @ V[b,:,h,:]   (M=64 q-tile, N=64, K=S=1024)
// grid: (S/64 [q-tile], B*H); 256 thr; 4x4 per thread
// ---------------------------------------------------------------------------
__global__ __launch_bounds__(256)
void attnv_kernel(const float* __restrict__ P, const float* __restrict__ V,
                  float* __restrict__ O) {
    int bh = blockIdx.y;
    int b = bh / HH, h = bh - b * HH;
    int q0 = blockIdx.x * 64;

    __shared__ float Ps[64][65];   // [k][q]
    __shared__ float Vs[64][64];   // [k][d]

    int tid = threadIdx.x;
    int tx = tid & 15, ty = tid >> 4;
    const size_t vbase = ((size_t)b * SS) * EE + (size_t)h * DD;

    float acc[4][4];
    #pragma unroll
    for (int i = 0; i < 4; i++)
        #pragma unroll
        for (int j = 0; j < 4; j++) acc[i][j] = 0.f;

    for (int kt = 0; kt < SS; kt += 64) {
        #pragma unroll
        for (int l = 0; l < 4; l++) {
            int f  = tid + l * 256;
            int r  = f >> 4;
            int cc = (f & 15) * 4;
            float4 pv = *reinterpret_cast<const float4*>(
                &P[((size_t)bh * SS + q0 + r) * SS + kt + cc]);
            Ps[cc + 0][r] = pv.x; Ps[cc + 1][r] = pv.y;
            Ps[cc + 2][r] = pv.z; Ps[cc + 3][r] = pv.w;
            *reinterpret_cast<float4*>(&Vs[r][cc]) =
                *reinterpret_cast<const float4*>(
                    &V[vbase + (size_t)(kt + r) * EE + cc]);
        }
        __syncthreads();
        #pragma unroll 8
        for (int kk = 0; kk < 64; kk++) {
            float pa[4], vb[4];
            #pragma unroll
            for (int i = 0; i < 4; i++) pa[i] = Ps[kk][ty * 4 + i];
            #pragma unroll
            for (int j = 0; j < 4; j++) vb[j] = Vs[kk][tx * 4 + j];
            #pragma unroll
            for (int i = 0; i < 4; i++)
                #pragma unroll
                for (int j = 0; j < 4; j++)
                    acc[i][j] += pa[i] * vb[j];
        }
        __syncthreads();
    }

    #pragma unroll
    for (int i = 0; i < 4; i++) {
        float4 ov = make_float4(acc[i][0], acc[i][1], acc[i][2], acc[i][3]);
        *reinterpret_cast<float4*>(
            &O[vbase + (size_t)(q0 + ty * 4 + i) * EE + tx * 4]) = ov;
    }
}

// ---------------------------------------------------------------------------
extern "C" void kernel_launch(void* const* d_in, const int* in_sizes, int n_in,
                              void* d_out, int out_size) {
    const float* hs    = (const float*)d_in[0];
    const float* mask  = (const float*)d_in[1];
    const float* wq    = (const float*)d_in[2];
    const float* bq    = (const float*)d_in[3];
    const float* wk    = (const float*)d_in[4];
    const float* bk    = (const float*)d_in[5];
    const float* wv    = (const float*)d_in[6];
    const float* bv    = (const float*)d_in[7];
    const float* wo    = (const float*)d_in[8];
    const float* bo    = (const float*)d_in[9];
    const float* ln1g  = (const float*)d_in[10];
    const float* ln1b  = (const float*)d_in[11];
    const float* ln2g  = (const float*)d_in[12];
    const float* ln2b  = (const float*)d_in[13];
    const float* w1    = (const float*)d_in[14];
    const float* b1    = (const float*)d_in[15];
    const float* w2    = (const float*)d_in[16];
    const float* b2    = (const float*)d_in[17];
    float* out = (float*)d_out;

    float *h, *q, *k, *v, *o, *x, *h2, *m, *sc;
    cudaGetSymbolAddress((void**)&h,  g_h);
    cudaGetSymbolAddress((void**)&q,  g_q);
    cudaGetSymbolAddress((void**)&k,  g_k);
    cudaGetSymbolAddress((void**)&v,  g_v);
    cudaGetSymbolAddress((void**)&o,  g_o);
    cudaGetSymbolAddress((void**)&x,  g_x);
    cudaGetSymbolAddress((void**)&h2, g_h2);
    cudaGetSymbolAddress((void**)&m,  g_m);
    cudaGetSymbolAddress((void**)&sc, g_sc);

    // 1. LN1
    ln_kernel<<<MROWS, 256>>>(hs, ln1g, ln1b, h);

    // 2. Q, K, V projections
    dim3 gproj(EE / 128, MROWS / 128);
    gemm_kernel<0><<<gproj, 256>>>(h, wq, bq, nullptr, q, MROWS, EE, EE);
    gemm_kernel<0><<<gproj, 256>>>(h, wk, bk, nullptr, k, MROWS, EE, EE);
    gemm_kernel<0><<<gproj, 256>>>(h, wv, bv, nullptr, v, MROWS, EE, EE);

    // 3. scores = QK^T * scale + mask
    scores_kernel<<<dim3(SS / 64, SS / 64, BB * HH), 256>>>(q, k, mask, sc);

    // 4. softmax
    softmax_kernel<<<BB * HH * SS, 256>>>(sc);

    // 5. O = P @ V
    attnv_kernel<<<dim3(SS / 64, BB * HH), 256>>>(sc, v, o);

    // 6. O-proj + residual
    gemm_kernel<0><<<gproj, 256>>>(o, wo, bo, hs, x, MROWS, EE, EE);

    // 7. LN2
    ln_kernel<<<MROWS, 256>>>(x, ln2g, ln2b, h2);

    // 8. MLP up + gelu
    gemm_kernel<1><<<dim3(II / 128, MROWS / 128), 256>>>(h2, w1, b1, nullptr, m,
                                                         MROWS, II, EE);
    // 9. MLP down + residual -> out
    gemm_kernel<0><<<dim3(EE / 128, MROWS / 128), 256>>>(m, w2, b2, x, out,
                                                         MROWS, EE, II);
}

// round 4
// speedup vs baseline: 1.8136x; 1.8136x over previous
#include <cuda_runtime.h>
#include <cuda_bf16.h>
#include <math.h>
#include <stdint.h>

// ---------------------------------------------------------------------------
// SiglipEncoderLayer  B=8 S=1024 E=768 H=12 D=64 I=3072  fp32 in/out
// R4: dense GEMMs on mma.sync.m16n8k16 bf16 (sm_100-portable tensor cores)
//     with hi/lo split packed as K'=3K. Attention SIMT fp32.
// ---------------------------------------------------------------------------

#define BB   8
#define SS   1024
#define EE   768
#define HH   12
#define DD   64
#define II   3072
#define MR   (BB*SS)            // 8192
#define K3E  (3*EE)             // 2304
#define K3I  (3*II)             // 9216
#define EPSF 1e-6f
#define SCALE_F 0.125f

// ---- scratch (device globals, 128B aligned) -------------------------------
__device__ __align__(128) float g_q [MR*EE];
__device__ __align__(128) float g_k [MR*EE];
__device__ __align__(128) float g_v [MR*EE];
__device__ __align__(128) float g_x [MR*EE];
__device__ __align__(128) float g_sc[(size_t)BB*HH*SS*SS];   // 402 MB

__device__ __align__(128) __nv_bfloat16 g_h1p[(size_t)MR*K3E];   // ln1 packed
__device__ __align__(128) __nv_bfloat16 g_h2p[(size_t)MR*K3E];   // ln2 packed
__device__ __align__(128) __nv_bfloat16 g_op [(size_t)MR*K3E];   // attn-out packed
__device__ __align__(128) __nv_bfloat16 g_mp [(size_t)MR*K3I];   // mlp-mid packed

// packed transposed weights: Wp[N][3K] = [Wh | Wh | Wl]
__device__ __align__(128) __nv_bfloat16 g_wqp[(size_t)EE*K3E];
__device__ __align__(128) __nv_bfloat16 g_wkp[(size_t)EE*K3E];
__device__ __align__(128) __nv_bfloat16 g_wvp[(size_t)EE*K3E];
__device__ __align__(128) __nv_bfloat16 g_wop[(size_t)EE*K3E];
__device__ __align__(128) __nv_bfloat16 g_w1p[(size_t)II*K3E];
__device__ __align__(128) __nv_bfloat16 g_w2p[(size_t)EE*K3I];

// ---------------------------------------------------------------------------
__device__ __forceinline__ uint32_t smem_u32(const void* p) {
    uint32_t a;
    asm("{ .reg .u64 t; cvta.to.shared.u64 t, %1; cvt.u32.u64 %0, t; }"
        : "=r"(a) : "l"(p));
    return a;
}
__device__ __forceinline__ void cp_async16(uint32_t s, const void* g) {
    asm volatile("cp.async.cg.shared.global [%0], [%1], 16;" :: "r"(s), "l"(g) : "memory");
}
#define CP_COMMIT() asm volatile("cp.async.commit_group;" ::: "memory")
#define CP_WAIT(n)  asm volatile("cp.async.wait_group %0;" :: "n"(n) : "memory")

__device__ __forceinline__ void ldsm4(uint32_t* r, uint32_t addr) {
    asm volatile("ldmatrix.sync.aligned.m8n8.x4.shared.b16 {%0,%1,%2,%3}, [%4];"
        : "=r"(r[0]), "=r"(r[1]), "=r"(r[2]), "=r"(r[3]) : "r"(addr));
}
__device__ __forceinline__ void mma16816(float* d, const uint32_t* a, const uint32_t* b) {
    asm volatile(
        "mma.sync.aligned.m16n8k16.row.col.f32.bf16.bf16.f32 "
        "{%0,%1,%2,%3}, {%4,%5,%6,%7}, {%8,%9}, {%0,%1,%2,%3};"
        : "+f"(d[0]), "+f"(d[1]), "+f"(d[2]), "+f"(d[3])
        : "r"(a[0]), "r"(a[1]), "r"(a[2]), "r"(a[3]), "r"(b[0]), "r"(b[1]));
}
__device__ __forceinline__ float gelu_tanh(float x) {
    float x3 = x * x * x;
    float t  = tanhf(0.7978845608028654f * (x + 0.044715f * x3));
    return 0.5f * x * (1.0f + t);
}
__device__ __forceinline__ void split_bf16(float v, __nv_bfloat16& h, __nv_bfloat16& l) {
    h = __float2bfloat16(v);
    l = __float2bfloat16(v - __bfloat162float(h));
}

// ---------------------------------------------------------------------------
// mma.sync GEMM: C[M,N] = A[M,K3] @ Wp[N,K3]^T (+bias / +res / gelu-pack)
//   MODE 0: outf = acc + bias
//   MODE 1: opk  = pack(split(gelu(acc + bias)))  (row width 3N: h, l, h)
//   MODE 2: outf = acc + bias + res
// Block 128x128, BK=32, 8 warps (4m x 2n), warp tile 32x64, cp.async x2.
// ---------------------------------------------------------------------------
template<int MODE>
__global__ __launch_bounds__(256)
void mma_gemm(const __nv_bfloat16* __restrict__ A,
              const __nv_bfloat16* __restrict__ W,
              const float* __restrict__ bias, const float* __restrict__ res,
              float* __restrict__ outf, __nv_bfloat16* __restrict__ opk,
              int M, int N, int K3) {
    __shared__ __align__(128) char smbuf[2][16384];     // per stage: A 8K + B 8K

    const int tid  = threadIdx.x;
    const int wid  = tid >> 5;
    const int lane = tid & 31;
    const int wm   = wid & 3;          // 0..3 (M direction, 32 rows each)
    const int wn   = wid >> 2;         // 0..1 (N direction, 64 cols each)
    const int m0   = blockIdx.y * 128;
    const int n0   = blockIdx.x * 128;

    const uint32_t sb = smem_u32(smbuf);

    float acc[2][8][4];
    #pragma unroll
    for (int mf = 0; mf < 2; mf++)
        #pragma unroll
        for (int nf = 0; nf < 8; nf++)
            #pragma unroll
            for (int r = 0; r < 4; r++) acc[mf][nf][r] = 0.f;

    const int nc = K3 >> 5;            // iterations of BK=32

    auto loadc = [&](int c, int s) {
        const int k0 = c << 5;
        uint32_t as = sb + s * 16384u;
        uint32_t bs = as + 8192u;
        #pragma unroll
        for (int i = 0; i < 2; i++) {
            int cid = tid + i * 256;
            int row = cid >> 2, ch = cid & 3;
            uint32_t soff = row * 64u + ((uint32_t)(ch ^ (row & 3)) << 4);
            cp_async16(as + soff, A + (size_t)(m0 + row) * K3 + k0 + ch * 8);
            cp_async16(bs + soff, W + (size_t)(n0 + row) * K3 + k0 + ch * 8);
        }
    };

    loadc(0, 0);
    CP_COMMIT();

    for (int c = 0; c < nc; c++) {
        const int s = c & 1;
        if (c + 1 < nc) {
            loadc(c + 1, s ^ 1);
            CP_COMMIT();
            CP_WAIT(1);
        } else {
            CP_WAIT(0);
        }
        __syncthreads();

        const uint32_t as = sb + s * 16384u;
        const uint32_t bs = as + 8192u;
        const int j = lane >> 3, r = lane & 7;

        #pragma unroll
        for (int ks = 0; ks < 2; ks++) {
            uint32_t af[2][4];
            #pragma unroll
            for (int mf = 0; mf < 2; mf++) {
                int row = wm * 32 + mf * 16 + (j & 1) * 8 + r;
                int kc  = ks * 2 + (j >> 1);
                ldsm4(af[mf], as + row * 64u + ((uint32_t)(kc ^ (row & 3)) << 4));
            }
            uint32_t bf[8][2];
            #pragma unroll
            for (int tp = 0; tp < 4; tp++) {
                int nrow = wn * 64 + tp * 16 + (j >> 1) * 8 + r;
                int kc   = ks * 2 + (j & 1);
                uint32_t t4[4];
                ldsm4(t4, bs + nrow * 64u + ((uint32_t)(kc ^ (nrow & 3)) << 4));
                bf[2*tp][0]   = t4[0]; bf[2*tp][1]   = t4[1];
                bf[2*tp+1][0] = t4[2]; bf[2*tp+1][1] = t4[3];
            }
            #pragma unroll
            for (int mf = 0; mf < 2; mf++)
                #pragma unroll
                for (int nf = 0; nf < 8; nf++)
                    mma16816(acc[mf][nf], af[mf], bf[nf]);
        }
        __syncthreads();
    }

    // epilogue
    const int gi = lane >> 2, ci = lane & 3;
    #pragma unroll
    for (int mf = 0; mf < 2; mf++) {
        int r0 = m0 + wm * 32 + mf * 16 + gi;
        #pragma unroll
        for (int nf = 0; nf < 8; nf++) {
            int col = n0 + wn * 64 + nf * 8 + ci * 2;
            float b0 = bias[col], b1 = bias[col + 1];
            float v00 = acc[mf][nf][0] + b0, v01 = acc[mf][nf][1] + b1;
            float v10 = acc[mf][nf][2] + b0, v11 = acc[mf][nf][3] + b1;
            if (MODE == 1) {
                v00 = gelu_tanh(v00); v01 = gelu_tanh(v01);
                v10 = gelu_tanh(v10); v11 = gelu_tanh(v11);
                __nv_bfloat16 h0,l0,h1,l1;
                size_t rw = (size_t)r0 * (3 * N) + col;
                split_bf16(v00, h0, l0); split_bf16(v01, h1, l1);
                *reinterpret_cast<__nv_bfloat162*>(opk + rw)         = __halves2bfloat162(h0, h1);
                *reinterpret_cast<__nv_bfloat162*>(opk + rw + N)     = __halves2bfloat162(l0, l1);
                *reinterpret_cast<__nv_bfloat162*>(opk + rw + 2*N)   = __halves2bfloat162(h0, h1);
                size_t rw2 = (size_t)(r0 + 8) * (3 * N) + col;
                split_bf16(v10, h0, l0); split_bf16(v11, h1, l1);
                *reinterpret_cast<__nv_bfloat162*>(opk + rw2)        = __halves2bfloat162(h0, h1);
                *reinterpret_cast<__nv_bfloat162*>(opk + rw2 + N)    = __halves2bfloat162(l0, l1);
                *reinterpret_cast<__nv_bfloat162*>(opk + rw2 + 2*N)  = __halves2bfloat162(h0, h1);
            } else {
                if (MODE == 2) {
                    const float2 r00 = *reinterpret_cast<const float2*>(res + (size_t)r0 * N + col);
                    const float2 r10 = *reinterpret_cast<const float2*>(res + (size_t)(r0 + 8) * N + col);
                    v00 += r00.x; v01 += r00.y; v10 += r10.x; v11 += r10.y;
                }
                *reinterpret_cast<float2*>(outf + (size_t)r0 * N + col)       = make_float2(v00, v01);
                *reinterpret_cast<float2*>(outf + (size_t)(r0 + 8) * N + col) = make_float2(v10, v11);
            }
        }
    }
}

// ---------------------------------------------------------------------------
// weight transpose + split + pack: W[K,N] -> Wp[N][3K] = [Wh | Wh | Wl]
// ---------------------------------------------------------------------------
__global__ void transpose_pack(const float* __restrict__ W,
                               __nv_bfloat16* __restrict__ wp,
                               int K, int N) {
    __shared__ float t[32][33];
    int tx = threadIdx.x, ty = threadIdx.y;
    int k0 = blockIdx.y * 32, n0 = blockIdx.x * 32;
    #pragma unroll
    for (int j = 0; j < 4; j++)
        t[ty + j*8][tx] = W[(size_t)(k0 + ty + j*8) * N + n0 + tx];
    __syncthreads();
    size_t K3 = 3 * (size_t)K;
    #pragma unroll
    for (int j = 0; j < 4; j++) {
        int nn = n0 + ty + j*8;
        int kk = k0 + tx;
        float v = t[tx][ty + j*8];
        __nv_bfloat16 h, l; split_bf16(v, h, l);
        wp[(size_t)nn * K3 + kk]         = h;
        wp[(size_t)nn * K3 + K + kk]     = h;
        wp[(size_t)nn * K3 + 2*K + kk]   = l;
    }
}

// ---------------------------------------------------------------------------
// LayerNorm -> packed activations [row][3E] = [h | l | h]
// ---------------------------------------------------------------------------
__global__ void ln_pack(const float* __restrict__ x,
                        const float* __restrict__ g,
                        const float* __restrict__ b,
                        __nv_bfloat16* __restrict__ pk) {
    int row = blockIdx.x;
    const float* xr = x + (size_t)row * EE;
    float s = 0.f, s2 = 0.f;
    for (int i = threadIdx.x; i < EE; i += 256) {
        float v = xr[i]; s += v; s2 += v * v;
    }
    __shared__ float rs[8], rs2[8];
    #pragma unroll
    for (int o = 16; o > 0; o >>= 1) {
        s  += __shfl_xor_sync(0xFFFFFFFFu, s,  o);
        s2 += __shfl_xor_sync(0xFFFFFFFFu, s2, o);
    }
    if ((threadIdx.x & 31) == 0) { rs[threadIdx.x>>5] = s; rs2[threadIdx.x>>5] = s2; }
    __syncthreads();
    float ts = 0.f, ts2 = 0.f;
    #pragma unroll
    for (int i = 0; i < 8; i++) { ts += rs[i]; ts2 += rs2[i]; }
    float mean = ts * (1.0f / EE);
    float var  = ts2 * (1.0f / EE) - mean * mean;
    float inv  = rsqrtf(var + EPSF);
    size_t rw = (size_t)row * K3E;
    for (int i = threadIdx.x; i < EE; i += 256) {
        float y = (xr[i] - mean) * inv * g[i] + b[i];
        __nv_bfloat16 h, l; split_bf16(y, h, l);
        pk[rw + i]          = h;
        pk[rw + EE + i]     = l;
        pk[rw + 2*EE + i]   = h;
    }
}

// ---------------------------------------------------------------------------
// scores = QK^T * scale + mask   (SIMT fp32)
// ---------------------------------------------------------------------------
__global__ __launch_bounds__(256)
void scores_kernel(const float* __restrict__ Q, const float* __restrict__ K,
                   const float* __restrict__ mask, float* __restrict__ sc) {
    int bh = blockIdx.z;
    int b = bh / HH, h = bh - b * HH;
    int q0 = blockIdx.y * 64, k0 = blockIdx.x * 64;
    __shared__ float Qs[64][65];
    __shared__ float Ks[64][65];
    int tid = threadIdx.x;
    int tx = tid & 15, ty = tid >> 4;
    const size_t base = ((size_t)b * SS) * EE + (size_t)h * DD;

    #pragma unroll
    for (int l = 0; l < 4; l++) {
        int f = tid + l * 256;
        int r = f >> 4;
        int dc = (f & 15) * 4;
        float4 qv = *reinterpret_cast<const float4*>(&Q[base + (size_t)(q0 + r) * EE + dc]);
        Qs[dc+0][r]=qv.x; Qs[dc+1][r]=qv.y; Qs[dc+2][r]=qv.z; Qs[dc+3][r]=qv.w;
        float4 kv = *reinterpret_cast<const float4*>(&K[base + (size_t)(k0 + r) * EE + dc]);
        Ks[dc+0][r]=kv.x; Ks[dc+1][r]=kv.y; Ks[dc+2][r]=kv.z; Ks[dc+3][r]=kv.w;
    }
    __syncthreads();
    float acc[4][4];
    #pragma unroll
    for (int i = 0; i < 4; i++)
        #pragma unroll
        for (int j = 0; j < 4; j++) acc[i][j] = 0.f;
    #pragma unroll 8
    for (int d = 0; d < 64; d++) {
        float qa[4], kb[4];
        #pragma unroll
        for (int i = 0; i < 4; i++) qa[i] = Qs[d][ty*4+i];
        #pragma unroll
        for (int j = 0; j < 4; j++) kb[j] = Ks[d][tx*4+j];
        #pragma unroll
        for (int i = 0; i < 4; i++)
            #pragma unroll
            for (int j = 0; j < 4; j++) acc[i][j] += qa[i] * kb[j];
    }
    #pragma unroll
    for (int i = 0; i < 4; i++) {
        int qi = q0 + ty*4 + i;
        size_t srow = ((size_t)bh * SS + qi) * SS;
        size_t mrow = ((size_t)b  * SS + qi) * SS;
        float4 mv = *reinterpret_cast<const float4*>(&mask[mrow + k0 + tx*4]);
        float4 ov;
        ov.x = acc[i][0]*SCALE_F + mv.x; ov.y = acc[i][1]*SCALE_F + mv.y;
        ov.z = acc[i][2]*SCALE_F + mv.z; ov.w = acc[i][3]*SCALE_F + mv.w;
        *reinterpret_cast<float4*>(&sc[srow + k0 + tx*4]) = ov;
    }
}

// ---------------------------------------------------------------------------
__global__ __launch_bounds__(256)
void softmax_kernel(float* __restrict__ sc) {
    size_t row = blockIdx.x;
    float4* r = reinterpret_cast<float4*>(sc + row * (size_t)SS);
    float4 v = r[threadIdx.x];
    __shared__ float redm[8], reds[8];
    float m = fmaxf(fmaxf(v.x, v.y), fmaxf(v.z, v.w));
    #pragma unroll
    for (int o = 16; o > 0; o >>= 1) m = fmaxf(m, __shfl_xor_sync(0xFFFFFFFFu, m, o));
    if ((threadIdx.x & 31) == 0) redm[threadIdx.x>>5] = m;
    __syncthreads();
    m = redm[0];
    #pragma unroll
    for (int i = 1; i < 8; i++) m = fmaxf(m, redm[i]);
    float4 e;
    e.x = __expf(v.x - m); e.y = __expf(v.y - m);
    e.z = __expf(v.z - m); e.w = __expf(v.w - m);
    float s = e.x + e.y + e.z + e.w;
    #pragma unroll
    for (int o = 16; o > 0; o >>= 1) s += __shfl_xor_sync(0xFFFFFFFFu, s, o);
    if ((threadIdx.x & 31) == 0) reds[threadIdx.x>>5] = s;
    __syncthreads();
    s = 0.f;
    #pragma unroll
    for (int i = 0; i < 8; i++) s += reds[i];
    float inv = 1.0f / s;
    e.x *= inv; e.y *= inv; e.z *= inv; e.w *= inv;
    r[threadIdx.x] = e;
}

// ---------------------------------------------------------------------------
// O = P @ V  -> packed bf16 [row][3E] = [h | l | h]
// ---------------------------------------------------------------------------
__global__ __launch_bounds__(256)
void attnv_kernel(const float* __restrict__ P, const float* __restrict__ V,
                  __nv_bfloat16* __restrict__ Op) {
    int bh = blockIdx.y;
    int b = bh / HH, h = bh - b * HH;
    int q0 = blockIdx.x * 64;
    __shared__ float Ps[64][65];
    __shared__ float Vs[64][64];
    int tid = threadIdx.x;
    int tx = tid & 15, ty = tid >> 4;
    const size_t vbase = ((size_t)b * SS) * EE + (size_t)h * DD;

    float acc[4][4];
    #pragma unroll
    for (int i = 0; i < 4; i++)
        #pragma unroll
        for (int j = 0; j < 4; j++) acc[i][j] = 0.f;

    for (int kt = 0; kt < SS; kt += 64) {
        #pragma unroll
        for (int l = 0; l < 4; l++) {
            int f = tid + l * 256;
            int r = f >> 4;
            int cc = (f & 15) * 4;
            float4 pv = *reinterpret_cast<const float4*>(
                &P[((size_t)bh * SS + q0 + r) * SS + kt + cc]);
            Ps[cc+0][r]=pv.x; Ps[cc+1][r]=pv.y; Ps[cc+2][r]=pv.z; Ps[cc+3][r]=pv.w;
            *reinterpret_cast<float4*>(&Vs[r][cc]) =
                *reinterpret_cast<const float4*>(&V[vbase + (size_t)(kt + r) * EE + cc]);
        }
        __syncthreads();
        #pragma unroll 8
        for (int kk = 0; kk < 64; kk++) {
            float pa[4], vb[4];
            #pragma unroll
            for (int i = 0; i < 4; i++) pa[i] = Ps[kk][ty*4+i];
            #pragma unroll
            for (int j = 0; j < 4; j++) vb[j] = Vs[kk][tx*4+j];
            #pragma unroll
            for (int i = 0; i < 4; i++)
                #pragma unroll
                for (int j = 0; j < 4; j++) acc[i][j] += pa[i] * vb[j];
        }
        __syncthreads();
    }
    #pragma unroll
    for (int i = 0; i < 4; i++) {
        int row = b * SS + q0 + ty*4 + i;
        int col = h * DD + tx*4;
        size_t rw = (size_t)row * K3E + col;
        #pragma unroll
        for (int j = 0; j < 4; j += 2) {
            __nv_bfloat16 h0,l0,h1,l1;
            split_bf16(acc[i][j],   h0, l0);
            split_bf16(acc[i][j+1], h1, l1);
            *reinterpret_cast<__nv_bfloat162*>(&Op[rw + j])            = __halves2bfloat162(h0, h1);
            *reinterpret_cast<__nv_bfloat162*>(&Op[rw + EE + j])       = __halves2bfloat162(l0, l1);
            *reinterpret_cast<__nv_bfloat162*>(&Op[rw + 2*EE + j])     = __halves2bfloat162(h0, h1);
        }
    }
}

// ---------------------------------------------------------------------------
extern "C" void kernel_launch(void* const* d_in, const int* in_sizes, int n_in,
                              void* d_out, int out_size) {
    const float* hs   = (const float*)d_in[0];
    const float* mask = (const float*)d_in[1];
    const float* wq   = (const float*)d_in[2];
    const float* bq   = (const float*)d_in[3];
    const float* wk   = (const float*)d_in[4];
    const float* bk   = (const float*)d_in[5];
    const float* wv   = (const float*)d_in[6];
    const float* bv   = (const float*)d_in[7];
    const float* wo   = (const float*)d_in[8];
    const float* bo   = (const float*)d_in[9];
    const float* ln1g = (const float*)d_in[10];
    const float* ln1b = (const float*)d_in[11];
    const float* ln2g = (const float*)d_in[12];
    const float* ln2b = (const float*)d_in[13];
    const float* w1   = (const float*)d_in[14];
    const float* b1   = (const float*)d_in[15];
    const float* w2   = (const float*)d_in[16];
    const float* b2   = (const float*)d_in[17];
    float* out = (float*)d_out;

    float *q, *k, *v, *x, *sc;
    __nv_bfloat16 *h1p, *h2p, *op, *mp, *wqp, *wkp, *wvp, *wop, *w1p, *w2p;
    cudaGetSymbolAddress((void**)&q,   g_q);
    cudaGetSymbolAddress((void**)&k,   g_k);
    cudaGetSymbolAddress((void**)&v,   g_v);
    cudaGetSymbolAddress((void**)&x,   g_x);
    cudaGetSymbolAddress((void**)&sc,  g_sc);
    cudaGetSymbolAddress((void**)&h1p, g_h1p);
    cudaGetSymbolAddress((void**)&h2p, g_h2p);
    cudaGetSymbolAddress((void**)&op,  g_op);
    cudaGetSymbolAddress((void**)&mp,  g_mp);
    cudaGetSymbolAddress((void**)&wqp, g_wqp);
    cudaGetSymbolAddress((void**)&wkp, g_wkp);
    cudaGetSymbolAddress((void**)&wvp, g_wvp);
    cudaGetSymbolAddress((void**)&wop, g_wop);
    cudaGetSymbolAddress((void**)&w1p, g_w1p);
    cudaGetSymbolAddress((void**)&w2p, g_w2p);

    dim3 tb(32, 8);
    transpose_pack<<<dim3(EE/32, EE/32), tb>>>(wq, wqp, EE, EE);
    transpose_pack<<<dim3(EE/32, EE/32), tb>>>(wk, wkp, EE, EE);
    transpose_pack<<<dim3(EE/32, EE/32), tb>>>(wv, wvp, EE, EE);
    transpose_pack<<<dim3(EE/32, EE/32), tb>>>(wo, wop, EE, EE);
    transpose_pack<<<dim3(II/32, EE/32), tb>>>(w1, w1p, EE, II);
    transpose_pack<<<dim3(EE/32, II/32), tb>>>(w2, w2p, II, EE);

    // 1. LN1 -> packed
    ln_pack<<<MR, 256>>>(hs, ln1g, ln1b, h1p);

    // 2. QKV projections (tensor core)
    dim3 gp(EE/128, MR/128);
    mma_gemm<0><<<gp, 256>>>(h1p, wqp, bq, nullptr, q, nullptr, MR, EE, K3E);
    mma_gemm<0><<<gp, 256>>>(h1p, wkp, bk, nullptr, k, nullptr, MR, EE, K3E);
    mma_gemm<0><<<gp, 256>>>(h1p, wvp, bv, nullptr, v, nullptr, MR, EE, K3E);

    // 3-5. attention (SIMT fp32)
    scores_kernel<<<dim3(SS/64, SS/64, BB*HH), 256>>>(q, k, mask, sc);
    softmax_kernel<<<BB*HH*SS, 256>>>(sc);
    attnv_kernel<<<dim3(SS/64, BB*HH), 256>>>(sc, v, op);

    // 6. O-proj + residual(hs) -> x
    mma_gemm<2><<<gp, 256>>>(op, wop, bo, hs, x, nullptr, MR, EE, K3E);

    // 7. LN2 -> packed
    ln_pack<<<MR, 256>>>(x, ln2g, ln2b, h2p);

    // 8. MLP up + gelu -> packed (row width 3*II)
    mma_gemm<1><<<dim3(II/128, MR/128), 256>>>(h2p, w1p, b1, nullptr, nullptr, mp, MR, II, K3E);

    // 9. MLP down + residual(x) -> out
    mma_gemm<2><<<dim3(EE/128, MR/128), 256>>>(mp, w2p, b2, x, out, nullptr, MR, EE, K3I);
}

// round 5
// speedup vs baseline: 2.4138x; 1.3309x over previous
#include <cuda_runtime.h>
#include <cuda_bf16.h>
#include <math.h>
#include <stdint.h>
#include <string.h>

// ---------------------------------------------------------------------------
// SiglipEncoderLayer  B=8 S=1024 E=768 H=12 D=64 I=3072  fp32 in/out
// R5: mma.sync bf16 split GEMMs + fused flash-attention (split precision,
//     online softmax, no materialized scores).
// ---------------------------------------------------------------------------

#define BB   8
#define SS   1024
#define EE   768
#define HH   12
#define DD   64
#define II   3072
#define MR   (BB*SS)            // 8192
#define K3E  (3*EE)             // 2304
#define K3I  (3*II)             // 9216
#define EPSF 1e-6f
#define SCALE_F 0.125f

// ---- scratch (device globals, 128B aligned) -------------------------------
__device__ __align__(128) float g_x [MR*EE];

__device__ __align__(128) __nv_bfloat16 g_h1p[(size_t)MR*K3E];   // ln1 packed
__device__ __align__(128) __nv_bfloat16 g_h2p[(size_t)MR*K3E];   // ln2 packed
__device__ __align__(128) __nv_bfloat16 g_qp [(size_t)MR*K3E];   // Q packed [h|l|h]
__device__ __align__(128) __nv_bfloat16 g_kp [(size_t)MR*K3E];   // K packed
__device__ __align__(128) __nv_bfloat16 g_vp [(size_t)MR*K3E];   // V packed
__device__ __align__(128) __nv_bfloat16 g_op [(size_t)MR*K3E];   // attn-out packed
__device__ __align__(128) __nv_bfloat16 g_mp [(size_t)MR*K3I];   // mlp-mid packed

// packed transposed weights: Wp[N][3K] = [Wh | Wh | Wl]
__device__ __align__(128) __nv_bfloat16 g_wqp[(size_t)EE*K3E];
__device__ __align__(128) __nv_bfloat16 g_wkp[(size_t)EE*K3E];
__device__ __align__(128) __nv_bfloat16 g_wvp[(size_t)EE*K3E];
__device__ __align__(128) __nv_bfloat16 g_wop[(size_t)EE*K3E];
__device__ __align__(128) __nv_bfloat16 g_w1p[(size_t)II*K3E];
__device__ __align__(128) __nv_bfloat16 g_w2p[(size_t)EE*K3I];

// ---------------------------------------------------------------------------
__device__ __forceinline__ uint32_t smem_u32(const void* p) {
    uint32_t a;
    asm("{ .reg .u64 t; cvta.to.shared.u64 t, %1; cvt.u32.u64 %0, t; }"
        : "=r"(a) : "l"(p));
    return a;
}
__device__ __forceinline__ void cp_async16(uint32_t s, const void* g) {
    asm volatile("cp.async.cg.shared.global [%0], [%1], 16;" :: "r"(s), "l"(g) : "memory");
}
#define CP_COMMIT() asm volatile("cp.async.commit_group;" ::: "memory")
#define CP_WAIT(n)  asm volatile("cp.async.wait_group %0;" :: "n"(n) : "memory")

__device__ __forceinline__ void ldsm4(uint32_t* r, uint32_t addr) {
    asm volatile("ldmatrix.sync.aligned.m8n8.x4.shared.b16 {%0,%1,%2,%3}, [%4];"
        : "=r"(r[0]), "=r"(r[1]), "=r"(r[2]), "=r"(r[3]) : "r"(addr));
}
__device__ __forceinline__ void ldsm4t(uint32_t* r, uint32_t addr) {
    asm volatile("ldmatrix.sync.aligned.m8n8.x4.trans.shared.b16 {%0,%1,%2,%3}, [%4];"
        : "=r"(r[0]), "=r"(r[1]), "=r"(r[2]), "=r"(r[3]) : "r"(addr));
}
__device__ __forceinline__ void mma16816(float* d, const uint32_t* a, const uint32_t* b) {
    asm volatile(
        "mma.sync.aligned.m16n8k16.row.col.f32.bf16.bf16.f32 "
        "{%0,%1,%2,%3}, {%4,%5,%6,%7}, {%8,%9}, {%0,%1,%2,%3};"
        : "+f"(d[0]), "+f"(d[1]), "+f"(d[2]), "+f"(d[3])
        : "r"(a[0]), "r"(a[1]), "r"(a[2]), "r"(a[3]), "r"(b[0]), "r"(b[1]));
}
__device__ __forceinline__ float gelu_tanh(float x) {
    float x3 = x * x * x;
    float t  = tanhf(0.7978845608028654f * (x + 0.044715f * x3));
    return 0.5f * x * (1.0f + t);
}
__device__ __forceinline__ void split_bf16(float v, __nv_bfloat16& h, __nv_bfloat16& l) {
    h = __float2bfloat16(v);
    l = __float2bfloat16(v - __bfloat162float(h));
}
__device__ __forceinline__ void split2(float x, float y, uint32_t& hi, uint32_t& lo) {
    __nv_bfloat16 hx, lx, hy, ly;
    split_bf16(x, hx, lx); split_bf16(y, hy, ly);
    __nv_bfloat162 H = __halves2bfloat162(hx, hy);
    __nv_bfloat162 L = __halves2bfloat162(lx, ly);
    hi = *reinterpret_cast<uint32_t*>(&H);
    lo = *reinterpret_cast<uint32_t*>(&L);
}

// ---------------------------------------------------------------------------
// mma.sync GEMM (same core as R4):
//   MODE 0: outf = acc + bias
//   MODE 1: opk  = pack(split(gelu(acc + bias)))   rows [h | l | h], width 3N
//   MODE 2: outf = acc + bias + res
//   MODE 3: opk  = pack(split(acc + bias))         rows [h | l | h], width 3N
// ---------------------------------------------------------------------------
template<int MODE>
__global__ __launch_bounds__(256)
void mma_gemm(const __nv_bfloat16* __restrict__ A,
              const __nv_bfloat16* __restrict__ W,
              const float* __restrict__ bias, const float* __restrict__ res,
              float* __restrict__ outf, __nv_bfloat16* __restrict__ opk,
              int M, int N, int K3) {
    __shared__ __align__(128) char smbuf[2][16384];

    const int tid  = threadIdx.x;
    const int wid  = tid >> 5;
    const int lane = tid & 31;
    const int wm   = wid & 3;
    const int wn   = wid >> 2;
    const int m0   = blockIdx.y * 128;
    const int n0   = blockIdx.x * 128;

    const uint32_t sb = smem_u32(smbuf);

    float acc[2][8][4];
    #pragma unroll
    for (int mf = 0; mf < 2; mf++)
        #pragma unroll
        for (int nf = 0; nf < 8; nf++)
            #pragma unroll
            for (int r = 0; r < 4; r++) acc[mf][nf][r] = 0.f;

    const int nc = K3 >> 5;

    auto loadc = [&](int c, int s) {
        const int k0 = c << 5;
        uint32_t as = sb + s * 16384u;
        uint32_t bs = as + 8192u;
        #pragma unroll
        for (int i = 0; i < 2; i++) {
            int cid = tid + i * 256;
            int row = cid >> 2, ch = cid & 3;
            uint32_t soff = row * 64u + ((uint32_t)(ch ^ (row & 3)) << 4);
            cp_async16(as + soff, A + (size_t)(m0 + row) * K3 + k0 + ch * 8);
            cp_async16(bs + soff, W + (size_t)(n0 + row) * K3 + k0 + ch * 8);
        }
    };

    loadc(0, 0);
    CP_COMMIT();

    for (int c = 0; c < nc; c++) {
        const int s = c & 1;
        if (c + 1 < nc) { loadc(c + 1, s ^ 1); CP_COMMIT(); CP_WAIT(1); }
        else            { CP_WAIT(0); }
        __syncthreads();

        const uint32_t as = sb + s * 16384u;
        const uint32_t bs = as + 8192u;
        const int j = lane >> 3, r = lane & 7;

        #pragma unroll
        for (int ks = 0; ks < 2; ks++) {
            uint32_t af[2][4];
            #pragma unroll
            for (int mf = 0; mf < 2; mf++) {
                int row = wm * 32 + mf * 16 + (j & 1) * 8 + r;
                int kc  = ks * 2 + (j >> 1);
                ldsm4(af[mf], as + row * 64u + ((uint32_t)(kc ^ (row & 3)) << 4));
            }
            uint32_t bf[8][2];
            #pragma unroll
            for (int tp = 0; tp < 4; tp++) {
                int nrow = wn * 64 + tp * 16 + (j >> 1) * 8 + r;
                int kc   = ks * 2 + (j & 1);
                uint32_t t4[4];
                ldsm4(t4, bs + nrow * 64u + ((uint32_t)(kc ^ (nrow & 3)) << 4));
                bf[2*tp][0]   = t4[0]; bf[2*tp][1]   = t4[1];
                bf[2*tp+1][0] = t4[2]; bf[2*tp+1][1] = t4[3];
            }
            #pragma unroll
            for (int mf = 0; mf < 2; mf++)
                #pragma unroll
                for (int nf = 0; nf < 8; nf++)
                    mma16816(acc[mf][nf], af[mf], bf[nf]);
        }
        __syncthreads();
    }

    const int gi = lane >> 2, ci = lane & 3;
    #pragma unroll
    for (int mf = 0; mf < 2; mf++) {
        int r0 = m0 + wm * 32 + mf * 16 + gi;
        #pragma unroll
        for (int nf = 0; nf < 8; nf++) {
            int col = n0 + wn * 64 + nf * 8 + ci * 2;
            float b0 = bias[col], b1 = bias[col + 1];
            float v00 = acc[mf][nf][0] + b0, v01 = acc[mf][nf][1] + b1;
            float v10 = acc[mf][nf][2] + b0, v11 = acc[mf][nf][3] + b1;
            if (MODE == 1 || MODE == 3) {
                if (MODE == 1) {
                    v00 = gelu_tanh(v00); v01 = gelu_tanh(v01);
                    v10 = gelu_tanh(v10); v11 = gelu_tanh(v11);
                }
                __nv_bfloat16 h0,l0,h1,l1;
                size_t rw = (size_t)r0 * (3 * N) + col;
                split_bf16(v00, h0, l0); split_bf16(v01, h1, l1);
                *reinterpret_cast<__nv_bfloat162*>(opk + rw)       = __halves2bfloat162(h0, h1);
                *reinterpret_cast<__nv_bfloat162*>(opk + rw + N)   = __halves2bfloat162(l0, l1);
                *reinterpret_cast<__nv_bfloat162*>(opk + rw + 2*N) = __halves2bfloat162(h0, h1);
                size_t rw2 = (size_t)(r0 + 8) * (3 * N) + col;
                split_bf16(v10, h0, l0); split_bf16(v11, h1, l1);
                *reinterpret_cast<__nv_bfloat162*>(opk + rw2)       = __halves2bfloat162(h0, h1);
                *reinterpret_cast<__nv_bfloat162*>(opk + rw2 + N)   = __halves2bfloat162(l0, l1);
                *reinterpret_cast<__nv_bfloat162*>(opk + rw2 + 2*N) = __halves2bfloat162(h0, h1);
            } else {
                if (MODE == 2) {
                    const float2 r00 = *reinterpret_cast<const float2*>(res + (size_t)r0 * N + col);
                    const float2 r10 = *reinterpret_cast<const float2*>(res + (size_t)(r0 + 8) * N + col);
                    v00 += r00.x; v01 += r00.y; v10 += r10.x; v11 += r10.y;
                }
                *reinterpret_cast<float2*>(outf + (size_t)r0 * N + col)       = make_float2(v00, v01);
                *reinterpret_cast<float2*>(outf + (size_t)(r0 + 8) * N + col) = make_float2(v10, v11);
            }
        }
    }
}

// ---------------------------------------------------------------------------
// Fused flash attention.
//   Inputs: Qp/Kp/Vp packed [row][3E] = [h | l | h]; per-head slices: hi at
//   col h*64, lo at EE + h*64.
//   Block: (q-tile 128) x (bh). 8 warps; warp w owns q rows w*16..w*16+16,
//   full 128-key width. K-iter: 128 keys, double-buffered cp.async stages.
//   S = Qh.Kh + Ql.Kh + Qh.Kl (fp32 acc); online softmax; P split hi/lo;
//   O += Ph.Vh + Pl.Vh + Ph.Vl.  Output packed [h|l|h] to Op.
// ---------------------------------------------------------------------------
#define FA_SMEM (32768 + 2*65536)     // Q(h,l) + 2 stages of {Kh,Kl,Vh,Vl}

__global__ __launch_bounds__(256, 1)
void flash_attn(const __nv_bfloat16* __restrict__ Qp,
                const __nv_bfloat16* __restrict__ Kp,
                const __nv_bfloat16* __restrict__ Vp,
                const float* __restrict__ mask,
                __nv_bfloat16* __restrict__ Op) {
    extern __shared__ __align__(128) char fsm[];
    const uint32_t sb = smem_u32(fsm);
    const int tid = threadIdx.x, wid = tid >> 5, lane = tid & 31;
    const int qt = blockIdx.x, bh = blockIdx.y;
    const int b = bh / HH, h = bh - b * HH;
    const int q0 = qt * 128;
    const int j = lane >> 3, r = lane & 7;
    const int gi = lane >> 2, ci = lane & 3;

    const uint32_t sQh = sb, sQl = sb + 16384u;
    const uint32_t stg0 = sb + 32768u;

    // ---- load Q tiles (hi, lo), swizzled 128B rows -------------------------
    {
        const size_t rbase = (size_t)(b * SS + q0);
        #pragma unroll
        for (int i = 0; i < 4; i++) {
            int idx = tid + i * 256;
            int row = idx >> 3, ch = idx & 7;
            uint32_t d = row * 128u + ((uint32_t)(ch ^ (row & 7)) << 4);
            const __nv_bfloat16* g = Qp + (rbase + row) * K3E + h * DD + ch * 8;
            cp_async16(sQh + d, g);
            cp_async16(sQl + d, g + EE);
        }
    }
    auto loadKV = [&](int it, int st) {
        const size_t rbase = (size_t)(b * SS + it * 128);
        uint32_t base = stg0 + st * 65536u;
        const __nv_bfloat16* s0 = Kp + h * DD;        // Kh
        const __nv_bfloat16* s1 = Kp + EE + h * DD;   // Kl
        const __nv_bfloat16* s2 = Vp + h * DD;        // Vh
        const __nv_bfloat16* s3 = Vp + EE + h * DD;   // Vl
        #pragma unroll
        for (int i = 0; i < 4; i++) {
            int idx = tid + i * 256;
            int row = idx >> 3, ch = idx & 7;
            size_t go = (rbase + row) * (size_t)K3E + ch * 8;
            uint32_t d = base + row * 128u + ((uint32_t)(ch ^ (row & 7)) << 4);
            cp_async16(d,           s0 + go);
            cp_async16(d + 16384u,  s1 + go);
            cp_async16(d + 32768u,  s2 + go);
            cp_async16(d + 49152u,  s3 + go);
        }
    };

    loadKV(0, 0);
    CP_COMMIT();

    float m0v = -1e30f, m1v = -1e30f, l0 = 0.f, l1 = 0.f;
    float o[8][4];
    #pragma unroll
    for (int nt = 0; nt < 8; nt++)
        #pragma unroll
        for (int t = 0; t < 4; t++) o[nt][t] = 0.f;

    const int NIT = SS / 128;       // 8
    for (int it = 0; it < NIT; it++) {
        const int st = it & 1;
        if (it + 1 < NIT) { loadKV(it + 1, st ^ 1); CP_COMMIT(); CP_WAIT(1); }
        else              { CP_WAIT(0); }
        __syncthreads();

        const uint32_t kb = stg0 + st * 65536u;

        // ---- S = Q.K^T (3-section split) ----------------------------------
        float s[16][4];
        #pragma unroll
        for (int t = 0; t < 16; t++)
            #pragma unroll
            for (int u = 0; u < 4; u++) s[t][u] = 0.f;

        #pragma unroll
        for (int sec = 0; sec < 3; sec++) {
            const uint32_t qb = (sec == 1) ? sQl : sQh;
            const uint32_t kk = kb + ((sec == 2) ? 16384u : 0u);
            #pragma unroll
            for (int kc = 0; kc < 4; kc++) {
                uint32_t af[4];
                int arow = wid * 16 + (j & 1) * 8 + r;
                int ach  = kc * 2 + (j >> 1);
                ldsm4(af, qb + arow * 128u + ((uint32_t)(ach ^ (arow & 7)) << 4));
                #pragma unroll
                for (int nt2 = 0; nt2 < 8; nt2++) {
                    int brow = nt2 * 16 + (j >> 1) * 8 + r;
                    int bch  = kc * 2 + (j & 1);
                    uint32_t t4[4];
                    ldsm4(t4, kk + brow * 128u + ((uint32_t)(bch ^ (brow & 7)) << 4));
                    uint32_t b0[2] = {t4[0], t4[1]}, b1[2] = {t4[2], t4[3]};
                    mma16816(s[2*nt2],   af, b0);
                    mma16816(s[2*nt2+1], af, b1);
                }
            }
        }

        // ---- scale + mask + online softmax --------------------------------
        const float* mr0 = mask + ((size_t)b * SS + (q0 + wid * 16 + gi)) * SS + it * 128;
        const float* mr1 = mr0 + 8 * (size_t)SS;
        float mx0 = -1e30f, mx1 = -1e30f;
        #pragma unroll
        for (int t = 0; t < 16; t++) {
            float2 u0 = *reinterpret_cast<const float2*>(mr0 + t * 8 + ci * 2);
            float2 u1 = *reinterpret_cast<const float2*>(mr1 + t * 8 + ci * 2);
            s[t][0] = s[t][0] * SCALE_F + u0.x;
            s[t][1] = s[t][1] * SCALE_F + u0.y;
            s[t][2] = s[t][2] * SCALE_F + u1.x;
            s[t][3] = s[t][3] * SCALE_F + u1.y;
            mx0 = fmaxf(mx0, fmaxf(s[t][0], s[t][1]));
            mx1 = fmaxf(mx1, fmaxf(s[t][2], s[t][3]));
        }
        mx0 = fmaxf(mx0, __shfl_xor_sync(0xFFFFFFFFu, mx0, 1));
        mx0 = fmaxf(mx0, __shfl_xor_sync(0xFFFFFFFFu, mx0, 2));
        mx1 = fmaxf(mx1, __shfl_xor_sync(0xFFFFFFFFu, mx1, 1));
        mx1 = fmaxf(mx1, __shfl_xor_sync(0xFFFFFFFFu, mx1, 2));
        const float mn0 = fmaxf(m0v, mx0), mn1 = fmaxf(m1v, mx1);
        const float a0 = __expf(m0v - mn0), a1 = __expf(m1v - mn1);
        m0v = mn0; m1v = mn1;

        float ps0 = 0.f, ps1 = 0.f;
        #pragma unroll
        for (int t = 0; t < 16; t++) {
            s[t][0] = __expf(s[t][0] - mn0);
            s[t][1] = __expf(s[t][1] - mn0);
            s[t][2] = __expf(s[t][2] - mn1);
            s[t][3] = __expf(s[t][3] - mn1);
            ps0 += s[t][0] + s[t][1];
            ps1 += s[t][2] + s[t][3];
        }
        ps0 += __shfl_xor_sync(0xFFFFFFFFu, ps0, 1);
        ps0 += __shfl_xor_sync(0xFFFFFFFFu, ps0, 2);
        ps1 += __shfl_xor_sync(0xFFFFFFFFu, ps1, 1);
        ps1 += __shfl_xor_sync(0xFFFFFFFFu, ps1, 2);
        l0 = l0 * a0 + ps0;
        l1 = l1 * a1 + ps1;

        #pragma unroll
        for (int nt = 0; nt < 8; nt++) {
            o[nt][0] *= a0; o[nt][1] *= a0;
            o[nt][2] *= a1; o[nt][3] *= a1;
        }

        // ---- O += P.V (split: Ph.Vh + Pl.Vh + Ph.Vl) ----------------------
        const uint32_t vh = kb + 32768u, vl = kb + 49152u;
        #pragma unroll
        for (int kt = 0; kt < 8; kt++) {
            uint32_t ph[4], pl[4];
            split2(s[2*kt][0],   s[2*kt][1],   ph[0], pl[0]);
            split2(s[2*kt][2],   s[2*kt][3],   ph[1], pl[1]);
            split2(s[2*kt+1][0], s[2*kt+1][1], ph[2], pl[2]);
            split2(s[2*kt+1][2], s[2*kt+1][3], ph[3], pl[3]);
            #pragma unroll
            for (int nt2 = 0; nt2 < 4; nt2++) {
                int vrow = kt * 16 + (j & 1) * 8 + r;
                int vch  = nt2 * 2 + (j >> 1);
                uint32_t sw = vrow * 128u + ((uint32_t)(vch ^ (vrow & 7)) << 4);
                uint32_t t4[4];
                ldsm4t(t4, vh + sw);
                uint32_t b0[2] = {t4[0], t4[1]}, b1[2] = {t4[2], t4[3]};
                mma16816(o[2*nt2],   ph, b0);
                mma16816(o[2*nt2+1], ph, b1);
                mma16816(o[2*nt2],   pl, b0);
                mma16816(o[2*nt2+1], pl, b1);
                ldsm4t(t4, vl + sw);
                uint32_t c0[2] = {t4[0], t4[1]}, c1[2] = {t4[2], t4[3]};
                mma16816(o[2*nt2],   ph, c0);
                mma16816(o[2*nt2+1], ph, c1);
            }
        }
        __syncthreads();
    }

    // ---- normalize + write packed [h|l|h] ---------------------------------
    const float inv0 = 1.f / l0, inv1 = 1.f / l1;
    const int qrow = b * SS + q0 + wid * 16 + gi;
    #pragma unroll
    for (int nt = 0; nt < 8; nt++) {
        int col = h * DD + nt * 8 + ci * 2;
        float v00 = o[nt][0] * inv0, v01 = o[nt][1] * inv0;
        float v10 = o[nt][2] * inv1, v11 = o[nt][3] * inv1;
        size_t rw0 = (size_t)qrow * K3E + col;
        size_t rw1 = (size_t)(qrow + 8) * K3E + col;
        __nv_bfloat16 h0, lo0, h1, lo1;
        split_bf16(v00, h0, lo0); split_bf16(v01, h1, lo1);
        *reinterpret_cast<__nv_bfloat162*>(Op + rw0)        = __halves2bfloat162(h0, h1);
        *reinterpret_cast<__nv_bfloat162*>(Op + rw0 + EE)   = __halves2bfloat162(lo0, lo1);
        *reinterpret_cast<__nv_bfloat162*>(Op + rw0 + 2*EE) = __halves2bfloat162(h0, h1);
        split_bf16(v10, h0, lo0); split_bf16(v11, h1, lo1);
        *reinterpret_cast<__nv_bfloat162*>(Op + rw1)        = __halves2bfloat162(h0, h1);
        *reinterpret_cast<__nv_bfloat162*>(Op + rw1 + EE)   = __halves2bfloat162(lo0, lo1);
        *reinterpret_cast<__nv_bfloat162*>(Op + rw1 + 2*EE) = __halves2bfloat162(h0, h1);
    }
}

// ---------------------------------------------------------------------------
__global__ void transpose_pack(const float* __restrict__ W,
                               __nv_bfloat16* __restrict__ wp,
                               int K, int N) {
    __shared__ float t[32][33];
    int tx = threadIdx.x, ty = threadIdx.y;
    int k0 = blockIdx.y * 32, n0 = blockIdx.x * 32;
    #pragma unroll
    for (int j = 0; j < 4; j++)
        t[ty + j*8][tx] = W[(size_t)(k0 + ty + j*8) * N + n0 + tx];
    __syncthreads();
    size_t K3 = 3 * (size_t)K;
    #pragma unroll
    for (int j = 0; j < 4; j++) {
        int nn = n0 + ty + j*8;
        int kk = k0 + tx;
        float v = t[tx][ty + j*8];
        __nv_bfloat16 h, l; split_bf16(v, h, l);
        wp[(size_t)nn * K3 + kk]       = h;
        wp[(size_t)nn * K3 + K + kk]   = h;
        wp[(size_t)nn * K3 + 2*K + kk] = l;
    }
}

// ---------------------------------------------------------------------------
__global__ void ln_pack(const float* __restrict__ x,
                        const float* __restrict__ g,
                        const float* __restrict__ b,
                        __nv_bfloat16* __restrict__ pk) {
    int row = blockIdx.x;
    const float* xr = x + (size_t)row * EE;
    float s = 0.f, s2 = 0.f;
    for (int i = threadIdx.x; i < EE; i += 256) {
        float v = xr[i]; s += v; s2 += v * v;
    }
    __shared__ float rs[8], rs2[8];
    #pragma unroll
    for (int o = 16; o > 0; o >>= 1) {
        s  += __shfl_xor_sync(0xFFFFFFFFu, s,  o);
        s2 += __shfl_xor_sync(0xFFFFFFFFu, s2, o);
    }
    if ((threadIdx.x & 31) == 0) { rs[threadIdx.x>>5] = s; rs2[threadIdx.x>>5] = s2; }
    __syncthreads();
    float ts = 0.f, ts2 = 0.f;
    #pragma unroll
    for (int i = 0; i < 8; i++) { ts += rs[i]; ts2 += rs2[i]; }
    float mean = ts * (1.0f / EE);
    float var  = ts2 * (1.0f / EE) - mean * mean;
    float inv  = rsqrtf(var + EPSF);
    size_t rw = (size_t)row * K3E;
    for (int i = threadIdx.x; i < EE; i += 256) {
        float y = (xr[i] - mean) * inv * g[i] + b[i];
        __nv_bfloat16 h, l; split_bf16(y, h, l);
        pk[rw + i]        = h;
        pk[rw + EE + i]   = l;
        pk[rw + 2*EE + i] = h;
    }
}

// ---------------------------------------------------------------------------
extern "C" void kernel_launch(void* const* d_in, const int* in_sizes, int n_in,
                              void* d_out, int out_size) {
    const float* hs   = (const float*)d_in[0];
    const float* mask = (const float*)d_in[1];
    const float* wq   = (const float*)d_in[2];
    const float* bq   = (const float*)d_in[3];
    const float* wk   = (const float*)d_in[4];
    const float* bk   = (const float*)d_in[5];
    const float* wv   = (const float*)d_in[6];
    const float* bv   = (const float*)d_in[7];
    const float* wo   = (const float*)d_in[8];
    const float* bo   = (const float*)d_in[9];
    const float* ln1g = (const float*)d_in[10];
    const float* ln1b = (const float*)d_in[11];
    const float* ln2g = (const float*)d_in[12];
    const float* ln2b = (const float*)d_in[13];
    const float* w1   = (const float*)d_in[14];
    const float* b1   = (const float*)d_in[15];
    const float* w2   = (const float*)d_in[16];
    const float* b2   = (const float*)d_in[17];
    float* out = (float*)d_out;

    float *x;
    __nv_bfloat16 *h1p, *h2p, *qp, *kp, *vp, *op, *mp;
    __nv_bfloat16 *wqp, *wkp, *wvp, *wop, *w1p, *w2p;
    cudaGetSymbolAddress((void**)&x,   g_x);
    cudaGetSymbolAddress((void**)&h1p, g_h1p);
    cudaGetSymbolAddress((void**)&h2p, g_h2p);
    cudaGetSymbolAddress((void**)&qp,  g_qp);
    cudaGetSymbolAddress((void**)&kp,  g_kp);
    cudaGetSymbolAddress((void**)&vp,  g_vp);
    cudaGetSymbolAddress((void**)&op,  g_op);
    cudaGetSymbolAddress((void**)&mp,  g_mp);
    cudaGetSymbolAddress((void**)&wqp, g_wqp);
    cudaGetSymbolAddress((void**)&wkp, g_wkp);
    cudaGetSymbolAddress((void**)&wvp, g_wvp);
    cudaGetSymbolAddress((void**)&wop, g_wop);
    cudaGetSymbolAddress((void**)&w1p, g_w1p);
    cudaGetSymbolAddress((void**)&w2p, g_w2p);

    cudaFuncSetAttribute(flash_attn, cudaFuncAttributeMaxDynamicSharedMemorySize, FA_SMEM);

    dim3 tb(32, 8);
    transpose_pack<<<dim3(EE/32, EE/32), tb>>>(wq, wqp, EE, EE);
    transpose_pack<<<dim3(EE/32, EE/32), tb>>>(wk, wkp, EE, EE);
    transpose_pack<<<dim3(EE/32, EE/32), tb>>>(wv, wvp, EE, EE);
    transpose_pack<<<dim3(EE/32, EE/32), tb>>>(wo, wop, EE, EE);
    transpose_pack<<<dim3(II/32, EE/32), tb>>>(w1, w1p, EE, II);
    transpose_pack<<<dim3(EE/32, II/32), tb>>>(w2, w2p, II, EE);

    // 1. LN1 -> packed
    ln_pack<<<MR, 256>>>(hs, ln1g, ln1b, h1p);

    // 2. QKV projections -> packed split bf16 (no fp32 intermediate)
    dim3 gp(EE/128, MR/128);
    mma_gemm<3><<<gp, 256>>>(h1p, wqp, bq, nullptr, nullptr, qp, MR, EE, K3E);
    mma_gemm<3><<<gp, 256>>>(h1p, wkp, bk, nullptr, nullptr, kp, MR, EE, K3E);
    mma_gemm<3><<<gp, 256>>>(h1p, wvp, bv, nullptr, nullptr, vp, MR, EE, K3E);

    // 3. fused flash attention -> packed attn-out
    flash_attn<<<dim3(SS/128, BB*HH), 256, FA_SMEM>>>(qp, kp, vp, mask, op);

    // 4. O-proj + residual(hs) -> x
    mma_gemm<2><<<gp, 256>>>(op, wop, bo, hs, x, nullptr, MR, EE, K3E);

    // 5. LN2 -> packed
    ln_pack<<<MR, 256>>>(x, ln2g, ln2b, h2p);

    // 6. MLP up + gelu -> packed
    mma_gemm<1><<<dim3(II/128, MR/128), 256>>>(h2p, w1p, b1, nullptr, nullptr, mp, MR, II, K3E);

    // 7. MLP down + residual(x) -> out
    mma_gemm<2><<<dim3(EE/128, MR/128), 256>>>(mp, w2p, b2, x, out, nullptr, MR, EE, K3I);
}

// round 6
// speedup vs baseline: 2.4289x; 1.0063x over previous
#include <cuda_runtime.h>
#include <cuda_bf16.h>
#include <math.h>
#include <stdint.h>
#include <string.h>

// ---------------------------------------------------------------------------
// SiglipEncoderLayer  B=8 S=1024 E=768 H=12 D=64 I=3072  fp32 in/out
// R6: R5 + mma_gemm 4-stage cp.async ring + 2 CTAs/SM.
// ---------------------------------------------------------------------------

#define BB   8
#define SS   1024
#define EE   768
#define HH   12
#define DD   64
#define II   3072
#define MR   (BB*SS)            // 8192
#define K3E  (3*EE)             // 2304
#define K3I  (3*II)             // 9216
#define EPSF 1e-6f
#define SCALE_F 0.125f

// ---- scratch (device globals, 128B aligned) -------------------------------
__device__ __align__(128) float g_x [MR*EE];

__device__ __align__(128) __nv_bfloat16 g_h1p[(size_t)MR*K3E];
__device__ __align__(128) __nv_bfloat16 g_h2p[(size_t)MR*K3E];
__device__ __align__(128) __nv_bfloat16 g_qp [(size_t)MR*K3E];
__device__ __align__(128) __nv_bfloat16 g_kp [(size_t)MR*K3E];
__device__ __align__(128) __nv_bfloat16 g_vp [(size_t)MR*K3E];
__device__ __align__(128) __nv_bfloat16 g_op [(size_t)MR*K3E];
__device__ __align__(128) __nv_bfloat16 g_mp [(size_t)MR*K3I];

__device__ __align__(128) __nv_bfloat16 g_wqp[(size_t)EE*K3E];
__device__ __align__(128) __nv_bfloat16 g_wkp[(size_t)EE*K3E];
__device__ __align__(128) __nv_bfloat16 g_wvp[(size_t)EE*K3E];
__device__ __align__(128) __nv_bfloat16 g_wop[(size_t)EE*K3E];
__device__ __align__(128) __nv_bfloat16 g_w1p[(size_t)II*K3E];
__device__ __align__(128) __nv_bfloat16 g_w2p[(size_t)EE*K3I];

// ---------------------------------------------------------------------------
__device__ __forceinline__ uint32_t smem_u32(const void* p) {
    uint32_t a;
    asm("{ .reg .u64 t; cvta.to.shared.u64 t, %1; cvt.u32.u64 %0, t; }"
        : "=r"(a) : "l"(p));
    return a;
}
__device__ __forceinline__ void cp_async16(uint32_t s, const void* g) {
    asm volatile("cp.async.cg.shared.global [%0], [%1], 16;" :: "r"(s), "l"(g) : "memory");
}
#define CP_COMMIT() asm volatile("cp.async.commit_group;" ::: "memory")
#define CP_WAIT(n)  asm volatile("cp.async.wait_group %0;" :: "n"(n) : "memory")

__device__ __forceinline__ void ldsm4(uint32_t* r, uint32_t addr) {
    asm volatile("ldmatrix.sync.aligned.m8n8.x4.shared.b16 {%0,%1,%2,%3}, [%4];"
        : "=r"(r[0]), "=r"(r[1]), "=r"(r[2]), "=r"(r[3]) : "r"(addr));
}
__device__ __forceinline__ void ldsm4t(uint32_t* r, uint32_t addr) {
    asm volatile("ldmatrix.sync.aligned.m8n8.x4.trans.shared.b16 {%0,%1,%2,%3}, [%4];"
        : "=r"(r[0]), "=r"(r[1]), "=r"(r[2]), "=r"(r[3]) : "r"(addr));
}
__device__ __forceinline__ void mma16816(float* d, const uint32_t* a, const uint32_t* b) {
    asm volatile(
        "mma.sync.aligned.m16n8k16.row.col.f32.bf16.bf16.f32 "
        "{%0,%1,%2,%3}, {%4,%5,%6,%7}, {%8,%9}, {%0,%1,%2,%3};"
        : "+f"(d[0]), "+f"(d[1]), "+f"(d[2]), "+f"(d[3])
        : "r"(a[0]), "r"(a[1]), "r"(a[2]), "r"(a[3]), "r"(b[0]), "r"(b[1]));
}
__device__ __forceinline__ float gelu_tanh(float x) {
    float x3 = x * x * x;
    float t  = tanhf(0.7978845608028654f * (x + 0.044715f * x3));
    return 0.5f * x * (1.0f + t);
}
__device__ __forceinline__ void split_bf16(float v, __nv_bfloat16& h, __nv_bfloat16& l) {
    h = __float2bfloat16(v);
    l = __float2bfloat16(v - __bfloat162float(h));
}
__device__ __forceinline__ void split2(float x, float y, uint32_t& hi, uint32_t& lo) {
    __nv_bfloat16 hx, lx, hy, ly;
    split_bf16(x, hx, lx); split_bf16(y, hy, ly);
    __nv_bfloat162 H = __halves2bfloat162(hx, hy);
    __nv_bfloat162 L = __halves2bfloat162(lx, ly);
    hi = *reinterpret_cast<uint32_t*>(&H);
    lo = *reinterpret_cast<uint32_t*>(&L);
}

// ---------------------------------------------------------------------------
// mma.sync GEMM, 4-stage cp.async ring, 2 CTAs/SM.
//   MODE 0: outf = acc + bias
//   MODE 1: opk  = pack(split(gelu(acc + bias)))   rows [h | l | h], width 3N
//   MODE 2: outf = acc + bias + res
//   MODE 3: opk  = pack(split(acc + bias))         rows [h | l | h], width 3N
// ---------------------------------------------------------------------------
#define GEMM_NS    4
#define GEMM_STG   16384
#define GEMM_SMEM  (GEMM_NS * GEMM_STG)     // 64 KB dynamic

template<int MODE>
__global__ __launch_bounds__(256, 2)
void mma_gemm(const __nv_bfloat16* __restrict__ A,
              const __nv_bfloat16* __restrict__ W,
              const float* __restrict__ bias, const float* __restrict__ res,
              float* __restrict__ outf, __nv_bfloat16* __restrict__ opk,
              int M, int N, int K3) {
    extern __shared__ __align__(128) char smbuf[];

    const int tid  = threadIdx.x;
    const int wid  = tid >> 5;
    const int lane = tid & 31;
    const int wm   = wid & 3;
    const int wn   = wid >> 2;
    const int m0   = blockIdx.y * 128;
    const int n0   = blockIdx.x * 128;

    const uint32_t sb = smem_u32(smbuf);

    float acc[2][8][4];
    #pragma unroll
    for (int mf = 0; mf < 2; mf++)
        #pragma unroll
        for (int nf = 0; nf < 8; nf++)
            #pragma unroll
            for (int r = 0; r < 4; r++) acc[mf][nf][r] = 0.f;

    const int nc = K3 >> 5;

    auto loadc = [&](int c, int s) {
        const int k0 = c << 5;
        uint32_t as = sb + (uint32_t)s * GEMM_STG;
        uint32_t bs = as + 8192u;
        #pragma unroll
        for (int i = 0; i < 2; i++) {
            int cid = tid + i * 256;
            int row = cid >> 2, ch = cid & 3;
            uint32_t soff = row * 64u + ((uint32_t)(ch ^ (row & 3)) << 4);
            cp_async16(as + soff, A + (size_t)(m0 + row) * K3 + k0 + ch * 8);
            cp_async16(bs + soff, W + (size_t)(n0 + row) * K3 + k0 + ch * 8);
        }
    };

    // prologue: stages 0..NS-2 in flight
    #pragma unroll
    for (int p = 0; p < GEMM_NS - 1; p++) { loadc(p, p); CP_COMMIT(); }

    for (int c = 0; c < nc; c++) {
        CP_WAIT(GEMM_NS - 2);            // group c complete
        __syncthreads();

        const uint32_t as = sb + (uint32_t)(c & (GEMM_NS - 1)) * GEMM_STG;
        const uint32_t bs = as + 8192u;
        const int j = lane >> 3, r = lane & 7;

        #pragma unroll
        for (int ks = 0; ks < 2; ks++) {
            uint32_t af[2][4];
            #pragma unroll
            for (int mf = 0; mf < 2; mf++) {
                int row = wm * 32 + mf * 16 + (j & 1) * 8 + r;
                int kc  = ks * 2 + (j >> 1);
                ldsm4(af[mf], as + row * 64u + ((uint32_t)(kc ^ (row & 3)) << 4));
            }
            uint32_t bf[8][2];
            #pragma unroll
            for (int tp = 0; tp < 4; tp++) {
                int nrow = wn * 64 + tp * 16 + (j >> 1) * 8 + r;
                int kc   = ks * 2 + (j & 1);
                uint32_t t4[4];
                ldsm4(t4, bs + nrow * 64u + ((uint32_t)(kc ^ (nrow & 3)) << 4));
                bf[2*tp][0]   = t4[0]; bf[2*tp][1]   = t4[1];
                bf[2*tp+1][0] = t4[2]; bf[2*tp+1][1] = t4[3];
            }
            #pragma unroll
            for (int mf = 0; mf < 2; mf++)
                #pragma unroll
                for (int nf = 0; nf < 8; nf++)
                    mma16816(acc[mf][nf], af[mf], bf[nf]);
        }
        __syncthreads();                  // all warps done reading stage c

        const int nxt = c + GEMM_NS - 1;
        if (nxt < nc) loadc(nxt, nxt & (GEMM_NS - 1));
        CP_COMMIT();                      // empty group at tail keeps counts uniform
    }

    const int gi = lane >> 2, ci = lane & 3;
    #pragma unroll
    for (int mf = 0; mf < 2; mf++) {
        int r0 = m0 + wm * 32 + mf * 16 + gi;
        #pragma unroll
        for (int nf = 0; nf < 8; nf++) {
            int col = n0 + wn * 64 + nf * 8 + ci * 2;
            float b0 = bias[col], b1 = bias[col + 1];
            float v00 = acc[mf][nf][0] + b0, v01 = acc[mf][nf][1] + b1;
            float v10 = acc[mf][nf][2] + b0, v11 = acc[mf][nf][3] + b1;
            if (MODE == 1 || MODE == 3) {
                if (MODE == 1) {
                    v00 = gelu_tanh(v00); v01 = gelu_tanh(v01);
                    v10 = gelu_tanh(v10); v11 = gelu_tanh(v11);
                }
                __nv_bfloat16 h0,l0,h1,l1;
                size_t rw = (size_t)r0 * (3 * N) + col;
                split_bf16(v00, h0, l0); split_bf16(v01, h1, l1);
                *reinterpret_cast<__nv_bfloat162*>(opk + rw)       = __halves2bfloat162(h0, h1);
                *reinterpret_cast<__nv_bfloat162*>(opk + rw + N)   = __halves2bfloat162(l0, l1);
                *reinterpret_cast<__nv_bfloat162*>(opk + rw + 2*N) = __halves2bfloat162(h0, h1);
                size_t rw2 = (size_t)(r0 + 8) * (3 * N) + col;
                split_bf16(v10, h0, l0); split_bf16(v11, h1, l1);
                *reinterpret_cast<__nv_bfloat162*>(opk + rw2)       = __halves2bfloat162(h0, h1);
                *reinterpret_cast<__nv_bfloat162*>(opk + rw2 + N)   = __halves2bfloat162(l0, l1);
                *reinterpret_cast<__nv_bfloat162*>(opk + rw2 + 2*N) = __halves2bfloat162(h0, h1);
            } else {
                if (MODE == 2) {
                    const float2 r00 = *reinterpret_cast<const float2*>(res + (size_t)r0 * N + col);
                    const float2 r10 = *reinterpret_cast<const float2*>(res + (size_t)(r0 + 8) * N + col);
                    v00 += r00.x; v01 += r00.y; v10 += r10.x; v11 += r10.y;
                }
                *reinterpret_cast<float2*>(outf + (size_t)r0 * N + col)       = make_float2(v00, v01);
                *reinterpret_cast<float2*>(outf + (size_t)(r0 + 8) * N + col) = make_float2(v10, v11);
            }
        }
    }
}

// ---------------------------------------------------------------------------
// Fused flash attention (unchanged from R5).
// ---------------------------------------------------------------------------
#define FA_SMEM (32768 + 2*65536)

__global__ __launch_bounds__(256, 1)
void flash_attn(const __nv_bfloat16* __restrict__ Qp,
                const __nv_bfloat16* __restrict__ Kp,
                const __nv_bfloat16* __restrict__ Vp,
                const float* __restrict__ mask,
                __nv_bfloat16* __restrict__ Op) {
    extern __shared__ __align__(128) char fsm[];
    const uint32_t sb = smem_u32(fsm);
    const int tid = threadIdx.x, wid = tid >> 5, lane = tid & 31;
    const int qt = blockIdx.x, bh = blockIdx.y;
    const int b = bh / HH, h = bh - b * HH;
    const int q0 = qt * 128;
    const int j = lane >> 3, r = lane & 7;
    const int gi = lane >> 2, ci = lane & 3;

    const uint32_t sQh = sb, sQl = sb + 16384u;
    const uint32_t stg0 = sb + 32768u;

    {
        const size_t rbase = (size_t)(b * SS + q0);
        #pragma unroll
        for (int i = 0; i < 4; i++) {
            int idx = tid + i * 256;
            int row = idx >> 3, ch = idx & 7;
            uint32_t d = row * 128u + ((uint32_t)(ch ^ (row & 7)) << 4);
            const __nv_bfloat16* g = Qp + (rbase + row) * K3E + h * DD + ch * 8;
            cp_async16(sQh + d, g);
            cp_async16(sQl + d, g + EE);
        }
    }
    auto loadKV = [&](int it, int st) {
        const size_t rbase = (size_t)(b * SS + it * 128);
        uint32_t base = stg0 + st * 65536u;
        const __nv_bfloat16* s0 = Kp + h * DD;
        const __nv_bfloat16* s1 = Kp + EE + h * DD;
        const __nv_bfloat16* s2 = Vp + h * DD;
        const __nv_bfloat16* s3 = Vp + EE + h * DD;
        #pragma unroll
        for (int i = 0; i < 4; i++) {
            int idx = tid + i * 256;
            int row = idx >> 3, ch = idx & 7;
            size_t go = (rbase + row) * (size_t)K3E + ch * 8;
            uint32_t d = base + row * 128u + ((uint32_t)(ch ^ (row & 7)) << 4);
            cp_async16(d,           s0 + go);
            cp_async16(d + 16384u,  s1 + go);
            cp_async16(d + 32768u,  s2 + go);
            cp_async16(d + 49152u,  s3 + go);
        }
    };

    loadKV(0, 0);
    CP_COMMIT();

    float m0v = -1e30f, m1v = -1e30f, l0 = 0.f, l1 = 0.f;
    float o[8][4];
    #pragma unroll
    for (int nt = 0; nt < 8; nt++)
        #pragma unroll
        for (int t = 0; t < 4; t++) o[nt][t] = 0.f;

    const int NIT = SS / 128;
    for (int it = 0; it < NIT; it++) {
        const int st = it & 1;
        if (it + 1 < NIT) { loadKV(it + 1, st ^ 1); CP_COMMIT(); CP_WAIT(1); }
        else              { CP_WAIT(0); }
        __syncthreads();

        const uint32_t kb = stg0 + st * 65536u;

        float s[16][4];
        #pragma unroll
        for (int t = 0; t < 16; t++)
            #pragma unroll
            for (int u = 0; u < 4; u++) s[t][u] = 0.f;

        #pragma unroll
        for (int sec = 0; sec < 3; sec++) {
            const uint32_t qb = (sec == 1) ? sQl : sQh;
            const uint32_t kk = kb + ((sec == 2) ? 16384u : 0u);
            #pragma unroll
            for (int kc = 0; kc < 4; kc++) {
                uint32_t af[4];
                int arow = wid * 16 + (j & 1) * 8 + r;
                int ach  = kc * 2 + (j >> 1);
                ldsm4(af, qb + arow * 128u + ((uint32_t)(ach ^ (arow & 7)) << 4));
                #pragma unroll
                for (int nt2 = 0; nt2 < 8; nt2++) {
                    int brow = nt2 * 16 + (j >> 1) * 8 + r;
                    int bch  = kc * 2 + (j & 1);
                    uint32_t t4[4];
                    ldsm4(t4, kk + brow * 128u + ((uint32_t)(bch ^ (brow & 7)) << 4));
                    uint32_t b0[2] = {t4[0], t4[1]}, b1[2] = {t4[2], t4[3]};
                    mma16816(s[2*nt2],   af, b0);
                    mma16816(s[2*nt2+1], af, b1);
                }
            }
        }

        const float* mr0 = mask + ((size_t)b * SS + (q0 + wid * 16 + gi)) * SS + it * 128;
        const float* mr1 = mr0 + 8 * (size_t)SS;
        float mx0 = -1e30f, mx1 = -1e30f;
        #pragma unroll
        for (int t = 0; t < 16; t++) {
            float2 u0 = *reinterpret_cast<const float2*>(mr0 + t * 8 + ci * 2);
            float2 u1 = *reinterpret_cast<const float2*>(mr1 + t * 8 + ci * 2);
            s[t][0] = s[t][0] * SCALE_F + u0.x;
            s[t][1] = s[t][1] * SCALE_F + u0.y;
            s[t][2] = s[t][2] * SCALE_F + u1.x;
            s[t][3] = s[t][3] * SCALE_F + u1.y;
            mx0 = fmaxf(mx0, fmaxf(s[t][0], s[t][1]));
            mx1 = fmaxf(mx1, fmaxf(s[t][2], s[t][3]));
        }
        mx0 = fmaxf(mx0, __shfl_xor_sync(0xFFFFFFFFu, mx0, 1));
        mx0 = fmaxf(mx0, __shfl_xor_sync(0xFFFFFFFFu, mx0, 2));
        mx1 = fmaxf(mx1, __shfl_xor_sync(0xFFFFFFFFu, mx1, 1));
        mx1 = fmaxf(mx1, __shfl_xor_sync(0xFFFFFFFFu, mx1, 2));
        const float mn0 = fmaxf(m0v, mx0), mn1 = fmaxf(m1v, mx1);
        const float a0 = __expf(m0v - mn0), a1 = __expf(m1v - mn1);
        m0v = mn0; m1v = mn1;

        float ps0 = 0.f, ps1 = 0.f;
        #pragma unroll
        for (int t = 0; t < 16; t++) {
            s[t][0] = __expf(s[t][0] - mn0);
            s[t][1] = __expf(s[t][1] - mn0);
            s[t][2] = __expf(s[t][2] - mn1);
            s[t][3] = __expf(s[t][3] - mn1);
            ps0 += s[t][0] + s[t][1];
            ps1 += s[t][2] + s[t][3];
        }
        ps0 += __shfl_xor_sync(0xFFFFFFFFu, ps0, 1);
        ps0 += __shfl_xor_sync(0xFFFFFFFFu, ps0, 2);
        ps1 += __shfl_xor_sync(0xFFFFFFFFu, ps1, 1);
        ps1 += __shfl_xor_sync(0xFFFFFFFFu, ps1, 2);
        l0 = l0 * a0 + ps0;
        l1 = l1 * a1 + ps1;

        #pragma unroll
        for (int nt = 0; nt < 8; nt++) {
            o[nt][0] *= a0; o[nt][1] *= a0;
            o[nt][2] *= a1; o[nt][3] *= a1;
        }

        const uint32_t vh = kb + 32768u, vl = kb + 49152u;
        #pragma unroll
        for (int kt = 0; kt < 8; kt++) {
            uint32_t ph[4], pl[4];
            split2(s[2*kt][0],   s[2*kt][1],   ph[0], pl[0]);
            split2(s[2*kt][2],   s[2*kt][3],   ph[1], pl[1]);
            split2(s[2*kt+1][0], s[2*kt+1][1], ph[2], pl[2]);
            split2(s[2*kt+1][2], s[2*kt+1][3], ph[3], pl[3]);
            #pragma unroll
            for (int nt2 = 0; nt2 < 4; nt2++) {
                int vrow = kt * 16 + (j & 1) * 8 + r;
                int vch  = nt2 * 2 + (j >> 1);
                uint32_t sw = vrow * 128u + ((uint32_t)(vch ^ (vrow & 7)) << 4);
                uint32_t t4[4];
                ldsm4t(t4, vh + sw);
                uint32_t b0[2] = {t4[0], t4[1]}, b1[2] = {t4[2], t4[3]};
                mma16816(o[2*nt2],   ph, b0);
                mma16816(o[2*nt2+1], ph, b1);
                mma16816(o[2*nt2],   pl, b0);
                mma16816(o[2*nt2+1], pl, b1);
                ldsm4t(t4, vl + sw);
                uint32_t c0[2] = {t4[0], t4[1]}, c1[2] = {t4[2], t4[3]};
                mma16816(o[2*nt2],   ph, c0);
                mma16816(o[2*nt2+1], ph, c1);
            }
        }
        __syncthreads();
    }

    const float inv0 = 1.f / l0, inv1 = 1.f / l1;
    const int qrow = b * SS + q0 + wid * 16 + gi;
    #pragma unroll
    for (int nt = 0; nt < 8; nt++) {
        int col = h * DD + nt * 8 + ci * 2;
        float v00 = o[nt][0] * inv0, v01 = o[nt][1] * inv0;
        float v10 = o[nt][2] * inv1, v11 = o[nt][3] * inv1;
        size_t rw0 = (size_t)qrow * K3E + col;
        size_t rw1 = (size_t)(qrow + 8) * K3E + col;
        __nv_bfloat16 h0, lo0, h1, lo1;
        split_bf16(v00, h0, lo0); split_bf16(v01, h1, lo1);
        *reinterpret_cast<__nv_bfloat162*>(Op + rw0)        = __halves2bfloat162(h0, h1);
        *reinterpret_cast<__nv_bfloat162*>(Op + rw0 + EE)   = __halves2bfloat162(lo0, lo1);
        *reinterpret_cast<__nv_bfloat162*>(Op + rw0 + 2*EE) = __halves2bfloat162(h0, h1);
        split_bf16(v10, h0, lo0); split_bf16(v11, h1, lo1);
        *reinterpret_cast<__nv_bfloat162*>(Op + rw1)        = __halves2bfloat162(h0, h1);
        *reinterpret_cast<__nv_bfloat162*>(Op + rw1 + EE)   = __halves2bfloat162(lo0, lo1);
        *reinterpret_cast<__nv_bfloat162*>(Op + rw1 + 2*EE) = __halves2bfloat162(h0, h1);
    }
}

// ---------------------------------------------------------------------------
__global__ void transpose_pack(const float* __restrict__ W,
                               __nv_bfloat16* __restrict__ wp,
                               int K, int N) {
    __shared__ float t[32][33];
    int tx = threadIdx.x, ty = threadIdx.y;
    int k0 = blockIdx.y * 32, n0 = blockIdx.x * 32;
    #pragma unroll
    for (int j = 0; j < 4; j++)
        t[ty + j*8][tx] = W[(size_t)(k0 + ty + j*8) * N + n0 + tx];
    __syncthreads();
    size_t K3 = 3 * (size_t)K;
    #pragma unroll
    for (int j = 0; j < 4; j++) {
        int nn = n0 + ty + j*8;
        int kk = k0 + tx;
        float v = t[tx][ty + j*8];
        __nv_bfloat16 h, l; split_bf16(v, h, l);
        wp[(size_t)nn * K3 + kk]       = h;
        wp[(size_t)nn * K3 + K + kk]   = h;
        wp[(size_t)nn * K3 + 2*K + kk] = l;
    }
}

// ---------------------------------------------------------------------------
__global__ void ln_pack(const float* __restrict__ x,
                        const float* __restrict__ g,
                        const float* __restrict__ b,
                        __nv_bfloat16* __restrict__ pk) {
    int row = blockIdx.x;
    const float* xr = x + (size_t)row * EE;
    float s = 0.f, s2 = 0.f;
    for (int i = threadIdx.x; i < EE; i += 256) {
        float v = xr[i]; s += v; s2 += v * v;
    }
    __shared__ float rs[8], rs2[8];
    #pragma unroll
    for (int o = 16; o > 0; o >>= 1) {
        s  += __shfl_xor_sync(0xFFFFFFFFu, s,  o);
        s2 += __shfl_xor_sync(0xFFFFFFFFu, s2, o);
    }
    if ((threadIdx.x & 31) == 0) { rs[threadIdx.x>>5] = s; rs2[threadIdx.x>>5] = s2; }
    __syncthreads();
    float ts = 0.f, ts2 = 0.f;
    #pragma unroll
    for (int i = 0; i < 8; i++) { ts += rs[i]; ts2 += rs2[i]; }
    float mean = ts * (1.0f / EE);
    float var  = ts2 * (1.0f / EE) - mean * mean;
    float inv  = rsqrtf(var + EPSF);
    size_t rw = (size_t)row * K3E;
    for (int i = threadIdx.x; i < EE; i += 256) {
        float y = (xr[i] - mean) * inv * g[i] + b[i];
        __nv_bfloat16 h, l; split_bf16(y, h, l);
        pk[rw + i]        = h;
        pk[rw + EE + i]   = l;
        pk[rw + 2*EE + i] = h;
    }
}

// ---------------------------------------------------------------------------
extern "C" void kernel_launch(void* const* d_in, const int* in_sizes, int n_in,
                              void* d_out, int out_size) {
    const float* hs   = (const float*)d_in[0];
    const float* mask = (const float*)d_in[1];
    const float* wq   = (const float*)d_in[2];
    const float* bq   = (const float*)d_in[3];
    const float* wk   = (const float*)d_in[4];
    const float* bk   = (const float*)d_in[5];
    const float* wv   = (const float*)d_in[6];
    const float* bv   = (const float*)d_in[7];
    const float* wo   = (const float*)d_in[8];
    const float* bo   = (const float*)d_in[9];
    const float* ln1g = (const float*)d_in[10];
    const float* ln1b = (const float*)d_in[11];
    const float* ln2g = (const float*)d_in[12];
    const float* ln2b = (const float*)d_in[13];
    const float* w1   = (const float*)d_in[14];
    const float* b1   = (const float*)d_in[15];
    const float* w2   = (const float*)d_in[16];
    const float* b2   = (const float*)d_in[17];
    float* out = (float*)d_out;

    float *x;
    __nv_bfloat16 *h1p, *h2p, *qp, *kp, *vp, *op, *mp;
    __nv_bfloat16 *wqp, *wkp, *wvp, *wop, *w1p, *w2p;
    cudaGetSymbolAddress((void**)&x,   g_x);
    cudaGetSymbolAddress((void**)&h1p, g_h1p);
    cudaGetSymbolAddress((void**)&h2p, g_h2p);
    cudaGetSymbolAddress((void**)&qp,  g_qp);
    cudaGetSymbolAddress((void**)&kp,  g_kp);
    cudaGetSymbolAddress((void**)&vp,  g_vp);
    cudaGetSymbolAddress((void**)&op,  g_op);
    cudaGetSymbolAddress((void**)&mp,  g_mp);
    cudaGetSymbolAddress((void**)&wqp, g_wqp);
    cudaGetSymbolAddress((void**)&wkp, g_wkp);
    cudaGetSymbolAddress((void**)&wvp, g_wvp);
    cudaGetSymbolAddress((void**)&wop, g_wop);
    cudaGetSymbolAddress((void**)&w1p, g_w1p);
    cudaGetSymbolAddress((void**)&w2p, g_w2p);

    cudaFuncSetAttribute(flash_attn, cudaFuncAttributeMaxDynamicSharedMemorySize, FA_SMEM);
    cudaFuncSetAttribute(mma_gemm<0>, cudaFuncAttributeMaxDynamicSharedMemorySize, GEMM_SMEM);
    cudaFuncSetAttribute(mma_gemm<1>, cudaFuncAttributeMaxDynamicSharedMemorySize, GEMM_SMEM);
    cudaFuncSetAttribute(mma_gemm<2>, cudaFuncAttributeMaxDynamicSharedMemorySize, GEMM_SMEM);
    cudaFuncSetAttribute(mma_gemm<3>, cudaFuncAttributeMaxDynamicSharedMemorySize, GEMM_SMEM);

    dim3 tb(32, 8);
    transpose_pack<<<dim3(EE/32, EE/32), tb>>>(wq, wqp, EE, EE);
    transpose_pack<<<dim3(EE/32, EE/32), tb>>>(wk, wkp, EE, EE);
    transpose_pack<<<dim3(EE/32, EE/32), tb>>>(wv, wvp, EE, EE);
    transpose_pack<<<dim3(EE/32, EE/32), tb>>>(wo, wop, EE, EE);
    transpose_pack<<<dim3(II/32, EE/32), tb>>>(w1, w1p, EE, II);
    transpose_pack<<<dim3(EE/32, II/32), tb>>>(w2, w2p, II, EE);

    // 1. LN1 -> packed
    ln_pack<<<MR, 256>>>(hs, ln1g, ln1b, h1p);

    // 2. QKV projections -> packed split bf16
    dim3 gp(EE/128, MR/128);
    mma_gemm<3><<<gp, 256, GEMM_SMEM>>>(h1p, wqp, bq, nullptr, nullptr, qp, MR, EE, K3E);
    mma_gemm<3><<<gp, 256, GEMM_SMEM>>>(h1p, wkp, bk, nullptr, nullptr, kp, MR, EE, K3E);
    mma_gemm<3><<<gp, 256, GEMM_SMEM>>>(h1p, wvp, bv, nullptr, nullptr, vp, MR, EE, K3E);

    // 3. fused flash attention -> packed attn-out
    flash_attn<<<dim3(SS/128, BB*HH), 256, FA_SMEM>>>(qp, kp, vp, mask, op);

    // 4. O-proj + residual(hs) -> x
    mma_gemm<2><<<gp, 256, GEMM_SMEM>>>(op, wop, bo, hs, x, nullptr, MR, EE, K3E);

    // 5. LN2 -> packed
    ln_pack<<<MR, 256>>>(x, ln2g, ln2b, h2p);

    // 6. MLP up + gelu -> packed
    mma_gemm<1><<<dim3(II/128, MR/128), 256, GEMM_SMEM>>>(h2p, w1p, b1, nullptr, nullptr, mp, MR, II, K3E);

    // 7. MLP down + residual(x) -> out
    mma_gemm<2><<<dim3(EE/128, MR/128), 256, GEMM_SMEM>>>(mp, w2p, b2, x, out, nullptr, MR, EE, K3I);
}

// round 7
// speedup vs baseline: 3.1543x; 1.2986x over previous
#include <cuda_runtime.h>
#include <cuda_fp16.h>
#include <math.h>
#include <stdint.h>

// ---------------------------------------------------------------------------
// SiglipEncoderLayer  B=8 S=1024 E=768 H=12 D=64 I=3072  fp32 in/out
// R7: fp16 splits. QKV (fused) + attention = 3-pass (fp32-class);
//     O-proj / MLP = 2-pass (err ~3e-4, linear propagation).
// ---------------------------------------------------------------------------

#define BB   8
#define SS   1024
#define EE   768
#define HH   12
#define DD   64
#define II   3072
#define MR   (BB*SS)            // 8192
#define K3E  (3*EE)             // 2304  (3-pass pack width, also QKV N)
#define K2E  (2*EE)             // 1536
#define K2I  (2*II)             // 6144
#define NQKV (3*EE)             // 2304 outputs (q|k|v)
#define RQKV (2*NQKV)           // 4608  qkv row width [H|L]
#define EPSF 1e-6f
#define SCALE_F 0.125f

// ---- scratch (device globals, 128B aligned) -------------------------------
__device__ __align__(128) float g_x [MR*EE];
__device__ __align__(128) float g_bqkv[NQKV];

__device__ __align__(128) __half g_h1p[(size_t)MR*K3E];     // ln1 [h|l|h]
__device__ __align__(128) __half g_h2p[(size_t)MR*K2E];     // ln2 [h|l]
__device__ __align__(128) __half g_qkv[(size_t)MR*RQKV];    // qkv [H(2304)|L(2304)]
__device__ __align__(128) __half g_op [(size_t)MR*K2E];     // attn out [h|l]
__device__ __align__(128) __half g_mp [(size_t)MR*K2I];     // mlp mid [h|l]

__device__ __align__(128) __half g_wqkvp[(size_t)NQKV*K3E]; // [Wh|Wh|Wl] rows
__device__ __align__(128) __half g_wop[(size_t)EE*K2E];     // [Wh|Wh]
__device__ __align__(128) __half g_w1p[(size_t)II*K2E];     // [Wh|Wh]
__device__ __align__(128) __half g_w2p[(size_t)EE*K2I];     // [Wh|Wh]

// ---------------------------------------------------------------------------
__device__ __forceinline__ uint32_t smem_u32(const void* p) {
    uint32_t a;
    asm("{ .reg .u64 t; cvta.to.shared.u64 t, %1; cvt.u32.u64 %0, t; }"
        : "=r"(a) : "l"(p));
    return a;
}
__device__ __forceinline__ void cp_async16(uint32_t s, const void* g) {
    asm volatile("cp.async.cg.shared.global [%0], [%1], 16;" :: "r"(s), "l"(g) : "memory");
}
#define CP_COMMIT() asm volatile("cp.async.commit_group;" ::: "memory")
#define CP_WAIT(n)  asm volatile("cp.async.wait_group %0;" :: "n"(n) : "memory")

__device__ __forceinline__ void ldsm4(uint32_t* r, uint32_t addr) {
    asm volatile("ldmatrix.sync.aligned.m8n8.x4.shared.b16 {%0,%1,%2,%3}, [%4];"
        : "=r"(r[0]), "=r"(r[1]), "=r"(r[2]), "=r"(r[3]) : "r"(addr));
}
__device__ __forceinline__ void ldsm4t(uint32_t* r, uint32_t addr) {
    asm volatile("ldmatrix.sync.aligned.m8n8.x4.trans.shared.b16 {%0,%1,%2,%3}, [%4];"
        : "=r"(r[0]), "=r"(r[1]), "=r"(r[2]), "=r"(r[3]) : "r"(addr));
}
__device__ __forceinline__ void mma16816(float* d, const uint32_t* a, const uint32_t* b) {
    asm volatile(
        "mma.sync.aligned.m16n8k16.row.col.f32.f16.f16.f32 "
        "{%0,%1,%2,%3}, {%4,%5,%6,%7}, {%8,%9}, {%0,%1,%2,%3};"
        : "+f"(d[0]), "+f"(d[1]), "+f"(d[2]), "+f"(d[3])
        : "r"(a[0]), "r"(a[1]), "r"(a[2]), "r"(a[3]), "r"(b[0]), "r"(b[1]));
}
__device__ __forceinline__ float gelu_tanh(float x) {
    float x3 = x * x * x;
    float t  = tanhf(0.7978845608028654f * (x + 0.044715f * x3));
    return 0.5f * x * (1.0f + t);
}
__device__ __forceinline__ void split_h(float v, __half& h, __half& l) {
    h = __float2half_rn(v);
    l = __float2half_rn(v - __half2float(h));
}
__device__ __forceinline__ void split2h(float x, float y, uint32_t& hi, uint32_t& lo) {
    __half hx, lx, hy, ly;
    split_h(x, hx, lx); split_h(y, hy, ly);
    __half2 H = __halves2half2(hx, hy);
    __half2 L = __halves2half2(lx, ly);
    hi = *reinterpret_cast<uint32_t*>(&H);
    lo = *reinterpret_cast<uint32_t*>(&L);
}

// ---------------------------------------------------------------------------
// mma.sync GEMM (fp16), 4-stage cp.async ring.
//   MODE 1: opk = pack[h|l](gelu(acc+bias)), width 2N
//   MODE 2: outf = acc + bias + res
//   MODE 3: opk = pack[h|l](acc+bias), width 2N
// ---------------------------------------------------------------------------
#define GEMM_NS    4
#define GEMM_STG   16384
#define GEMM_SMEM  (GEMM_NS * GEMM_STG)

template<int MODE>
__global__ __launch_bounds__(256, 2)
void mma_gemm(const __half* __restrict__ A,
              const __half* __restrict__ W,
              const float* __restrict__ bias, const float* __restrict__ res,
              float* __restrict__ outf, __half* __restrict__ opk,
              int M, int N, int KP) {
    extern __shared__ __align__(128) char smbuf[];

    const int tid  = threadIdx.x;
    const int wid  = tid >> 5;
    const int lane = tid & 31;
    const int wm   = wid & 3;
    const int wn   = wid >> 2;
    const int m0   = blockIdx.y * 128;
    const int n0   = blockIdx.x * 128;

    const uint32_t sb = smem_u32(smbuf);

    float acc[2][8][4];
    #pragma unroll
    for (int mf = 0; mf < 2; mf++)
        #pragma unroll
        for (int nf = 0; nf < 8; nf++)
            #pragma unroll
            for (int r = 0; r < 4; r++) acc[mf][nf][r] = 0.f;

    const int nc = KP >> 5;

    auto loadc = [&](int c, int s) {
        const int k0 = c << 5;
        uint32_t as = sb + (uint32_t)s * GEMM_STG;
        uint32_t bs = as + 8192u;
        #pragma unroll
        for (int i = 0; i < 2; i++) {
            int cid = tid + i * 256;
            int row = cid >> 2, ch = cid & 3;
            uint32_t soff = row * 64u + ((uint32_t)(ch ^ (row & 3)) << 4);
            cp_async16(as + soff, A + (size_t)(m0 + row) * KP + k0 + ch * 8);
            cp_async16(bs + soff, W + (size_t)(n0 + row) * KP + k0 + ch * 8);
        }
    };

    #pragma unroll
    for (int p = 0; p < GEMM_NS - 1; p++) { loadc(p, p); CP_COMMIT(); }

    for (int c = 0; c < nc; c++) {
        CP_WAIT(GEMM_NS - 2);
        __syncthreads();

        const uint32_t as = sb + (uint32_t)(c & (GEMM_NS - 1)) * GEMM_STG;
        const uint32_t bs = as + 8192u;
        const int j = lane >> 3, r = lane & 7;

        #pragma unroll
        for (int ks = 0; ks < 2; ks++) {
            uint32_t af[2][4];
            #pragma unroll
            for (int mf = 0; mf < 2; mf++) {
                int row = wm * 32 + mf * 16 + (j & 1) * 8 + r;
                int kc  = ks * 2 + (j >> 1);
                ldsm4(af[mf], as + row * 64u + ((uint32_t)(kc ^ (row & 3)) << 4));
            }
            uint32_t bf[8][2];
            #pragma unroll
            for (int tp = 0; tp < 4; tp++) {
                int nrow = wn * 64 + tp * 16 + (j >> 1) * 8 + r;
                int kc   = ks * 2 + (j & 1);
                uint32_t t4[4];
                ldsm4(t4, bs + nrow * 64u + ((uint32_t)(kc ^ (nrow & 3)) << 4));
                bf[2*tp][0]   = t4[0]; bf[2*tp][1]   = t4[1];
                bf[2*tp+1][0] = t4[2]; bf[2*tp+1][1] = t4[3];
            }
            #pragma unroll
            for (int mf = 0; mf < 2; mf++)
                #pragma unroll
                for (int nf = 0; nf < 8; nf++)
                    mma16816(acc[mf][nf], af[mf], bf[nf]);
        }
        __syncthreads();

        const int nxt = c + GEMM_NS - 1;
        if (nxt < nc) loadc(nxt, nxt & (GEMM_NS - 1));
        CP_COMMIT();
    }

    const int gi = lane >> 2, ci = lane & 3;
    #pragma unroll
    for (int mf = 0; mf < 2; mf++) {
        int r0 = m0 + wm * 32 + mf * 16 + gi;
        #pragma unroll
        for (int nf = 0; nf < 8; nf++) {
            int col = n0 + wn * 64 + nf * 8 + ci * 2;
            float b0 = bias[col], b1 = bias[col + 1];
            float v00 = acc[mf][nf][0] + b0, v01 = acc[mf][nf][1] + b1;
            float v10 = acc[mf][nf][2] + b0, v11 = acc[mf][nf][3] + b1;
            if (MODE == 1 || MODE == 3) {
                if (MODE == 1) {
                    v00 = gelu_tanh(v00); v01 = gelu_tanh(v01);
                    v10 = gelu_tanh(v10); v11 = gelu_tanh(v11);
                }
                __half h0,l0,h1,l1;
                size_t rw = (size_t)r0 * (2 * N) + col;
                split_h(v00, h0, l0); split_h(v01, h1, l1);
                *reinterpret_cast<__half2*>(opk + rw)     = __halves2half2(h0, h1);
                *reinterpret_cast<__half2*>(opk + rw + N) = __halves2half2(l0, l1);
                size_t rw2 = (size_t)(r0 + 8) * (2 * N) + col;
                split_h(v10, h0, l0); split_h(v11, h1, l1);
                *reinterpret_cast<__half2*>(opk + rw2)     = __halves2half2(h0, h1);
                *reinterpret_cast<__half2*>(opk + rw2 + N) = __halves2half2(l0, l1);
            } else {
                if (MODE == 2) {
                    const float2 r00 = *reinterpret_cast<const float2*>(res + (size_t)r0 * N + col);
                    const float2 r10 = *reinterpret_cast<const float2*>(res + (size_t)(r0 + 8) * N + col);
                    v00 += r00.x; v01 += r00.y; v10 += r10.x; v11 += r10.y;
                }
                *reinterpret_cast<float2*>(outf + (size_t)r0 * N + col)       = make_float2(v00, v01);
                *reinterpret_cast<float2*>(outf + (size_t)(r0 + 8) * N + col) = make_float2(v10, v11);
            }
        }
    }
}

// ---------------------------------------------------------------------------
// Fused flash attention (fp16). QK^T 3-pass, PV 3-pass, online softmax.
// Q/K/V come from the fused qkv buffer: row stride RQKV, hi at col sec,
// lo at col sec + NQKV.  Output: [h|l] rows of width K2E.
// ---------------------------------------------------------------------------
#define FA_SMEM (32768 + 2*65536)

__global__ __launch_bounds__(256, 1)
void flash_attn(const __half* __restrict__ QKV,
                const float* __restrict__ mask,
                __half* __restrict__ Op) {
    extern __shared__ __align__(128) char fsm[];
    const uint32_t sb = smem_u32(fsm);
    const int tid = threadIdx.x, wid = tid >> 5, lane = tid & 31;
    const int qt = blockIdx.x, bh = blockIdx.y;
    const int b = bh / HH, h = bh - b * HH;
    const int q0 = qt * 128;
    const int j = lane >> 3, r = lane & 7;
    const int gi = lane >> 2, ci = lane & 3;

    const int qoff = h * DD, koff = EE + h * DD, voff = 2 * EE + h * DD;

    const uint32_t sQh = sb, sQl = sb + 16384u;
    const uint32_t stg0 = sb + 32768u;

    {
        const size_t rbase = (size_t)(b * SS + q0);
        #pragma unroll
        for (int i = 0; i < 4; i++) {
            int idx = tid + i * 256;
            int row = idx >> 3, ch = idx & 7;
            uint32_t d = row * 128u + ((uint32_t)(ch ^ (row & 7)) << 4);
            const __half* g = QKV + (rbase + row) * RQKV + qoff + ch * 8;
            cp_async16(sQh + d, g);
            cp_async16(sQl + d, g + NQKV);
        }
    }
    auto loadKV = [&](int it, int st) {
        const size_t rbase = (size_t)(b * SS + it * 128);
        uint32_t base = stg0 + st * 65536u;
        #pragma unroll
        for (int i = 0; i < 4; i++) {
            int idx = tid + i * 256;
            int row = idx >> 3, ch = idx & 7;
            const __half* g = QKV + (rbase + row) * RQKV + ch * 8;
            uint32_t d = base + row * 128u + ((uint32_t)(ch ^ (row & 7)) << 4);
            cp_async16(d,           g + koff);          // Kh
            cp_async16(d + 16384u,  g + koff + NQKV);   // Kl
            cp_async16(d + 32768u,  g + voff);          // Vh
            cp_async16(d + 49152u,  g + voff + NQKV);   // Vl
        }
    };

    loadKV(0, 0);
    CP_COMMIT();

    float m0v = -1e30f, m1v = -1e30f, l0 = 0.f, l1 = 0.f;
    float o[8][4];
    #pragma unroll
    for (int nt = 0; nt < 8; nt++)
        #pragma unroll
        for (int t = 0; t < 4; t++) o[nt][t] = 0.f;

    const int NIT = SS / 128;
    for (int it = 0; it < NIT; it++) {
        const int st = it & 1;
        if (it + 1 < NIT) { loadKV(it + 1, st ^ 1); CP_COMMIT(); CP_WAIT(1); }
        else              { CP_WAIT(0); }
        __syncthreads();

        const uint32_t kb = stg0 + st * 65536u;

        float s[16][4];
        #pragma unroll
        for (int t = 0; t < 16; t++)
            #pragma unroll
            for (int u = 0; u < 4; u++) s[t][u] = 0.f;

        #pragma unroll
        for (int sec = 0; sec < 3; sec++) {
            const uint32_t qb = (sec == 1) ? sQl : sQh;
            const uint32_t kk = kb + ((sec == 2) ? 16384u : 0u);
            #pragma unroll
            for (int kc = 0; kc < 4; kc++) {
                uint32_t af[4];
                int arow = wid * 16 + (j & 1) * 8 + r;
                int ach  = kc * 2 + (j >> 1);
                ldsm4(af, qb + arow * 128u + ((uint32_t)(ach ^ (arow & 7)) << 4));
                #pragma unroll
                for (int nt2 = 0; nt2 < 8; nt2++) {
                    int brow = nt2 * 16 + (j >> 1) * 8 + r;
                    int bch  = kc * 2 + (j & 1);
                    uint32_t t4[4];
                    ldsm4(t4, kk + brow * 128u + ((uint32_t)(bch ^ (brow & 7)) << 4));
                    uint32_t b0[2] = {t4[0], t4[1]}, b1[2] = {t4[2], t4[3]};
                    mma16816(s[2*nt2],   af, b0);
                    mma16816(s[2*nt2+1], af, b1);
                }
            }
        }

        const float* mr0 = mask + ((size_t)b * SS + (q0 + wid * 16 + gi)) * SS + it * 128;
        const float* mr1 = mr0 + 8 * (size_t)SS;
        float mx0 = -1e30f, mx1 = -1e30f;
        #pragma unroll
        for (int t = 0; t < 16; t++) {
            float2 u0 = *reinterpret_cast<const float2*>(mr0 + t * 8 + ci * 2);
            float2 u1 = *reinterpret_cast<const float2*>(mr1 + t * 8 + ci * 2);
            s[t][0] = s[t][0] * SCALE_F + u0.x;
            s[t][1] = s[t][1] * SCALE_F + u0.y;
            s[t][2] = s[t][2] * SCALE_F + u1.x;
            s[t][3] = s[t][3] * SCALE_F + u1.y;
            mx0 = fmaxf(mx0, fmaxf(s[t][0], s[t][1]));
            mx1 = fmaxf(mx1, fmaxf(s[t][2], s[t][3]));
        }
        mx0 = fmaxf(mx0, __shfl_xor_sync(0xFFFFFFFFu, mx0, 1));
        mx0 = fmaxf(mx0, __shfl_xor_sync(0xFFFFFFFFu, mx0, 2));
        mx1 = fmaxf(mx1, __shfl_xor_sync(0xFFFFFFFFu, mx1, 1));
        mx1 = fmaxf(mx1, __shfl_xor_sync(0xFFFFFFFFu, mx1, 2));
        const float mn0 = fmaxf(m0v, mx0), mn1 = fmaxf(m1v, mx1);
        const float a0 = __expf(m0v - mn0), a1 = __expf(m1v - mn1);
        m0v = mn0; m1v = mn1;

        float ps0 = 0.f, ps1 = 0.f;
        #pragma unroll
        for (int t = 0; t < 16; t++) {
            s[t][0] = __expf(s[t][0] - mn0);
            s[t][1] = __expf(s[t][1] - mn0);
            s[t][2] = __expf(s[t][2] - mn1);
            s[t][3] = __expf(s[t][3] - mn1);
            ps0 += s[t][0] + s[t][1];
            ps1 += s[t][2] + s[t][3];
        }
        ps0 += __shfl_xor_sync(0xFFFFFFFFu, ps0, 1);
        ps0 += __shfl_xor_sync(0xFFFFFFFFu, ps0, 2);
        ps1 += __shfl_xor_sync(0xFFFFFFFFu, ps1, 1);
        ps1 += __shfl_xor_sync(0xFFFFFFFFu, ps1, 2);
        l0 = l0 * a0 + ps0;
        l1 = l1 * a1 + ps1;

        #pragma unroll
        for (int nt = 0; nt < 8; nt++) {
            o[nt][0] *= a0; o[nt][1] *= a0;
            o[nt][2] *= a1; o[nt][3] *= a1;
        }

        const uint32_t vh = kb + 32768u, vl = kb + 49152u;
        #pragma unroll
        for (int kt = 0; kt < 8; kt++) {
            uint32_t ph[4], pl[4];
            split2h(s[2*kt][0],   s[2*kt][1],   ph[0], pl[0]);
            split2h(s[2*kt][2],   s[2*kt][3],   ph[1], pl[1]);
            split2h(s[2*kt+1][0], s[2*kt+1][1], ph[2], pl[2]);
            split2h(s[2*kt+1][2], s[2*kt+1][3], ph[3], pl[3]);
            #pragma unroll
            for (int nt2 = 0; nt2 < 4; nt2++) {
                int vrow = kt * 16 + (j & 1) * 8 + r;
                int vch  = nt2 * 2 + (j >> 1);
                uint32_t sw = vrow * 128u + ((uint32_t)(vch ^ (vrow & 7)) << 4);
                uint32_t t4[4];
                ldsm4t(t4, vh + sw);
                uint32_t b0[2] = {t4[0], t4[1]}, b1[2] = {t4[2], t4[3]};
                mma16816(o[2*nt2],   ph, b0);
                mma16816(o[2*nt2+1], ph, b1);
                mma16816(o[2*nt2],   pl, b0);
                mma16816(o[2*nt2+1], pl, b1);
                ldsm4t(t4, vl + sw);
                uint32_t c0[2] = {t4[0], t4[1]}, c1[2] = {t4[2], t4[3]};
                mma16816(o[2*nt2],   ph, c0);
                mma16816(o[2*nt2+1], ph, c1);
            }
        }
        __syncthreads();
    }

    const float inv0 = 1.f / l0, inv1 = 1.f / l1;
    const int qrow = b * SS + q0 + wid * 16 + gi;
    #pragma unroll
    for (int nt = 0; nt < 8; nt++) {
        int col = h * DD + nt * 8 + ci * 2;
        float v00 = o[nt][0] * inv0, v01 = o[nt][1] * inv0;
        float v10 = o[nt][2] * inv1, v11 = o[nt][3] * inv1;
        size_t rw0 = (size_t)qrow * K2E + col;
        size_t rw1 = (size_t)(qrow + 8) * K2E + col;
        __half h0, lo0, h1, lo1;
        split_h(v00, h0, lo0); split_h(v01, h1, lo1);
        *reinterpret_cast<__half2*>(Op + rw0)      = __halves2half2(h0, h1);
        *reinterpret_cast<__half2*>(Op + rw0 + EE) = __halves2half2(lo0, lo1);
        split_h(v10, h0, lo0); split_h(v11, h1, lo1);
        *reinterpret_cast<__half2*>(Op + rw1)      = __halves2half2(h0, h1);
        *reinterpret_cast<__half2*>(Op + rw1 + EE) = __halves2half2(lo0, lo1);
    }
}

// ---------------------------------------------------------------------------
// transpose + split + pack (3-term): W[K,N] -> rows [Wh|Wh|Wl] at row_off
// ---------------------------------------------------------------------------
__global__ void transpose_pack3(const float* __restrict__ W,
                                __half* __restrict__ wp,
                                int K, int N, int row_off) {
    __shared__ float t[32][33];
    int tx = threadIdx.x, ty = threadIdx.y;
    int k0 = blockIdx.y * 32, n0 = blockIdx.x * 32;
    #pragma unroll
    for (int j = 0; j < 4; j++)
        t[ty + j*8][tx] = W[(size_t)(k0 + ty + j*8) * N + n0 + tx];
    __syncthreads();
    size_t K3 = 3 * (size_t)K;
    #pragma unroll
    for (int j = 0; j < 4; j++) {
        int nn = row_off + n0 + ty + j*8;
        int kk = k0 + tx;
        float v = t[tx][ty + j*8];
        __half h, l; split_h(v, h, l);
        wp[(size_t)nn * K3 + kk]       = h;
        wp[(size_t)nn * K3 + K + kk]   = h;
        wp[(size_t)nn * K3 + 2*K + kk] = l;
    }
}

// 2-term: W[K,N] -> rows [Wh|Wh] (lo dropped; pairs with split activations)
__global__ void transpose_pack2(const float* __restrict__ W,
                                __half* __restrict__ wp,
                                int K, int N) {
    __shared__ float t[32][33];
    int tx = threadIdx.x, ty = threadIdx.y;
    int k0 = blockIdx.y * 32, n0 = blockIdx.x * 32;
    #pragma unroll
    for (int j = 0; j < 4; j++)
        t[ty + j*8][tx] = W[(size_t)(k0 + ty + j*8) * N + n0 + tx];
    __syncthreads();
    size_t K2 = 2 * (size_t)K;
    #pragma unroll
    for (int j = 0; j < 4; j++) {
        int nn = n0 + ty + j*8;
        int kk = k0 + tx;
        __half h = __float2half_rn(t[tx][ty + j*8]);
        wp[(size_t)nn * K2 + kk]     = h;
        wp[(size_t)nn * K2 + K + kk] = h;
    }
}

// ---------------------------------------------------------------------------
__global__ void bias_cat(const float* __restrict__ bq, const float* __restrict__ bk,
                         const float* __restrict__ bv, float* __restrict__ dst) {
    int i = blockIdx.x * 256 + threadIdx.x;
    if (i < NQKV)
        dst[i] = (i < EE) ? bq[i] : (i < 2*EE) ? bk[i - EE] : bv[i - 2*EE];
}

// ---------------------------------------------------------------------------
// LayerNorm -> packed fp16.  PACK3: [h|l|h] width 3E;  PACK2: [h|l] width 2E.
// ---------------------------------------------------------------------------
template<int PACK>
__global__ void ln_pack(const float* __restrict__ x,
                        const float* __restrict__ g,
                        const float* __restrict__ b,
                        __half* __restrict__ pk) {
    int row = blockIdx.x;
    const float* xr = x + (size_t)row * EE;
    float s = 0.f, s2 = 0.f;
    for (int i = threadIdx.x; i < EE; i += 256) {
        float v = xr[i]; s += v; s2 += v * v;
    }
    __shared__ float rs[8], rs2[8];
    #pragma unroll
    for (int o = 16; o > 0; o >>= 1) {
        s  += __shfl_xor_sync(0xFFFFFFFFu, s,  o);
        s2 += __shfl_xor_sync(0xFFFFFFFFu, s2, o);
    }
    if ((threadIdx.x & 31) == 0) { rs[threadIdx.x>>5] = s; rs2[threadIdx.x>>5] = s2; }
    __syncthreads();
    float ts = 0.f, ts2 = 0.f;
    #pragma unroll
    for (int i = 0; i < 8; i++) { ts += rs[i]; ts2 += rs2[i]; }
    float mean = ts * (1.0f / EE);
    float var  = ts2 * (1.0f / EE) - mean * mean;
    float inv  = rsqrtf(var + EPSF);
    size_t rw = (size_t)row * (PACK * EE);
    for (int i = threadIdx.x; i < EE; i += 256) {
        float y = (xr[i] - mean) * inv * g[i] + b[i];
        __half h, l; split_h(y, h, l);
        pk[rw + i]      = h;
        pk[rw + EE + i] = l;
        if (PACK == 3) pk[rw + 2*EE + i] = h;
    }
}

// ---------------------------------------------------------------------------
extern "C" void kernel_launch(void* const* d_in, const int* in_sizes, int n_in,
                              void* d_out, int out_size) {
    const float* hs   = (const float*)d_in[0];
    const float* mask = (const float*)d_in[1];
    const float* wq   = (const float*)d_in[2];
    const float* bq   = (const float*)d_in[3];
    const float* wk   = (const float*)d_in[4];
    const float* bk   = (const float*)d_in[5];
    const float* wv   = (const float*)d_in[6];
    const float* bv   = (const float*)d_in[7];
    const float* wo   = (const float*)d_in[8];
    const float* bo   = (const float*)d_in[9];
    const float* ln1g = (const float*)d_in[10];
    const float* ln1b = (const float*)d_in[11];
    const float* ln2g = (const float*)d_in[12];
    const float* ln2b = (const float*)d_in[13];
    const float* w1   = (const float*)d_in[14];
    const float* b1   = (const float*)d_in[15];
    const float* w2   = (const float*)d_in[16];
    const float* b2   = (const float*)d_in[17];
    float* out = (float*)d_out;

    float *x, *bqkv;
    __half *h1p, *h2p, *qkv, *op, *mp, *wqkvp, *wop, *w1p, *w2p;
    cudaGetSymbolAddress((void**)&x,     g_x);
    cudaGetSymbolAddress((void**)&bqkv,  g_bqkv);
    cudaGetSymbolAddress((void**)&h1p,   g_h1p);
    cudaGetSymbolAddress((void**)&h2p,   g_h2p);
    cudaGetSymbolAddress((void**)&qkv,   g_qkv);
    cudaGetSymbolAddress((void**)&op,    g_op);
    cudaGetSymbolAddress((void**)&mp,    g_mp);
    cudaGetSymbolAddress((void**)&wqkvp, g_wqkvp);
    cudaGetSymbolAddress((void**)&wop,   g_wop);
    cudaGetSymbolAddress((void**)&w1p,   g_w1p);
    cudaGetSymbolAddress((void**)&w2p,   g_w2p);

    cudaFuncSetAttribute(flash_attn, cudaFuncAttributeMaxDynamicSharedMemorySize, FA_SMEM);
    cudaFuncSetAttribute(mma_gemm<1>, cudaFuncAttributeMaxDynamicSharedMemorySize, GEMM_SMEM);
    cudaFuncSetAttribute(mma_gemm<2>, cudaFuncAttributeMaxDynamicSharedMemorySize, GEMM_SMEM);
    cudaFuncSetAttribute(mma_gemm<3>, cudaFuncAttributeMaxDynamicSharedMemorySize, GEMM_SMEM);

    dim3 tb(32, 8);
    transpose_pack3<<<dim3(EE/32, EE/32), tb>>>(wq, wqkvp, EE, EE, 0);
    transpose_pack3<<<dim3(EE/32, EE/32), tb>>>(wk, wqkvp, EE, EE, EE);
    transpose_pack3<<<dim3(EE/32, EE/32), tb>>>(wv, wqkvp, EE, EE, 2*EE);
    transpose_pack2<<<dim3(EE/32, EE/32), tb>>>(wo, wop, EE, EE);
    transpose_pack2<<<dim3(II/32, EE/32), tb>>>(w1, w1p, EE, II);
    transpose_pack2<<<dim3(EE/32, II/32), tb>>>(w2, w2p, II, EE);
    bias_cat<<<(NQKV + 255) / 256, 256>>>(bq, bk, bv, bqkv);

    // 1. LN1 -> [h|l|h]
    ln_pack<3><<<MR, 256>>>(hs, ln1g, ln1b, h1p);

    // 2. fused QKV projection (3-pass) -> qkv [H|L]
    mma_gemm<3><<<dim3(NQKV/128, MR/128), 256, GEMM_SMEM>>>(
        h1p, wqkvp, bqkv, nullptr, nullptr, qkv, MR, NQKV, K3E);

    // 3. fused flash attention -> op [h|l]
    flash_attn<<<dim3(SS/128, BB*HH), 256, FA_SMEM>>>(qkv, mask, op);

    // 4. O-proj (2-pass) + residual(hs) -> x
    mma_gemm<2><<<dim3(EE/128, MR/128), 256, GEMM_SMEM>>>(
        op, wop, bo, hs, x, nullptr, MR, EE, K2E);

    // 5. LN2 -> [h|l]
    ln_pack<2><<<MR, 256>>>(x, ln2g, ln2b, h2p);

    // 6. MLP up + gelu (2-pass) -> mp [h|l]
    mma_gemm<1><<<dim3(II/128, MR/128), 256, GEMM_SMEM>>>(
        h2p, w1p, b1, nullptr, nullptr, mp, MR, II, K2E);

    // 7. MLP down (2-pass) + residual(x) -> out
    mma_gemm<2><<<dim3(EE/128, MR/128), 256, GEMM_SMEM>>>(
        mp, w2p, b2, x, out, nullptr, MR, EE, K2I);
}

// round 9
// speedup vs baseline: 4.5698x; 1.4488x over previous
#include <cuda_runtime.h>
#include <cuda_fp16.h>
#include <math.h>
#include <stdint.h>

// ---------------------------------------------------------------------------
// SiglipEncoderLayer  B=8 S=1024 E=768 H=12 D=64 I=3072  fp32 in/out
// R9 (= R8 resubmission; R8 bench died to container flake, code audited clean)
// QK-proj + QK^T = 3-pass fp16 (score precision);
// V-proj / O-proj / MLP = 1-pass plain fp16; PV = 2-pass (P split, Vh).
// ---------------------------------------------------------------------------

#define BB   8
#define SS   1024
#define EE   768
#define HH   12
#define DD   64
#define II   3072
#define MR   (BB*SS)            // 8192
#define K3E  (3*EE)             // 2304
#define NQK  (2*EE)             // 1536 (q|k outputs)
#define RQK  (2*NQK)            // 3072 qk row width [H|L]
#define EPSF 1e-6f
#define SCALE_F 0.125f

// ---- scratch (device globals, 128B aligned) -------------------------------
__device__ __align__(128) float g_x [MR*EE];
__device__ __align__(128) float g_bqk[NQK];

__device__ __align__(128) __half g_h1p[(size_t)MR*K3E];   // ln1 [h|l|h]
__device__ __align__(128) __half g_h2 [(size_t)MR*EE];    // ln2 plain
__device__ __align__(128) __half g_qk [(size_t)MR*RQK];   // qk [H(1536)|L(1536)]
__device__ __align__(128) __half g_v  [(size_t)MR*EE];    // v plain
__device__ __align__(128) __half g_o  [(size_t)MR*EE];    // attn out plain
__device__ __align__(128) __half g_m  [(size_t)MR*II];    // gelu out plain

__device__ __align__(128) __half g_wqkp[(size_t)NQK*K3E]; // [Wh|Wh|Wl]
__device__ __align__(128) __half g_wv [(size_t)EE*EE];    // plain [N][K]
__device__ __align__(128) __half g_wo [(size_t)EE*EE];
__device__ __align__(128) __half g_w1 [(size_t)II*EE];
__device__ __align__(128) __half g_w2 [(size_t)EE*II];

// ---------------------------------------------------------------------------
__device__ __forceinline__ uint32_t smem_u32(const void* p) {
    uint32_t a;
    asm("{ .reg .u64 t; cvta.to.shared.u64 t, %1; cvt.u32.u64 %0, t; }"
        : "=r"(a) : "l"(p));
    return a;
}
__device__ __forceinline__ void cp_async16(uint32_t s, const void* g) {
    asm volatile("cp.async.cg.shared.global [%0], [%1], 16;" :: "r"(s), "l"(g) : "memory");
}
#define CP_COMMIT() asm volatile("cp.async.commit_group;" ::: "memory")
#define CP_WAIT(n)  asm volatile("cp.async.wait_group %0;" :: "n"(n) : "memory")

__device__ __forceinline__ void ldsm4(uint32_t* r, uint32_t addr) {
    asm volatile("ldmatrix.sync.aligned.m8n8.x4.shared.b16 {%0,%1,%2,%3}, [%4];"
        : "=r"(r[0]), "=r"(r[1]), "=r"(r[2]), "=r"(r[3]) : "r"(addr));
}
__device__ __forceinline__ void ldsm4t(uint32_t* r, uint32_t addr) {
    asm volatile("ldmatrix.sync.aligned.m8n8.x4.trans.shared.b16 {%0,%1,%2,%3}, [%4];"
        : "=r"(r[0]), "=r"(r[1]), "=r"(r[2]), "=r"(r[3]) : "r"(addr));
}
__device__ __forceinline__ void mma16816(float* d, const uint32_t* a, const uint32_t* b) {
    asm volatile(
        "mma.sync.aligned.m16n8k16.row.col.f32.f16.f16.f32 "
        "{%0,%1,%2,%3}, {%4,%5,%6,%7}, {%8,%9}, {%0,%1,%2,%3};"
        : "+f"(d[0]), "+f"(d[1]), "+f"(d[2]), "+f"(d[3])
        : "r"(a[0]), "r"(a[1]), "r"(a[2]), "r"(a[3]), "r"(b[0]), "r"(b[1]));
}
__device__ __forceinline__ float gelu_tanh(float x) {
    float x3 = x * x * x;
    float t  = tanhf(0.7978845608028654f * (x + 0.044715f * x3));
    return 0.5f * x * (1.0f + t);
}
__device__ __forceinline__ void split_h(float v, __half& h, __half& l) {
    h = __float2half_rn(v);
    l = __float2half_rn(v - __half2float(h));
}
__device__ __forceinline__ void split2h(float x, float y, uint32_t& hi, uint32_t& lo) {
    __half hx, lx, hy, ly;
    split_h(x, hx, lx); split_h(y, hy, ly);
    __half2 H = __halves2half2(hx, hy);
    __half2 L = __halves2half2(lx, ly);
    hi = *reinterpret_cast<uint32_t*>(&H);
    lo = *reinterpret_cast<uint32_t*>(&L);
}

// ---------------------------------------------------------------------------
// mma.sync GEMM (fp16), 4-stage cp.async ring, separate lda/ldw.
//   MODE 0: opk plain = acc + bias                       (V-proj)
//   MODE 1: opk plain = gelu(acc + bias)                 (MLP up)
//   MODE 2: outf fp32 = acc + bias + res                 (O-proj, MLP down)
//   MODE 3: opk [H|L] width 2N = split(acc + bias)       (QK-proj)
// ---------------------------------------------------------------------------
#define GEMM_NS    4
#define GEMM_STG   16384
#define GEMM_SMEM  (GEMM_NS * GEMM_STG)

template<int MODE>
__global__ __launch_bounds__(256, 2)
void mma_gemm(const __half* __restrict__ A,
              const __half* __restrict__ W,
              const float* __restrict__ bias, const float* __restrict__ res,
              float* __restrict__ outf, __half* __restrict__ opk,
              int M, int N, int KP, int lda, int ldw) {
    extern __shared__ __align__(128) char smbuf[];

    const int tid  = threadIdx.x;
    const int wid  = tid >> 5;
    const int lane = tid & 31;
    const int wm   = wid & 3;
    const int wn   = wid >> 2;
    const int m0   = blockIdx.y * 128;
    const int n0   = blockIdx.x * 128;

    const uint32_t sb = smem_u32(smbuf);

    float acc[2][8][4];
    #pragma unroll
    for (int mf = 0; mf < 2; mf++)
        #pragma unroll
        for (int nf = 0; nf < 8; nf++)
            #pragma unroll
            for (int r = 0; r < 4; r++) acc[mf][nf][r] = 0.f;

    const int nc = KP >> 5;

    auto loadc = [&](int c, int s) {
        const int k0 = c << 5;
        uint32_t as = sb + (uint32_t)s * GEMM_STG;
        uint32_t bs = as + 8192u;
        #pragma unroll
        for (int i = 0; i < 2; i++) {
            int cid = tid + i * 256;
            int row = cid >> 2, ch = cid & 3;
            uint32_t soff = row * 64u + ((uint32_t)(ch ^ (row & 3)) << 4);
            cp_async16(as + soff, A + (size_t)(m0 + row) * lda + k0 + ch * 8);
            cp_async16(bs + soff, W + (size_t)(n0 + row) * ldw + k0 + ch * 8);
        }
    };

    #pragma unroll
    for (int p = 0; p < GEMM_NS - 1; p++) { loadc(p, p); CP_COMMIT(); }

    for (int c = 0; c < nc; c++) {
        CP_WAIT(GEMM_NS - 2);
        __syncthreads();

        const uint32_t as = sb + (uint32_t)(c & (GEMM_NS - 1)) * GEMM_STG;
        const uint32_t bs = as + 8192u;
        const int j = lane >> 3, r = lane & 7;

        #pragma unroll
        for (int ks = 0; ks < 2; ks++) {
            uint32_t af[2][4];
            #pragma unroll
            for (int mf = 0; mf < 2; mf++) {
                int row = wm * 32 + mf * 16 + (j & 1) * 8 + r;
                int kc  = ks * 2 + (j >> 1);
                ldsm4(af[mf], as + row * 64u + ((uint32_t)(kc ^ (row & 3)) << 4));
            }
            uint32_t bf[8][2];
            #pragma unroll
            for (int tp = 0; tp < 4; tp++) {
                int nrow = wn * 64 + tp * 16 + (j >> 1) * 8 + r;
                int kc   = ks * 2 + (j & 1);
                uint32_t t4[4];
                ldsm4(t4, bs + nrow * 64u + ((uint32_t)(kc ^ (nrow & 3)) << 4));
                bf[2*tp][0]   = t4[0]; bf[2*tp][1]   = t4[1];
                bf[2*tp+1][0] = t4[2]; bf[2*tp+1][1] = t4[3];
            }
            #pragma unroll
            for (int mf = 0; mf < 2; mf++)
                #pragma unroll
                for (int nf = 0; nf < 8; nf++)
                    mma16816(acc[mf][nf], af[mf], bf[nf]);
        }
        __syncthreads();

        const int nxt = c + GEMM_NS - 1;
        if (nxt < nc) loadc(nxt, nxt & (GEMM_NS - 1));
        CP_COMMIT();
    }

    const int gi = lane >> 2, ci = lane & 3;
    #pragma unroll
    for (int mf = 0; mf < 2; mf++) {
        int r0 = m0 + wm * 32 + mf * 16 + gi;
        #pragma unroll
        for (int nf = 0; nf < 8; nf++) {
            int col = n0 + wn * 64 + nf * 8 + ci * 2;
            float b0 = bias[col], b1 = bias[col + 1];
            float v00 = acc[mf][nf][0] + b0, v01 = acc[mf][nf][1] + b1;
            float v10 = acc[mf][nf][2] + b0, v11 = acc[mf][nf][3] + b1;
            if (MODE == 0 || MODE == 1) {
                if (MODE == 1) {
                    v00 = gelu_tanh(v00); v01 = gelu_tanh(v01);
                    v10 = gelu_tanh(v10); v11 = gelu_tanh(v11);
                }
                *reinterpret_cast<__half2*>(opk + (size_t)r0 * N + col) =
                    __halves2half2(__float2half_rn(v00), __float2half_rn(v01));
                *reinterpret_cast<__half2*>(opk + (size_t)(r0 + 8) * N + col) =
                    __halves2half2(__float2half_rn(v10), __float2half_rn(v11));
            } else if (MODE == 3) {
                __half h0,l0,h1,l1;
                size_t rw = (size_t)r0 * (2 * N) + col;
                split_h(v00, h0, l0); split_h(v01, h1, l1);
                *reinterpret_cast<__half2*>(opk + rw)     = __halves2half2(h0, h1);
                *reinterpret_cast<__half2*>(opk + rw + N) = __halves2half2(l0, l1);
                size_t rw2 = (size_t)(r0 + 8) * (2 * N) + col;
                split_h(v10, h0, l0); split_h(v11, h1, l1);
                *reinterpret_cast<__half2*>(opk + rw2)     = __halves2half2(h0, h1);
                *reinterpret_cast<__half2*>(opk + rw2 + N) = __halves2half2(l0, l1);
            } else {
                const float2 r00 = *reinterpret_cast<const float2*>(res + (size_t)r0 * N + col);
                const float2 r10 = *reinterpret_cast<const float2*>(res + (size_t)(r0 + 8) * N + col);
                v00 += r00.x; v01 += r00.y; v10 += r10.x; v11 += r10.y;
                *reinterpret_cast<float2*>(outf + (size_t)r0 * N + col)       = make_float2(v00, v01);
                *reinterpret_cast<float2*>(outf + (size_t)(r0 + 8) * N + col) = make_float2(v10, v11);
            }
        }
    }
}

// ---------------------------------------------------------------------------
// Fused flash attention.
//   QK buf: rows [H(1536)|L(1536)], q_h at h*64, k_h at 768+h*64, lo +1536.
//   V buf: plain rows of 768.
//   QK^T = Qh.Kh + Ql.Kh + Qh.Kl (3-pass). PV = (Ph+Pl).Vh (2-pass).
//   Output: plain fp16 rows of 768.
// ---------------------------------------------------------------------------
#define FA_STG  49152                   // Kh,Kl,Vh = 3 x 16KB
#define FA_SMEM (32768 + 2*FA_STG)      // Q(h,l) + 2 stages = 128 KB

__global__ __launch_bounds__(256, 1)
void flash_attn(const __half* __restrict__ QK,
                const __half* __restrict__ V,
                const float* __restrict__ mask,
                __half* __restrict__ Op) {
    extern __shared__ __align__(128) char fsm[];
    const uint32_t sb = smem_u32(fsm);
    const int tid = threadIdx.x, wid = tid >> 5, lane = tid & 31;
    const int qt = blockIdx.x, bh = blockIdx.y;
    const int b = bh / HH, h = bh - b * HH;
    const int q0 = qt * 128;
    const int j = lane >> 3, r = lane & 7;
    const int gi = lane >> 2, ci = lane & 3;

    const int qoff = h * DD;            // q_h; lo at +NQK
    const int koff = EE + h * DD;       // k_h; lo at +NQK

    const uint32_t sQh = sb, sQl = sb + 16384u;
    const uint32_t stg0 = sb + 32768u;

    {
        const size_t rbase = (size_t)(b * SS + q0);
        #pragma unroll
        for (int i = 0; i < 4; i++) {
            int idx = tid + i * 256;
            int row = idx >> 3, ch = idx & 7;
            uint32_t d = row * 128u + ((uint32_t)(ch ^ (row & 7)) << 4);
            const __half* g = QK + (rbase + row) * RQK + qoff + ch * 8;
            cp_async16(sQh + d, g);
            cp_async16(sQl + d, g + NQK);
        }
    }
    auto loadKV = [&](int it, int st) {
        const size_t rbase = (size_t)(b * SS + it * 128);
        uint32_t base = stg0 + st * (uint32_t)FA_STG;
        #pragma unroll
        for (int i = 0; i < 4; i++) {
            int idx = tid + i * 256;
            int row = idx >> 3, ch = idx & 7;
            const __half* gk = QK + (rbase + row) * RQK + koff + ch * 8;
            const __half* gv = V  + (rbase + row) * EE  + h * DD + ch * 8;
            uint32_t d = base + row * 128u + ((uint32_t)(ch ^ (row & 7)) << 4);
            cp_async16(d,          gk);          // Kh
            cp_async16(d + 16384u, gk + NQK);    // Kl
            cp_async16(d + 32768u, gv);          // Vh
        }
    };

    loadKV(0, 0);
    CP_COMMIT();

    float m0v = -1e30f, m1v = -1e30f, l0 = 0.f, l1 = 0.f;
    float o[8][4];
    #pragma unroll
    for (int nt = 0; nt < 8; nt++)
        #pragma unroll
        for (int t = 0; t < 4; t++) o[nt][t] = 0.f;

    const int NIT = SS / 128;
    for (int it = 0; it < NIT; it++) {
        const int st = it & 1;
        if (it + 1 < NIT) { loadKV(it + 1, st ^ 1); CP_COMMIT(); CP_WAIT(1); }
        else              { CP_WAIT(0); }
        __syncthreads();

        const uint32_t kb = stg0 + st * (uint32_t)FA_STG;

        float s[16][4];
        #pragma unroll
        for (int t = 0; t < 16; t++)
            #pragma unroll
            for (int u = 0; u < 4; u++) s[t][u] = 0.f;

        #pragma unroll
        for (int sec = 0; sec < 3; sec++) {
            const uint32_t qb = (sec == 1) ? sQl : sQh;
            const uint32_t kk = kb + ((sec == 2) ? 16384u : 0u);
            #pragma unroll
            for (int kc = 0; kc < 4; kc++) {
                uint32_t af[4];
                int arow = wid * 16 + (j & 1) * 8 + r;
                int ach  = kc * 2 + (j >> 1);
                ldsm4(af, qb + arow * 128u + ((uint32_t)(ach ^ (arow & 7)) << 4));
                #pragma unroll
                for (int nt2 = 0; nt2 < 8; nt2++) {
                    int brow = nt2 * 16 + (j >> 1) * 8 + r;
                    int bch  = kc * 2 + (j & 1);
                    uint32_t t4[4];
                    ldsm4(t4, kk + brow * 128u + ((uint32_t)(bch ^ (brow & 7)) << 4));
                    uint32_t b0[2] = {t4[0], t4[1]}, b1[2] = {t4[2], t4[3]};
                    mma16816(s[2*nt2],   af, b0);
                    mma16816(s[2*nt2+1], af, b1);
                }
            }
        }

        const float* mr0 = mask + ((size_t)b * SS + (q0 + wid * 16 + gi)) * SS + it * 128;
        const float* mr1 = mr0 + 8 * (size_t)SS;
        float mx0 = -1e30f, mx1 = -1e30f;
        #pragma unroll
        for (int t = 0; t < 16; t++) {
            float2 u0 = *reinterpret_cast<const float2*>(mr0 + t * 8 + ci * 2);
            float2 u1 = *reinterpret_cast<const float2*>(mr1 + t * 8 + ci * 2);
            s[t][0] = s[t][0] * SCALE_F + u0.x;
            s[t][1] = s[t][1] * SCALE_F + u0.y;
            s[t][2] = s[t][2] * SCALE_F + u1.x;
            s[t][3] = s[t][3] * SCALE_F + u1.y;
            mx0 = fmaxf(mx0, fmaxf(s[t][0], s[t][1]));
            mx1 = fmaxf(mx1, fmaxf(s[t][2], s[t][3]));
        }
        mx0 = fmaxf(mx0, __shfl_xor_sync(0xFFFFFFFFu, mx0, 1));
        mx0 = fmaxf(mx0, __shfl_xor_sync(0xFFFFFFFFu, mx0, 2));
        mx1 = fmaxf(mx1, __shfl_xor_sync(0xFFFFFFFFu, mx1, 1));
        mx1 = fmaxf(mx1, __shfl_xor_sync(0xFFFFFFFFu, mx1, 2));
        const float mn0 = fmaxf(m0v, mx0), mn1 = fmaxf(m1v, mx1);
        const float a0 = __expf(m0v - mn0), a1 = __expf(m1v - mn1);
        m0v = mn0; m1v = mn1;

        float ps0 = 0.f, ps1 = 0.f;
        #pragma unroll
        for (int t = 0; t < 16; t++) {
            s[t][0] = __expf(s[t][0] - mn0);
            s[t][1] = __expf(s[t][1] - mn0);
            s[t][2] = __expf(s[t][2] - mn1);
            s[t][3] = __expf(s[t][3] - mn1);
            ps0 += s[t][0] + s[t][1];
            ps1 += s[t][2] + s[t][3];
        }
        ps0 += __shfl_xor_sync(0xFFFFFFFFu, ps0, 1);
        ps0 += __shfl_xor_sync(0xFFFFFFFFu, ps0, 2);
        ps1 += __shfl_xor_sync(0xFFFFFFFFu, ps1, 1);
        ps1 += __shfl_xor_sync(0xFFFFFFFFu, ps1, 2);
        l0 = l0 * a0 + ps0;
        l1 = l1 * a1 + ps1;

        #pragma unroll
        for (int nt = 0; nt < 8; nt++) {
            o[nt][0] *= a0; o[nt][1] *= a0;
            o[nt][2] *= a1; o[nt][3] *= a1;
        }

        const uint32_t vh = kb + 32768u;
        #pragma unroll
        for (int kt = 0; kt < 8; kt++) {
            uint32_t ph[4], pl[4];
            split2h(s[2*kt][0],   s[2*kt][1],   ph[0], pl[0]);
            split2h(s[2*kt][2],   s[2*kt][3],   ph[1], pl[1]);
            split2h(s[2*kt+1][0], s[2*kt+1][1], ph[2], pl[2]);
            split2h(s[2*kt+1][2], s[2*kt+1][3], ph[3], pl[3]);
            #pragma unroll
            for (int nt2 = 0; nt2 < 4; nt2++) {
                int vrow = kt * 16 + (j & 1) * 8 + r;
                int vch  = nt2 * 2 + (j >> 1);
                uint32_t sw = vrow * 128u + ((uint32_t)(vch ^ (vrow & 7)) << 4);
                uint32_t t4[4];
                ldsm4t(t4, vh + sw);
                uint32_t b0[2] = {t4[0], t4[1]}, b1[2] = {t4[2], t4[3]};
                mma16816(o[2*nt2],   ph, b0);
                mma16816(o[2*nt2+1], ph, b1);
                mma16816(o[2*nt2],   pl, b0);
                mma16816(o[2*nt2+1], pl, b1);
            }
        }
        __syncthreads();
    }

    const float inv0 = 1.f / l0, inv1 = 1.f / l1;
    const int qrow = b * SS + q0 + wid * 16 + gi;
    #pragma unroll
    for (int nt = 0; nt < 8; nt++) {
        int col = h * DD + nt * 8 + ci * 2;
        *reinterpret_cast<__half2*>(Op + (size_t)qrow * EE + col) =
            __halves2half2(__float2half_rn(o[nt][0] * inv0),
                           __float2half_rn(o[nt][1] * inv0));
        *reinterpret_cast<__half2*>(Op + (size_t)(qrow + 8) * EE + col) =
            __halves2half2(__float2half_rn(o[nt][2] * inv1),
                           __float2half_rn(o[nt][3] * inv1));
    }
}

// ---------------------------------------------------------------------------
// transpose + split + pack (3-term): W[K,N] -> rows [Wh|Wh|Wl] at row_off
// ---------------------------------------------------------------------------
__global__ void transpose_pack3(const float* __restrict__ W,
                                __half* __restrict__ wp,
                                int K, int N, int row_off) {
    __shared__ float t[32][33];
    int tx = threadIdx.x, ty = threadIdx.y;
    int k0 = blockIdx.y * 32, n0 = blockIdx.x * 32;
    #pragma unroll
    for (int j = 0; j < 4; j++)
        t[ty + j*8][tx] = W[(size_t)(k0 + ty + j*8) * N + n0 + tx];
    __syncthreads();
    size_t K3 = 3 * (size_t)K;
    #pragma unroll
    for (int j = 0; j < 4; j++) {
        int nn = row_off + n0 + ty + j*8;
        int kk = k0 + tx;
        float v = t[tx][ty + j*8];
        __half h, l; split_h(v, h, l);
        wp[(size_t)nn * K3 + kk]       = h;
        wp[(size_t)nn * K3 + K + kk]   = h;
        wp[(size_t)nn * K3 + 2*K + kk] = l;
    }
}

// plain 1-term transpose: W[K,N] -> wp[N][K] fp16
__global__ void transpose_pack1(const float* __restrict__ W,
                                __half* __restrict__ wp,
                                int K, int N) {
    __shared__ float t[32][33];
    int tx = threadIdx.x, ty = threadIdx.y;
    int k0 = blockIdx.y * 32, n0 = blockIdx.x * 32;
    #pragma unroll
    for (int j = 0; j < 4; j++)
        t[ty + j*8][tx] = W[(size_t)(k0 + ty + j*8) * N + n0 + tx];
    __syncthreads();
    #pragma unroll
    for (int j = 0; j < 4; j++) {
        int nn = n0 + ty + j*8;
        int kk = k0 + tx;
        wp[(size_t)nn * K + kk] = __float2half_rn(t[tx][ty + j*8]);
    }
}

// ---------------------------------------------------------------------------
__global__ void bias_cat2(const float* __restrict__ bq, const float* __restrict__ bk,
                          float* __restrict__ dst) {
    int i = blockIdx.x * 256 + threadIdx.x;
    if (i < NQK)
        dst[i] = (i < EE) ? bq[i] : bk[i - EE];
}

// ---------------------------------------------------------------------------
// LayerNorm. PACK3: [h|l|h] width 3E.  PACK1: plain fp16 width E.
// ---------------------------------------------------------------------------
template<int PACK>
__global__ void ln_pack(const float* __restrict__ x,
                        const float* __restrict__ g,
                        const float* __restrict__ b,
                        __half* __restrict__ pk) {
    int row = blockIdx.x;
    const float* xr = x + (size_t)row * EE;
    float s = 0.f, s2 = 0.f;
    for (int i = threadIdx.x; i < EE; i += 256) {
        float v = xr[i]; s += v; s2 += v * v;
    }
    __shared__ float rs[8], rs2[8];
    #pragma unroll
    for (int o = 16; o > 0; o >>= 1) {
        s  += __shfl_xor_sync(0xFFFFFFFFu, s,  o);
        s2 += __shfl_xor_sync(0xFFFFFFFFu, s2, o);
    }
    if ((threadIdx.x & 31) == 0) { rs[threadIdx.x>>5] = s; rs2[threadIdx.x>>5] = s2; }
    __syncthreads();
    float ts = 0.f, ts2 = 0.f;
    #pragma unroll
    for (int i = 0; i < 8; i++) { ts += rs[i]; ts2 += rs2[i]; }
    float mean = ts * (1.0f / EE);
    float var  = ts2 * (1.0f / EE) - mean * mean;
    float inv  = rsqrtf(var + EPSF);
    size_t rw = (size_t)row * (PACK * EE);
    for (int i = threadIdx.x; i < EE; i += 256) {
        float y = (xr[i] - mean) * inv * g[i] + b[i];
        if (PACK == 3) {
            __half h, l; split_h(y, h, l);
            pk[rw + i]        = h;
            pk[rw + EE + i]   = l;
            pk[rw + 2*EE + i] = h;
        } else {
            pk[rw + i] = __float2half_rn(y);
        }
    }
}

// ---------------------------------------------------------------------------
extern "C" void kernel_launch(void* const* d_in, const int* in_sizes, int n_in,
                              void* d_out, int out_size) {
    const float* hs   = (const float*)d_in[0];
    const float* mask = (const float*)d_in[1];
    const float* wq   = (const float*)d_in[2];
    const float* bq   = (const float*)d_in[3];
    const float* wk   = (const float*)d_in[4];
    const float* bk   = (const float*)d_in[5];
    const float* wv   = (const float*)d_in[6];
    const float* bv   = (const float*)d_in[7];
    const float* wo   = (const float*)d_in[8];
    const float* bo   = (const float*)d_in[9];
    const float* ln1g = (const float*)d_in[10];
    const float* ln1b = (const float*)d_in[11];
    const float* ln2g = (const float*)d_in[12];
    const float* ln2b = (const float*)d_in[13];
    const float* w1   = (const float*)d_in[14];
    const float* b1   = (const float*)d_in[15];
    const float* w2   = (const float*)d_in[16];
    const float* b2   = (const float*)d_in[17];
    float* out = (float*)d_out;

    float *x, *bqk;
    __half *h1p, *h2, *qk, *v, *o, *m, *wqkp, *wv_, *wo_, *w1_, *w2_;
    cudaGetSymbolAddress((void**)&x,    g_x);
    cudaGetSymbolAddress((void**)&bqk,  g_bqk);
    cudaGetSymbolAddress((void**)&h1p,  g_h1p);
    cudaGetSymbolAddress((void**)&h2,   g_h2);
    cudaGetSymbolAddress((void**)&qk,   g_qk);
    cudaGetSymbolAddress((void**)&v,    g_v);
    cudaGetSymbolAddress((void**)&o,    g_o);
    cudaGetSymbolAddress((void**)&m,    g_m);
    cudaGetSymbolAddress((void**)&wqkp, g_wqkp);
    cudaGetSymbolAddress((void**)&wv_,  g_wv);
    cudaGetSymbolAddress((void**)&wo_,  g_wo);
    cudaGetSymbolAddress((void**)&w1_,  g_w1);
    cudaGetSymbolAddress((void**)&w2_,  g_w2);

    cudaFuncSetAttribute(flash_attn, cudaFuncAttributeMaxDynamicSharedMemorySize, FA_SMEM);
    cudaFuncSetAttribute(mma_gemm<0>, cudaFuncAttributeMaxDynamicSharedMemorySize, GEMM_SMEM);
    cudaFuncSetAttribute(mma_gemm<1>, cudaFuncAttributeMaxDynamicSharedMemorySize, GEMM_SMEM);
    cudaFuncSetAttribute(mma_gemm<2>, cudaFuncAttributeMaxDynamicSharedMemorySize, GEMM_SMEM);
    cudaFuncSetAttribute(mma_gemm<3>, cudaFuncAttributeMaxDynamicSharedMemorySize, GEMM_SMEM);

    dim3 tb(32, 8);
    transpose_pack3<<<dim3(EE/32, EE/32), tb>>>(wq, wqkp, EE, EE, 0);
    transpose_pack3<<<dim3(EE/32, EE/32), tb>>>(wk, wqkp, EE, EE, EE);
    transpose_pack1<<<dim3(EE/32, EE/32), tb>>>(wv, wv_, EE, EE);
    transpose_pack1<<<dim3(EE/32, EE/32), tb>>>(wo, wo_, EE, EE);
    transpose_pack1<<<dim3(II/32, EE/32), tb>>>(w1, w1_, EE, II);
    transpose_pack1<<<dim3(EE/32, II/32), tb>>>(w2, w2_, II, EE);
    bias_cat2<<<(NQK + 255) / 256, 256>>>(bq, bk, bqk);

    // 1. LN1 -> [h|l|h]
    ln_pack<3><<<MR, 256>>>(hs, ln1g, ln1b, h1p);

    // 2a. QK projection (3-pass) -> qk [H|L]
    mma_gemm<3><<<dim3(NQK/128, MR/128), 256, GEMM_SMEM>>>(
        h1p, wqkp, bqk, nullptr, nullptr, qk, MR, NQK, K3E, K3E, K3E);
    // 2b. V projection (1-pass: hi section of h1p x plain wv) -> v
    mma_gemm<0><<<dim3(EE/128, MR/128), 256, GEMM_SMEM>>>(
        h1p, wv_, bv, nullptr, nullptr, v, MR, EE, EE, K3E, EE);

    // 3. fused flash attention -> o (plain fp16)
    flash_attn<<<dim3(SS/128, BB*HH), 256, FA_SMEM>>>(qk, v, mask, o);

    // 4. O-proj (1-pass) + residual(hs) -> x
    mma_gemm<2><<<dim3(EE/128, MR/128), 256, GEMM_SMEM>>>(
        o, wo_, bo, hs, x, nullptr, MR, EE, EE, EE, EE);

    // 5. LN2 -> plain fp16
    ln_pack<1><<<MR, 256>>>(x, ln2g, ln2b, h2);

    // 6. MLP up + gelu (1-pass) -> m (plain fp16)
    mma_gemm<1><<<dim3(II/128, MR/128), 256, GEMM_SMEM>>>(
        h2, w1_, b1, nullptr, nullptr, m, MR, II, EE, EE, EE);

    // 7. MLP down (1-pass) + residual(x) -> out
    mma_gemm<2><<<dim3(EE/128, MR/128), 256, GEMM_SMEM>>>(
        m, w2_, b2, x, out, nullptr, MR, EE, II, II, II);
}

// round 11
// speedup vs baseline: 5.3005x; 1.1599x over previous
#include <cuda_runtime.h>
#include <cuda_fp16.h>
#include <math.h>
#include <stdint.h>

// ---------------------------------------------------------------------------
// SiglipEncoderLayer  B=8 S=1024 E=768 H=12 D=64 I=3072  fp32 in/out
// R11 (= R10 resubmission; R10 bench died to container flake, code audited
// clean against passing R9 — same precedent as R8->R9).
//   QK-proj 2-pass ((Ah+Al).Wh); QK^T 2-pass ((Qh+Ql).Kh); PV 1-pass (Ph.Vh);
//   V-proj / O-proj / MLP 1-pass plain fp16.
// ---------------------------------------------------------------------------

#define BB   8
#define SS   1024
#define EE   768
#define HH   12
#define DD   64
#define II   3072
#define MR   (BB*SS)            // 8192
#define K2E  (2*EE)             // 1536
#define NQK  (2*EE)             // 1536 (q|k outputs)
#define RQK  (2*NQK)            // 3072 qk row width [H|L]
#define EPSF 1e-6f
#define SCALE_F 0.125f

// ---- scratch (device globals, 128B aligned) -------------------------------
__device__ __align__(128) float g_x [MR*EE];
__device__ __align__(128) float g_bqk[NQK];

__device__ __align__(128) __half g_h1p[(size_t)MR*K2E];   // ln1 [h|l]
__device__ __align__(128) __half g_h2 [(size_t)MR*EE];    // ln2 plain
__device__ __align__(128) __half g_qk [(size_t)MR*RQK];   // qk [H(1536)|L(1536)]
__device__ __align__(128) __half g_v  [(size_t)MR*EE];    // v plain
__device__ __align__(128) __half g_o  [(size_t)MR*EE];    // attn out plain
__device__ __align__(128) __half g_m  [(size_t)MR*II];    // gelu out plain

__device__ __align__(128) __half g_wqkp[(size_t)NQK*K2E]; // [Wh|Wh]
__device__ __align__(128) __half g_wv [(size_t)EE*EE];    // plain [N][K]
__device__ __align__(128) __half g_wo [(size_t)EE*EE];
__device__ __align__(128) __half g_w1 [(size_t)II*EE];
__device__ __align__(128) __half g_w2 [(size_t)EE*II];

// ---------------------------------------------------------------------------
__device__ __forceinline__ uint32_t smem_u32(const void* p) {
    uint32_t a;
    asm("{ .reg .u64 t; cvta.to.shared.u64 t, %1; cvt.u32.u64 %0, t; }"
        : "=r"(a) : "l"(p));
    return a;
}
__device__ __forceinline__ void cp_async16(uint32_t s, const void* g) {
    asm volatile("cp.async.cg.shared.global [%0], [%1], 16;" :: "r"(s), "l"(g) : "memory");
}
#define CP_COMMIT() asm volatile("cp.async.commit_group;" ::: "memory")
#define CP_WAIT(n)  asm volatile("cp.async.wait_group %0;" :: "n"(n) : "memory")

__device__ __forceinline__ void ldsm4(uint32_t* r, uint32_t addr) {
    asm volatile("ldmatrix.sync.aligned.m8n8.x4.shared.b16 {%0,%1,%2,%3}, [%4];"
        : "=r"(r[0]), "=r"(r[1]), "=r"(r[2]), "=r"(r[3]) : "r"(addr));
}
__device__ __forceinline__ void ldsm4t(uint32_t* r, uint32_t addr) {
    asm volatile("ldmatrix.sync.aligned.m8n8.x4.trans.shared.b16 {%0,%1,%2,%3}, [%4];"
        : "=r"(r[0]), "=r"(r[1]), "=r"(r[2]), "=r"(r[3]) : "r"(addr));
}
__device__ __forceinline__ void mma16816(float* d, const uint32_t* a, const uint32_t* b) {
    asm volatile(
        "mma.sync.aligned.m16n8k16.row.col.f32.f16.f16.f32 "
        "{%0,%1,%2,%3}, {%4,%5,%6,%7}, {%8,%9}, {%0,%1,%2,%3};"
        : "+f"(d[0]), "+f"(d[1]), "+f"(d[2]), "+f"(d[3])
        : "r"(a[0]), "r"(a[1]), "r"(a[2]), "r"(a[3]), "r"(b[0]), "r"(b[1]));
}
__device__ __forceinline__ float gelu_tanh(float x) {
    float x3 = x * x * x;
    float t  = tanhf(0.7978845608028654f * (x + 0.044715f * x3));
    return 0.5f * x * (1.0f + t);
}
__device__ __forceinline__ void split_h(float v, __half& h, __half& l) {
    h = __float2half_rn(v);
    l = __float2half_rn(v - __half2float(h));
}
__device__ __forceinline__ uint32_t pack2h(float x, float y) {
    __half2 H = __halves2half2(__float2half_rn(x), __float2half_rn(y));
    return *reinterpret_cast<uint32_t*>(&H);
}

// ---------------------------------------------------------------------------
// mma.sync GEMM (fp16), 4-stage cp.async ring, separate lda/ldw.
//   MODE 0: opk plain = acc + bias                       (V-proj)
//   MODE 1: opk plain = gelu(acc + bias)                 (MLP up)
//   MODE 2: outf fp32 = acc + bias + res                 (O-proj, MLP down)
//   MODE 3: opk [H|L] width 2N = split(acc + bias)       (QK-proj)
// ---------------------------------------------------------------------------
#define GEMM_NS    4
#define GEMM_STG   16384
#define GEMM_SMEM  (GEMM_NS * GEMM_STG)

template<int MODE>
__global__ __launch_bounds__(256, 2)
void mma_gemm(const __half* __restrict__ A,
              const __half* __restrict__ W,
              const float* __restrict__ bias, const float* __restrict__ res,
              float* __restrict__ outf, __half* __restrict__ opk,
              int M, int N, int KP, int lda, int ldw) {
    extern __shared__ __align__(128) char smbuf[];

    const int tid  = threadIdx.x;
    const int wid  = tid >> 5;
    const int lane = tid & 31;
    const int wm   = wid & 3;
    const int wn   = wid >> 2;
    const int m0   = blockIdx.y * 128;
    const int n0   = blockIdx.x * 128;

    const uint32_t sb = smem_u32(smbuf);

    float acc[2][8][4];
    #pragma unroll
    for (int mf = 0; mf < 2; mf++)
        #pragma unroll
        for (int nf = 0; nf < 8; nf++)
            #pragma unroll
            for (int r = 0; r < 4; r++) acc[mf][nf][r] = 0.f;

    const int nc = KP >> 5;

    auto loadc = [&](int c, int s) {
        const int k0 = c << 5;
        uint32_t as = sb + (uint32_t)s * GEMM_STG;
        uint32_t bs = as + 8192u;
        #pragma unroll
        for (int i = 0; i < 2; i++) {
            int cid = tid + i * 256;
            int row = cid >> 2, ch = cid & 3;
            uint32_t soff = row * 64u + ((uint32_t)(ch ^ (row & 3)) << 4);
            cp_async16(as + soff, A + (size_t)(m0 + row) * lda + k0 + ch * 8);
            cp_async16(bs + soff, W + (size_t)(n0 + row) * ldw + k0 + ch * 8);
        }
    };

    #pragma unroll
    for (int p = 0; p < GEMM_NS - 1; p++) { loadc(p, p); CP_COMMIT(); }

    for (int c = 0; c < nc; c++) {
        CP_WAIT(GEMM_NS - 2);
        __syncthreads();

        const uint32_t as = sb + (uint32_t)(c & (GEMM_NS - 1)) * GEMM_STG;
        const uint32_t bs = as + 8192u;
        const int j = lane >> 3, r = lane & 7;

        #pragma unroll
        for (int ks = 0; ks < 2; ks++) {
            uint32_t af[2][4];
            #pragma unroll
            for (int mf = 0; mf < 2; mf++) {
                int row = wm * 32 + mf * 16 + (j & 1) * 8 + r;
                int kc  = ks * 2 + (j >> 1);
                ldsm4(af[mf], as + row * 64u + ((uint32_t)(kc ^ (row & 3)) << 4));
            }
            uint32_t bf[8][2];
            #pragma unroll
            for (int tp = 0; tp < 4; tp++) {
                int nrow = wn * 64 + tp * 16 + (j >> 1) * 8 + r;
                int kc   = ks * 2 + (j & 1);
                uint32_t t4[4];
                ldsm4(t4, bs + nrow * 64u + ((uint32_t)(kc ^ (nrow & 3)) << 4));
                bf[2*tp][0]   = t4[0]; bf[2*tp][1]   = t4[1];
                bf[2*tp+1][0] = t4[2]; bf[2*tp+1][1] = t4[3];
            }
            #pragma unroll
            for (int mf = 0; mf < 2; mf++)
                #pragma unroll
                for (int nf = 0; nf < 8; nf++)
                    mma16816(acc[mf][nf], af[mf], bf[nf]);
        }
        __syncthreads();

        const int nxt = c + GEMM_NS - 1;
        if (nxt < nc) loadc(nxt, nxt & (GEMM_NS - 1));
        CP_COMMIT();
    }

    const int gi = lane >> 2, ci = lane & 3;
    #pragma unroll
    for (int mf = 0; mf < 2; mf++) {
        int r0 = m0 + wm * 32 + mf * 16 + gi;
        #pragma unroll
        for (int nf = 0; nf < 8; nf++) {
            int col = n0 + wn * 64 + nf * 8 + ci * 2;
            float b0 = bias[col], b1 = bias[col + 1];
            float v00 = acc[mf][nf][0] + b0, v01 = acc[mf][nf][1] + b1;
            float v10 = acc[mf][nf][2] + b0, v11 = acc[mf][nf][3] + b1;
            if (MODE == 0 || MODE == 1) {
                if (MODE == 1) {
                    v00 = gelu_tanh(v00); v01 = gelu_tanh(v01);
                    v10 = gelu_tanh(v10); v11 = gelu_tanh(v11);
                }
                *reinterpret_cast<__half2*>(opk + (size_t)r0 * N + col) =
                    __halves2half2(__float2half_rn(v00), __float2half_rn(v01));
                *reinterpret_cast<__half2*>(opk + (size_t)(r0 + 8) * N + col) =
                    __halves2half2(__float2half_rn(v10), __float2half_rn(v11));
            } else if (MODE == 3) {
                __half h0,l0,h1,l1;
                size_t rw = (size_t)r0 * (2 * N) + col;
                split_h(v00, h0, l0); split_h(v01, h1, l1);
                *reinterpret_cast<__half2*>(opk + rw)     = __halves2half2(h0, h1);
                *reinterpret_cast<__half2*>(opk + rw + N) = __halves2half2(l0, l1);
                size_t rw2 = (size_t)(r0 + 8) * (2 * N) + col;
                split_h(v10, h0, l0); split_h(v11, h1, l1);
                *reinterpret_cast<__half2*>(opk + rw2)     = __halves2half2(h0, h1);
                *reinterpret_cast<__half2*>(opk + rw2 + N) = __halves2half2(l0, l1);
            } else {
                const float2 r00 = *reinterpret_cast<const float2*>(res + (size_t)r0 * N + col);
                const float2 r10 = *reinterpret_cast<const float2*>(res + (size_t)(r0 + 8) * N + col);
                v00 += r00.x; v01 += r00.y; v10 += r10.x; v11 += r10.y;
                *reinterpret_cast<float2*>(outf + (size_t)r0 * N + col)       = make_float2(v00, v01);
                *reinterpret_cast<float2*>(outf + (size_t)(r0 + 8) * N + col) = make_float2(v10, v11);
            }
        }
    }
}

// ---------------------------------------------------------------------------
// Fused flash attention.
//   QK buf: rows [H(1536)|L(1536)], q_h at h*64, k_h at 768+h*64, q_l +1536.
//   V buf: plain rows of 768.
//   QK^T = (Qh + Ql).Kh (2-pass).  PV = Ph.Vh (1-pass).
//   Output: plain fp16 rows of 768.
// ---------------------------------------------------------------------------
#define FA_STG  32768                   // Kh,Vh = 2 x 16KB
#define FA_SMEM (32768 + 2*FA_STG)      // Q(h,l) + 2 stages = 96 KB

__global__ __launch_bounds__(256, 1)
void flash_attn(const __half* __restrict__ QK,
                const __half* __restrict__ V,
                const float* __restrict__ mask,
                __half* __restrict__ Op) {
    extern __shared__ __align__(128) char fsm[];
    const uint32_t sb = smem_u32(fsm);
    const int tid = threadIdx.x, wid = tid >> 5, lane = tid & 31;
    const int qt = blockIdx.x, bh = blockIdx.y;
    const int b = bh / HH, h = bh - b * HH;
    const int q0 = qt * 128;
    const int j = lane >> 3, r = lane & 7;
    const int gi = lane >> 2, ci = lane & 3;

    const int qoff = h * DD;            // q_h; lo at +NQK
    const int koff = EE + h * DD;       // k_h

    const uint32_t sQh = sb, sQl = sb + 16384u;
    const uint32_t stg0 = sb + 32768u;

    {
        const size_t rbase = (size_t)(b * SS + q0);
        #pragma unroll
        for (int i = 0; i < 4; i++) {
            int idx = tid + i * 256;
            int row = idx >> 3, ch = idx & 7;
            uint32_t d = row * 128u + ((uint32_t)(ch ^ (row & 7)) << 4);
            const __half* g = QK + (rbase + row) * RQK + qoff + ch * 8;
            cp_async16(sQh + d, g);
            cp_async16(sQl + d, g + NQK);
        }
    }
    auto loadKV = [&](int it, int st) {
        const size_t rbase = (size_t)(b * SS + it * 128);
        uint32_t base = stg0 + st * (uint32_t)FA_STG;
        #pragma unroll
        for (int i = 0; i < 4; i++) {
            int idx = tid + i * 256;
            int row = idx >> 3, ch = idx & 7;
            const __half* gk = QK + (rbase + row) * RQK + koff + ch * 8;
            const __half* gv = V  + (rbase + row) * EE  + h * DD + ch * 8;
            uint32_t d = base + row * 128u + ((uint32_t)(ch ^ (row & 7)) << 4);
            cp_async16(d,          gk);          // Kh
            cp_async16(d + 16384u, gv);          // Vh
        }
    };

    loadKV(0, 0);
    CP_COMMIT();

    float m0v = -1e30f, m1v = -1e30f, l0 = 0.f, l1 = 0.f;
    float o[8][4];
    #pragma unroll
    for (int nt = 0; nt < 8; nt++)
        #pragma unroll
        for (int t = 0; t < 4; t++) o[nt][t] = 0.f;

    const int NIT = SS / 128;
    for (int it = 0; it < NIT; it++) {
        const int st = it & 1;
        if (it + 1 < NIT) { loadKV(it + 1, st ^ 1); CP_COMMIT(); CP_WAIT(1); }
        else              { CP_WAIT(0); }
        __syncthreads();

        const uint32_t kb = stg0 + st * (uint32_t)FA_STG;

        float s[16][4];
        #pragma unroll
        for (int t = 0; t < 16; t++)
            #pragma unroll
            for (int u = 0; u < 4; u++) s[t][u] = 0.f;

        #pragma unroll
        for (int sec = 0; sec < 2; sec++) {
            const uint32_t qb = (sec == 1) ? sQl : sQh;
            #pragma unroll
            for (int kc = 0; kc < 4; kc++) {
                uint32_t af[4];
                int arow = wid * 16 + (j & 1) * 8 + r;
                int ach  = kc * 2 + (j >> 1);
                ldsm4(af, qb + arow * 128u + ((uint32_t)(ach ^ (arow & 7)) << 4));
                #pragma unroll
                for (int nt2 = 0; nt2 < 8; nt2++) {
                    int brow = nt2 * 16 + (j >> 1) * 8 + r;
                    int bch  = kc * 2 + (j & 1);
                    uint32_t t4[4];
                    ldsm4(t4, kb + brow * 128u + ((uint32_t)(bch ^ (brow & 7)) << 4));
                    uint32_t b0[2] = {t4[0], t4[1]}, b1[2] = {t4[2], t4[3]};
                    mma16816(s[2*nt2],   af, b0);
                    mma16816(s[2*nt2+1], af, b1);
                }
            }
        }

        const float* mr0 = mask + ((size_t)b * SS + (q0 + wid * 16 + gi)) * SS + it * 128;
        const float* mr1 = mr0 + 8 * (size_t)SS;
        float mx0 = -1e30f, mx1 = -1e30f;
        #pragma unroll
        for (int t = 0; t < 16; t++) {
            float2 u0 = *reinterpret_cast<const float2*>(mr0 + t * 8 + ci * 2);
            float2 u1 = *reinterpret_cast<const float2*>(mr1 + t * 8 + ci * 2);
            s[t][0] = s[t][0] * SCALE_F + u0.x;
            s[t][1] = s[t][1] * SCALE_F + u0.y;
            s[t][2] = s[t][2] * SCALE_F + u1.x;
            s[t][3] = s[t][3] * SCALE_F + u1.y;
            mx0 = fmaxf(mx0, fmaxf(s[t][0], s[t][1]));
            mx1 = fmaxf(mx1, fmaxf(s[t][2], s[t][3]));
        }
        mx0 = fmaxf(mx0, __shfl_xor_sync(0xFFFFFFFFu, mx0, 1));
        mx0 = fmaxf(mx0, __shfl_xor_sync(0xFFFFFFFFu, mx0, 2));
        mx1 = fmaxf(mx1, __shfl_xor_sync(0xFFFFFFFFu, mx1, 1));
        mx1 = fmaxf(mx1, __shfl_xor_sync(0xFFFFFFFFu, mx1, 2));
        const float mn0 = fmaxf(m0v, mx0), mn1 = fmaxf(m1v, mx1);
        const float a0 = __expf(m0v - mn0), a1 = __expf(m1v - mn1);
        m0v = mn0; m1v = mn1;

        float ps0 = 0.f, ps1 = 0.f;
        #pragma unroll
        for (int t = 0; t < 16; t++) {
            s[t][0] = __expf(s[t][0] - mn0);
            s[t][1] = __expf(s[t][1] - mn0);
            s[t][2] = __expf(s[t][2] - mn1);
            s[t][3] = __expf(s[t][3] - mn1);
            ps0 += s[t][0] + s[t][1];
            ps1 += s[t][2] + s[t][3];
        }
        ps0 += __shfl_xor_sync(0xFFFFFFFFu, ps0, 1);
        ps0 += __shfl_xor_sync(0xFFFFFFFFu, ps0, 2);
        ps1 += __shfl_xor_sync(0xFFFFFFFFu, ps1, 1);
        ps1 += __shfl_xor_sync(0xFFFFFFFFu, ps1, 2);
        l0 = l0 * a0 + ps0;
        l1 = l1 * a1 + ps1;

        #pragma unroll
        for (int nt = 0; nt < 8; nt++) {
            o[nt][0] *= a0; o[nt][1] *= a0;
            o[nt][2] *= a1; o[nt][3] *= a1;
        }

        const uint32_t vh = kb + 16384u;
        #pragma unroll
        for (int kt = 0; kt < 8; kt++) {
            uint32_t ph[4];
            ph[0] = pack2h(s[2*kt][0],   s[2*kt][1]);
            ph[1] = pack2h(s[2*kt][2],   s[2*kt][3]);
            ph[2] = pack2h(s[2*kt+1][0], s[2*kt+1][1]);
            ph[3] = pack2h(s[2*kt+1][2], s[2*kt+1][3]);
            #pragma unroll
            for (int nt2 = 0; nt2 < 4; nt2++) {
                int vrow = kt * 16 + (j & 1) * 8 + r;
                int vch  = nt2 * 2 + (j >> 1);
                uint32_t sw = vrow * 128u + ((uint32_t)(vch ^ (vrow & 7)) << 4);
                uint32_t t4[4];
                ldsm4t(t4, vh + sw);
                uint32_t b0[2] = {t4[0], t4[1]}, b1[2] = {t4[2], t4[3]};
                mma16816(o[2*nt2],   ph, b0);
                mma16816(o[2*nt2+1], ph, b1);
            }
        }
        __syncthreads();
    }

    const float inv0 = 1.f / l0, inv1 = 1.f / l1;
    const int qrow = b * SS + q0 + wid * 16 + gi;
    #pragma unroll
    for (int nt = 0; nt < 8; nt++) {
        int col = h * DD + nt * 8 + ci * 2;
        *reinterpret_cast<__half2*>(Op + (size_t)qrow * EE + col) =
            __halves2half2(__float2half_rn(o[nt][0] * inv0),
                           __float2half_rn(o[nt][1] * inv0));
        *reinterpret_cast<__half2*>(Op + (size_t)(qrow + 8) * EE + col) =
            __halves2half2(__float2half_rn(o[nt][2] * inv1),
                           __float2half_rn(o[nt][3] * inv1));
    }
}

// ---------------------------------------------------------------------------
// 2-term transpose: W[K,N] -> rows [Wh|Wh] width 2K at row_off
// ---------------------------------------------------------------------------
__global__ void transpose_pack2(const float* __restrict__ W,
                                __half* __restrict__ wp,
                                int K, int N, int row_off) {
    __shared__ float t[32][33];
    int tx = threadIdx.x, ty = threadIdx.y;
    int k0 = blockIdx.y * 32, n0 = blockIdx.x * 32;
    #pragma unroll
    for (int j = 0; j < 4; j++)
        t[ty + j*8][tx] = W[(size_t)(k0 + ty + j*8) * N + n0 + tx];
    __syncthreads();
    size_t K2 = 2 * (size_t)K;
    #pragma unroll
    for (int j = 0; j < 4; j++) {
        int nn = row_off + n0 + ty + j*8;
        int kk = k0 + tx;
        __half h = __float2half_rn(t[tx][ty + j*8]);
        wp[(size_t)nn * K2 + kk]     = h;
        wp[(size_t)nn * K2 + K + kk] = h;
    }
}

// plain 1-term transpose: W[K,N] -> wp[N][K] fp16
__global__ void transpose_pack1(const float* __restrict__ W,
                                __half* __restrict__ wp,
                                int K, int N) {
    __shared__ float t[32][33];
    int tx = threadIdx.x, ty = threadIdx.y;
    int k0 = blockIdx.y * 32, n0 = blockIdx.x * 32;
    #pragma unroll
    for (int j = 0; j < 4; j++)
        t[ty + j*8][tx] = W[(size_t)(k0 + ty + j*8) * N + n0 + tx];
    __syncthreads();
    #pragma unroll
    for (int j = 0; j < 4; j++) {
        int nn = n0 + ty + j*8;
        int kk = k0 + tx;
        wp[(size_t)nn * K + kk] = __float2half_rn(t[tx][ty + j*8]);
    }
}

// ---------------------------------------------------------------------------
__global__ void bias_cat2(const float* __restrict__ bq, const float* __restrict__ bk,
                          float* __restrict__ dst) {
    int i = blockIdx.x * 256 + threadIdx.x;
    if (i < NQK)
        dst[i] = (i < EE) ? bq[i] : bk[i - EE];
}

// ---------------------------------------------------------------------------
// LayerNorm. PACK2: [h|l] width 2E.  PACK1: plain fp16 width E.
// ---------------------------------------------------------------------------
template<int PACK>
__global__ void ln_pack(const float* __restrict__ x,
                        const float* __restrict__ g,
                        const float* __restrict__ b,
                        __half* __restrict__ pk) {
    int row = blockIdx.x;
    const float* xr = x + (size_t)row * EE;
    float s = 0.f, s2 = 0.f;
    for (int i = threadIdx.x; i < EE; i += 256) {
        float v = xr[i]; s += v; s2 += v * v;
    }
    __shared__ float rs[8], rs2[8];
    #pragma unroll
    for (int o = 16; o > 0; o >>= 1) {
        s  += __shfl_xor_sync(0xFFFFFFFFu, s,  o);
        s2 += __shfl_xor_sync(0xFFFFFFFFu, s2, o);
    }
    if ((threadIdx.x & 31) == 0) { rs[threadIdx.x>>5] = s; rs2[threadIdx.x>>5] = s2; }
    __syncthreads();
    float ts = 0.f, ts2 = 0.f;
    #pragma unroll
    for (int i = 0; i < 8; i++) { ts += rs[i]; ts2 += rs2[i]; }
    float mean = ts * (1.0f / EE);
    float var  = ts2 * (1.0f / EE) - mean * mean;
    float inv  = rsqrtf(var + EPSF);
    size_t rw = (size_t)row * (PACK * EE);
    for (int i = threadIdx.x; i < EE; i += 256) {
        float y = (xr[i] - mean) * inv * g[i] + b[i];
        if (PACK == 2) {
            __half h, l; split_h(y, h, l);
            pk[rw + i]      = h;
            pk[rw + EE + i] = l;
        } else {
            pk[rw + i] = __float2half_rn(y);
        }
    }
}

// ---------------------------------------------------------------------------
extern "C" void kernel_launch(void* const* d_in, const int* in_sizes, int n_in,
                              void* d_out, int out_size) {
    const float* hs   = (const float*)d_in[0];
    const float* mask = (const float*)d_in[1];
    const float* wq   = (const float*)d_in[2];
    const float* bq   = (const float*)d_in[3];
    const float* wk   = (const float*)d_in[4];
    const float* bk   = (const float*)d_in[5];
    const float* wv   = (const float*)d_in[6];
    const float* bv   = (const float*)d_in[7];
    const float* wo   = (const float*)d_in[8];
    const float* bo   = (const float*)d_in[9];
    const float* ln1g = (const float*)d_in[10];
    const float* ln1b = (const float*)d_in[11];
    const float* ln2g = (const float*)d_in[12];
    const float* ln2b = (const float*)d_in[13];
    const float* w1   = (const float*)d_in[14];
    const float* b1   = (const float*)d_in[15];
    const float* w2   = (const float*)d_in[16];
    const float* b2   = (const float*)d_in[17];
    float* out = (float*)d_out;

    float *x, *bqk;
    __half *h1p, *h2, *qk, *v, *o, *m, *wqkp, *wv_, *wo_, *w1_, *w2_;
    cudaGetSymbolAddress((void**)&x,    g_x);
    cudaGetSymbolAddress((void**)&bqk,  g_bqk);
    cudaGetSymbolAddress((void**)&h1p,  g_h1p);
    cudaGetSymbolAddress((void**)&h2,   g_h2);
    cudaGetSymbolAddress((void**)&qk,   g_qk);
    cudaGetSymbolAddress((void**)&v,    g_v);
    cudaGetSymbolAddress((void**)&o,    g_o);
    cudaGetSymbolAddress((void**)&m,    g_m);
    cudaGetSymbolAddress((void**)&wqkp, g_wqkp);
    cudaGetSymbolAddress((void**)&wv_,  g_wv);
    cudaGetSymbolAddress((void**)&wo_,  g_wo);
    cudaGetSymbolAddress((void**)&w1_,  g_w1);
    cudaGetSymbolAddress((void**)&w2_,  g_w2);

    cudaFuncSetAttribute(flash_attn, cudaFuncAttributeMaxDynamicSharedMemorySize, FA_SMEM);
    cudaFuncSetAttribute(mma_gemm<0>, cudaFuncAttributeMaxDynamicSharedMemorySize, GEMM_SMEM);
    cudaFuncSetAttribute(mma_gemm<1>, cudaFuncAttributeMaxDynamicSharedMemorySize, GEMM_SMEM);
    cudaFuncSetAttribute(mma_gemm<2>, cudaFuncAttributeMaxDynamicSharedMemorySize, GEMM_SMEM);
    cudaFuncSetAttribute(mma_gemm<3>, cudaFuncAttributeMaxDynamicSharedMemorySize, GEMM_SMEM);

    dim3 tb(32, 8);
    transpose_pack2<<<dim3(EE/32, EE/32), tb>>>(wq, wqkp, EE, EE, 0);
    transpose_pack2<<<dim3(EE/32, EE/32), tb>>>(wk, wqkp, EE, EE, EE);
    transpose_pack1<<<dim3(EE/32, EE/32), tb>>>(wv, wv_, EE, EE);
    transpose_pack1<<<dim3(EE/32, EE/32), tb>>>(wo, wo_, EE, EE);
    transpose_pack1<<<dim3(II/32, EE/32), tb>>>(w1, w1_, EE, II);
    transpose_pack1<<<dim3(EE/32, II/32), tb>>>(w2, w2_, II, EE);
    bias_cat2<<<(NQK + 255) / 256, 256>>>(bq, bk, bqk);

    // 1. LN1 -> [h|l]
    ln_pack<2><<<MR, 256>>>(hs, ln1g, ln1b, h1p);

    // 2a. QK projection (2-pass) -> qk [H|L]
    mma_gemm<3><<<dim3(NQK/128, MR/128), 256, GEMM_SMEM>>>(
        h1p, wqkp, bqk, nullptr, nullptr, qk, MR, NQK, K2E, K2E, K2E);
    // 2b. V projection (1-pass: hi section of h1p x plain wv) -> v
    mma_gemm<0><<<dim3(EE/128, MR/128), 256, GEMM_SMEM>>>(
        h1p, wv_, bv, nullptr, nullptr, v, MR, EE, EE, K2E, EE);

    // 3. fused flash attention -> o (plain fp16)
    flash_attn<<<dim3(SS/128, BB*HH), 256, FA_SMEM>>>(qk, v, mask, o);

    // 4. O-proj (1-pass) + residual(hs) -> x
    mma_gemm<2><<<dim3(EE/128, MR/128), 256, GEMM_SMEM>>>(
        o, wo_, bo, hs, x, nullptr, MR, EE, EE, EE, EE);

    // 5. LN2 -> plain fp16
    ln_pack<1><<<MR, 256>>>(x, ln2g, ln2b, h2);

    // 6. MLP up + gelu (1-pass) -> m (plain fp16)
    mma_gemm<1><<<dim3(II/128, MR/128), 256, GEMM_SMEM>>>(
        h2, w1_, b1, nullptr, nullptr, m, MR, II, EE, EE, EE);

    // 7. MLP down (1-pass) + residual(x) -> out
    mma_gemm<2><<<dim3(EE/128, MR/128), 256, GEMM_SMEM>>>(
        m, w2_, b2, x, out, nullptr, MR, EE, II, II, II);
}

// round 14
// speedup vs baseline: 6.0691x; 1.1450x over previous
#include <cuda_runtime.h>
#include <cuda_fp16.h>
#include <math.h>
#include <stdint.h>

// ---------------------------------------------------------------------------
// SiglipEncoderLayer  B=8 S=1024 E=768 H=12 D=64 I=3072  fp32 in/out
// R14 (third submission of the R12 design; R12/R13 hit consecutive container
// failures — audit clean, broker-streak hypothesis; if this fails, R15
// reverts to known-good R11 to separate code- vs environment-triggered).
// Full 1-pass fp16. Fused QKV GEMM (N=2304); vanilla fp16 flash attn;
// O-proj / MLP 1-pass.
// ---------------------------------------------------------------------------

#define BB   8
#define SS   1024
#define EE   768
#define HH   12
#define DD   64
#define II   3072
#define MR   (BB*SS)            // 8192
#define NQKV (3*EE)             // 2304 (q|k|v outputs, row width)
#define EPSF 1e-6f
#define SCALE_F 0.125f

// ---- scratch (device globals, 128B aligned) -------------------------------
__device__ __align__(128) float g_x [MR*EE];
__device__ __align__(128) float g_bqkv[NQKV];

__device__ __align__(128) __half g_h1 [(size_t)MR*EE];     // ln1 plain
__device__ __align__(128) __half g_h2 [(size_t)MR*EE];     // ln2 plain
__device__ __align__(128) __half g_qkv[(size_t)MR*NQKV];   // q|k|v rows
__device__ __align__(128) __half g_o  [(size_t)MR*EE];     // attn out plain
__device__ __align__(128) __half g_m  [(size_t)MR*II];     // gelu out plain

__device__ __align__(128) __half g_wqkv[(size_t)NQKV*EE];  // [N=2304][K=768]
__device__ __align__(128) __half g_wo [(size_t)EE*EE];
__device__ __align__(128) __half g_w1 [(size_t)II*EE];
__device__ __align__(128) __half g_w2 [(size_t)EE*II];

// ---------------------------------------------------------------------------
__device__ __forceinline__ uint32_t smem_u32(const void* p) {
    uint32_t a;
    asm("{ .reg .u64 t; cvta.to.shared.u64 t, %1; cvt.u32.u64 %0, t; }"
        : "=r"(a) : "l"(p));
    return a;
}
__device__ __forceinline__ void cp_async16(uint32_t s, const void* g) {
    asm volatile("cp.async.cg.shared.global [%0], [%1], 16;" :: "r"(s), "l"(g) : "memory");
}
#define CP_COMMIT() asm volatile("cp.async.commit_group;" ::: "memory")
#define CP_WAIT(n)  asm volatile("cp.async.wait_group %0;" :: "n"(n) : "memory")

__device__ __forceinline__ void ldsm4(uint32_t* r, uint32_t addr) {
    asm volatile("ldmatrix.sync.aligned.m8n8.x4.shared.b16 {%0,%1,%2,%3}, [%4];"
        : "=r"(r[0]), "=r"(r[1]), "=r"(r[2]), "=r"(r[3]) : "r"(addr));
}
__device__ __forceinline__ void ldsm4t(uint32_t* r, uint32_t addr) {
    asm volatile("ldmatrix.sync.aligned.m8n8.x4.trans.shared.b16 {%0,%1,%2,%3}, [%4];"
        : "=r"(r[0]), "=r"(r[1]), "=r"(r[2]), "=r"(r[3]) : "r"(addr));
}
__device__ __forceinline__ void mma16816(float* d, const uint32_t* a, const uint32_t* b) {
    asm volatile(
        "mma.sync.aligned.m16n8k16.row.col.f32.f16.f16.f32 "
        "{%0,%1,%2,%3}, {%4,%5,%6,%7}, {%8,%9}, {%0,%1,%2,%3};"
        : "+f"(d[0]), "+f"(d[1]), "+f"(d[2]), "+f"(d[3])
        : "r"(a[0]), "r"(a[1]), "r"(a[2]), "r"(a[3]), "r"(b[0]), "r"(b[1]));
}
__device__ __forceinline__ float gelu_tanh(float x) {
    float x3 = x * x * x;
    float t  = tanhf(0.7978845608028654f * (x + 0.044715f * x3));
    return 0.5f * x * (1.0f + t);
}
__device__ __forceinline__ uint32_t pack2h(float x, float y) {
    __half2 H = __halves2half2(__float2half_rn(x), __float2half_rn(y));
    return *reinterpret_cast<uint32_t*>(&H);
}

// ---------------------------------------------------------------------------
// mma.sync GEMM (fp16), 4-stage cp.async ring, separate lda/ldw/ldo.
//   MODE 0: opk plain = acc + bias                       (QKV-proj)
//   MODE 1: opk plain = gelu(acc + bias)                 (MLP up)
//   MODE 2: outf fp32 = acc + bias + res                 (O-proj, MLP down)
// ---------------------------------------------------------------------------
#define GEMM_NS    4
#define GEMM_STG   16384
#define GEMM_SMEM  (GEMM_NS * GEMM_STG)

template<int MODE>
__global__ __launch_bounds__(256, 2)
void mma_gemm(const __half* __restrict__ A,
              const __half* __restrict__ W,
              const float* __restrict__ bias, const float* __restrict__ res,
              float* __restrict__ outf, __half* __restrict__ opk,
              int M, int N, int KP, int lda, int ldw, int ldo) {
    extern __shared__ __align__(128) char smbuf[];

    const int tid  = threadIdx.x;
    const int wid  = tid >> 5;
    const int lane = tid & 31;
    const int wm   = wid & 3;
    const int wn   = wid >> 2;
    const int m0   = blockIdx.y * 128;
    const int n0   = blockIdx.x * 128;

    const uint32_t sb = smem_u32(smbuf);

    float acc[2][8][4];
    #pragma unroll
    for (int mf = 0; mf < 2; mf++)
        #pragma unroll
        for (int nf = 0; nf < 8; nf++)
            #pragma unroll
            for (int r = 0; r < 4; r++) acc[mf][nf][r] = 0.f;

    const int nc = KP >> 5;

    auto loadc = [&](int c, int s) {
        const int k0 = c << 5;
        uint32_t as = sb + (uint32_t)s * GEMM_STG;
        uint32_t bs = as + 8192u;
        #pragma unroll
        for (int i = 0; i < 2; i++) {
            int cid = tid + i * 256;
            int row = cid >> 2, ch = cid & 3;
            uint32_t soff = row * 64u + ((uint32_t)(ch ^ (row & 3)) << 4);
            cp_async16(as + soff, A + (size_t)(m0 + row) * lda + k0 + ch * 8);
            cp_async16(bs + soff, W + (size_t)(n0 + row) * ldw + k0 + ch * 8);
        }
    };

    #pragma unroll
    for (int p = 0; p < GEMM_NS - 1; p++) { loadc(p, p); CP_COMMIT(); }

    for (int c = 0; c < nc; c++) {
        CP_WAIT(GEMM_NS - 2);
        __syncthreads();

        const uint32_t as = sb + (uint32_t)(c & (GEMM_NS - 1)) * GEMM_STG;
        const uint32_t bs = as + 8192u;
        const int j = lane >> 3, r = lane & 7;

        #pragma unroll
        for (int ks = 0; ks < 2; ks++) {
            uint32_t af[2][4];
            #pragma unroll
            for (int mf = 0; mf < 2; mf++) {
                int row = wm * 32 + mf * 16 + (j & 1) * 8 + r;
                int kc  = ks * 2 + (j >> 1);
                ldsm4(af[mf], as + row * 64u + ((uint32_t)(kc ^ (row & 3)) << 4));
            }
            uint32_t bf[8][2];
            #pragma unroll
            for (int tp = 0; tp < 4; tp++) {
                int nrow = wn * 64 + tp * 16 + (j >> 1) * 8 + r;
                int kc   = ks * 2 + (j & 1);
                uint32_t t4[4];
                ldsm4(t4, bs + nrow * 64u + ((uint32_t)(kc ^ (nrow & 3)) << 4));
                bf[2*tp][0]   = t4[0]; bf[2*tp][1]   = t4[1];
                bf[2*tp+1][0] = t4[2]; bf[2*tp+1][1] = t4[3];
            }
            #pragma unroll
            for (int mf = 0; mf < 2; mf++)
                #pragma unroll
                for (int nf = 0; nf < 8; nf++)
                    mma16816(acc[mf][nf], af[mf], bf[nf]);
        }
        __syncthreads();

        const int nxt = c + GEMM_NS - 1;
        if (nxt < nc) loadc(nxt, nxt & (GEMM_NS - 1));
        CP_COMMIT();
    }

    const int gi = lane >> 2, ci = lane & 3;
    #pragma unroll
    for (int mf = 0; mf < 2; mf++) {
        int r0 = m0 + wm * 32 + mf * 16 + gi;
        #pragma unroll
        for (int nf = 0; nf < 8; nf++) {
            int col = n0 + wn * 64 + nf * 8 + ci * 2;
            float b0 = bias[col], b1 = bias[col + 1];
            float v00 = acc[mf][nf][0] + b0, v01 = acc[mf][nf][1] + b1;
            float v10 = acc[mf][nf][2] + b0, v11 = acc[mf][nf][3] + b1;
            if (MODE == 0 || MODE == 1) {
                if (MODE == 1) {
                    v00 = gelu_tanh(v00); v01 = gelu_tanh(v01);
                    v10 = gelu_tanh(v10); v11 = gelu_tanh(v11);
                }
                *reinterpret_cast<__half2*>(opk + (size_t)r0 * ldo + col) =
                    __halves2half2(__float2half_rn(v00), __float2half_rn(v01));
                *reinterpret_cast<__half2*>(opk + (size_t)(r0 + 8) * ldo + col) =
                    __halves2half2(__float2half_rn(v10), __float2half_rn(v11));
            } else {
                const float2 r00 = *reinterpret_cast<const float2*>(res + (size_t)r0 * N + col);
                const float2 r10 = *reinterpret_cast<const float2*>(res + (size_t)(r0 + 8) * N + col);
                v00 += r00.x; v01 += r00.y; v10 += r10.x; v11 += r10.y;
                *reinterpret_cast<float2*>(outf + (size_t)r0 * N + col)       = make_float2(v00, v01);
                *reinterpret_cast<float2*>(outf + (size_t)(r0 + 8) * N + col) = make_float2(v10, v11);
            }
        }
    }
}

// ---------------------------------------------------------------------------
// Fused flash attention (plain fp16 1-pass).
//   QKV buf: rows of 2304: q at h*64, k at 768+h*64, v at 1536+h*64.
//   Output: plain fp16 rows of 768.
// ---------------------------------------------------------------------------
#define FA_STG  32768                   // K,V = 2 x 16KB
#define FA_SMEM (16384 + 2*FA_STG)      // Q + 2 stages = 80 KB

__global__ __launch_bounds__(256, 1)
void flash_attn(const __half* __restrict__ QKV,
                const float* __restrict__ mask,
                __half* __restrict__ Op) {
    extern __shared__ __align__(128) char fsm[];
    const uint32_t sb = smem_u32(fsm);
    const int tid = threadIdx.x, wid = tid >> 5, lane = tid & 31;
    const int qt = blockIdx.x, bh = blockIdx.y;
    const int b = bh / HH, h = bh - b * HH;
    const int q0 = qt * 128;
    const int j = lane >> 3, r = lane & 7;
    const int gi = lane >> 2, ci = lane & 3;

    const int qoff = h * DD;
    const int koff = EE + h * DD;
    const int voff = 2 * EE + h * DD;

    const uint32_t sQ  = sb;
    const uint32_t stg0 = sb + 16384u;

    {
        const size_t rbase = (size_t)(b * SS + q0);
        #pragma unroll
        for (int i = 0; i < 4; i++) {
            int idx = tid + i * 256;
            int row = idx >> 3, ch = idx & 7;
            uint32_t d = row * 128u + ((uint32_t)(ch ^ (row & 7)) << 4);
            cp_async16(sQ + d, QKV + (rbase + row) * NQKV + qoff + ch * 8);
        }
    }
    auto loadKV = [&](int it, int st) {
        const size_t rbase = (size_t)(b * SS + it * 128);
        uint32_t base = stg0 + st * (uint32_t)FA_STG;
        #pragma unroll
        for (int i = 0; i < 4; i++) {
            int idx = tid + i * 256;
            int row = idx >> 3, ch = idx & 7;
            const __half* g = QKV + (rbase + row) * NQKV + ch * 8;
            uint32_t d = base + row * 128u + ((uint32_t)(ch ^ (row & 7)) << 4);
            cp_async16(d,          g + koff);    // K
            cp_async16(d + 16384u, g + voff);    // V
        }
    };

    loadKV(0, 0);
    CP_COMMIT();

    float m0v = -1e30f, m1v = -1e30f, l0 = 0.f, l1 = 0.f;
    float o[8][4];
    #pragma unroll
    for (int nt = 0; nt < 8; nt++)
        #pragma unroll
        for (int t = 0; t < 4; t++) o[nt][t] = 0.f;

    const int NIT = SS / 128;
    for (int it = 0; it < NIT; it++) {
        const int st = it & 1;
        if (it + 1 < NIT) { loadKV(it + 1, st ^ 1); CP_COMMIT(); CP_WAIT(1); }
        else              { CP_WAIT(0); }
        __syncthreads();

        const uint32_t kb = stg0 + st * (uint32_t)FA_STG;

        float s[16][4];
        #pragma unroll
        for (int t = 0; t < 16; t++)
            #pragma unroll
            for (int u = 0; u < 4; u++) s[t][u] = 0.f;

        #pragma unroll
        for (int kc = 0; kc < 4; kc++) {
            uint32_t af[4];
            int arow = wid * 16 + (j & 1) * 8 + r;
            int ach  = kc * 2 + (j >> 1);
            ldsm4(af, sQ + arow * 128u + ((uint32_t)(ach ^ (arow & 7)) << 4));
            #pragma unroll
            for (int nt2 = 0; nt2 < 8; nt2++) {
                int brow = nt2 * 16 + (j >> 1) * 8 + r;
                int bch  = kc * 2 + (j & 1);
                uint32_t t4[4];
                ldsm4(t4, kb + brow * 128u + ((uint32_t)(bch ^ (brow & 7)) << 4));
                uint32_t b0[2] = {t4[0], t4[1]}, b1[2] = {t4[2], t4[3]};
                mma16816(s[2*nt2],   af, b0);
                mma16816(s[2*nt2+1], af, b1);
            }
        }

        const float* mr0 = mask + ((size_t)b * SS + (q0 + wid * 16 + gi)) * SS + it * 128;
        const float* mr1 = mr0 + 8 * (size_t)SS;
        float mx0 = -1e30f, mx1 = -1e30f;
        #pragma unroll
        for (int t = 0; t < 16; t++) {
            float2 u0 = *reinterpret_cast<const float2*>(mr0 + t * 8 + ci * 2);
            float2 u1 = *reinterpret_cast<const float2*>(mr1 + t * 8 + ci * 2);
            s[t][0] = s[t][0] * SCALE_F + u0.x;
            s[t][1] = s[t][1] * SCALE_F + u0.y;
            s[t][2] = s[t][2] * SCALE_F + u1.x;
            s[t][3] = s[t][3] * SCALE_F + u1.y;
            mx0 = fmaxf(mx0, fmaxf(s[t][0], s[t][1]));
            mx1 = fmaxf(mx1, fmaxf(s[t][2], s[t][3]));
        }
        mx0 = fmaxf(mx0, __shfl_xor_sync(0xFFFFFFFFu, mx0, 1));
        mx0 = fmaxf(mx0, __shfl_xor_sync(0xFFFFFFFFu, mx0, 2));
        mx1 = fmaxf(mx1, __shfl_xor_sync(0xFFFFFFFFu, mx1, 1));
        mx1 = fmaxf(mx1, __shfl_xor_sync(0xFFFFFFFFu, mx1, 2));
        const float mn0 = fmaxf(m0v, mx0), mn1 = fmaxf(m1v, mx1);
        const float a0 = __expf(m0v - mn0), a1 = __expf(m1v - mn1);
        m0v = mn0; m1v = mn1;

        float ps0 = 0.f, ps1 = 0.f;
        #pragma unroll
        for (int t = 0; t < 16; t++) {
            s[t][0] = __expf(s[t][0] - mn0);
            s[t][1] = __expf(s[t][1] - mn0);
            s[t][2] = __expf(s[t][2] - mn1);
            s[t][3] = __expf(s[t][3] - mn1);
            ps0 += s[t][0] + s[t][1];
            ps1 += s[t][2] + s[t][3];
        }
        ps0 += __shfl_xor_sync(0xFFFFFFFFu, ps0, 1);
        ps0 += __shfl_xor_sync(0xFFFFFFFFu, ps0, 2);
        ps1 += __shfl_xor_sync(0xFFFFFFFFu, ps1, 1);
        ps1 += __shfl_xor_sync(0xFFFFFFFFu, ps1, 2);
        l0 = l0 * a0 + ps0;
        l1 = l1 * a1 + ps1;

        #pragma unroll
        for (int nt = 0; nt < 8; nt++) {
            o[nt][0] *= a0; o[nt][1] *= a0;
            o[nt][2] *= a1; o[nt][3] *= a1;
        }

        const uint32_t vh = kb + 16384u;
        #pragma unroll
        for (int kt = 0; kt < 8; kt++) {
            uint32_t ph[4];
            ph[0] = pack2h(s[2*kt][0],   s[2*kt][1]);
            ph[1] = pack2h(s[2*kt][2],   s[2*kt][3]);
            ph[2] = pack2h(s[2*kt+1][0], s[2*kt+1][1]);
            ph[3] = pack2h(s[2*kt+1][2], s[2*kt+1][3]);
            #pragma unroll
            for (int nt2 = 0; nt2 < 4; nt2++) {
                int vrow = kt * 16 + (j & 1) * 8 + r;
                int vch  = nt2 * 2 + (j >> 1);
                uint32_t sw = vrow * 128u + ((uint32_t)(vch ^ (vrow & 7)) << 4);
                uint32_t t4[4];
                ldsm4t(t4, vh + sw);
                uint32_t b0[2] = {t4[0], t4[1]}, b1[2] = {t4[2], t4[3]};
                mma16816(o[2*nt2],   ph, b0);
                mma16816(o[2*nt2+1], ph, b1);
            }
        }
        __syncthreads();
    }

    const float inv0 = 1.f / l0, inv1 = 1.f / l1;
    const int qrow = b * SS + q0 + wid * 16 + gi;
    #pragma unroll
    for (int nt = 0; nt < 8; nt++) {
        int col = h * DD + nt * 8 + ci * 2;
        *reinterpret_cast<__half2*>(Op + (size_t)qrow * EE + col) =
            __halves2half2(__float2half_rn(o[nt][0] * inv0),
                           __float2half_rn(o[nt][1] * inv0));
        *reinterpret_cast<__half2*>(Op + (size_t)(qrow + 8) * EE + col) =
            __halves2half2(__float2half_rn(o[nt][2] * inv1),
                           __float2half_rn(o[nt][3] * inv1));
    }
}

// ---------------------------------------------------------------------------
// plain 1-term transpose: W[K,N] -> wp[row_off + N][K] fp16
// ---------------------------------------------------------------------------
__global__ void transpose_pack1(const float* __restrict__ W,
                                __half* __restrict__ wp,
                                int K, int N, int row_off) {
    __shared__ float t[32][33];
    int tx = threadIdx.x, ty = threadIdx.y;
    int k0 = blockIdx.y * 32, n0 = blockIdx.x * 32;
    #pragma unroll
    for (int j = 0; j < 4; j++)
        t[ty + j*8][tx] = W[(size_t)(k0 + ty + j*8) * N + n0 + tx];
    __syncthreads();
    #pragma unroll
    for (int j = 0; j < 4; j++) {
        int nn = row_off + n0 + ty + j*8;
        int kk = k0 + tx;
        wp[(size_t)nn * K + kk] = __float2half_rn(t[tx][ty + j*8]);
    }
}

// ---------------------------------------------------------------------------
__global__ void bias_cat3(const float* __restrict__ bq, const float* __restrict__ bk,
                          const float* __restrict__ bv, float* __restrict__ dst) {
    int i = blockIdx.x * 256 + threadIdx.x;
    if (i < NQKV)
        dst[i] = (i < EE) ? bq[i] : (i < 2*EE) ? bk[i - EE] : bv[i - 2*EE];
}

// ---------------------------------------------------------------------------
// LayerNorm -> plain fp16
// ---------------------------------------------------------------------------
__global__ void ln_h(const float* __restrict__ x,
                     const float* __restrict__ g,
                     const float* __restrict__ b,
                     __half* __restrict__ pk) {
    int row = blockIdx.x;
    const float* xr = x + (size_t)row * EE;
    float s = 0.f, s2 = 0.f;
    for (int i = threadIdx.x; i < EE; i += 256) {
        float v = xr[i]; s += v; s2 += v * v;
    }
    __shared__ float rs[8], rs2[8];
    #pragma unroll
    for (int o = 16; o > 0; o >>= 1) {
        s  += __shfl_xor_sync(0xFFFFFFFFu, s,  o);
        s2 += __shfl_xor_sync(0xFFFFFFFFu, s2, o);
    }
    if ((threadIdx.x & 31) == 0) { rs[threadIdx.x>>5] = s; rs2[threadIdx.x>>5] = s2; }
    __syncthreads();
    float ts = 0.f, ts2 = 0.f;
    #pragma unroll
    for (int i = 0; i < 8; i++) { ts += rs[i]; ts2 += rs2[i]; }
    float mean = ts * (1.0f / EE);
    float var  = ts2 * (1.0f / EE) - mean * mean;
    float inv  = rsqrtf(var + EPSF);
    size_t rw = (size_t)row * EE;
    for (int i = threadIdx.x; i < EE; i += 256) {
        float y = (xr[i] - mean) * inv * g[i] + b[i];
        pk[rw + i] = __float2half_rn(y);
    }
}

// ---------------------------------------------------------------------------
extern "C" void kernel_launch(void* const* d_in, const int* in_sizes, int n_in,
                              void* d_out, int out_size) {
    const float* hs   = (const float*)d_in[0];
    const float* mask = (const float*)d_in[1];
    const float* wq   = (const float*)d_in[2];
    const float* bq   = (const float*)d_in[3];
    const float* wk   = (const float*)d_in[4];
    const float* bk   = (const float*)d_in[5];
    const float* wv   = (const float*)d_in[6];
    const float* bv   = (const float*)d_in[7];
    const float* wo   = (const float*)d_in[8];
    const float* bo   = (const float*)d_in[9];
    const float* ln1g = (const float*)d_in[10];
    const float* ln1b = (const float*)d_in[11];
    const float* ln2g = (const float*)d_in[12];
    const float* ln2b = (const float*)d_in[13];
    const float* w1   = (const float*)d_in[14];
    const float* b1   = (const float*)d_in[15];
    const float* w2   = (const float*)d_in[16];
    const float* b2   = (const float*)d_in[17];
    float* out = (float*)d_out;

    float *x, *bqkv;
    __half *h1, *h2, *qkv, *o, *m, *wqkv, *wo_, *w1_, *w2_;
    cudaGetSymbolAddress((void**)&x,    g_x);
    cudaGetSymbolAddress((void**)&bqkv, g_bqkv);
    cudaGetSymbolAddress((void**)&h1,   g_h1);
    cudaGetSymbolAddress((void**)&h2,   g_h2);
    cudaGetSymbolAddress((void**)&qkv,  g_qkv);
    cudaGetSymbolAddress((void**)&o,    g_o);
    cudaGetSymbolAddress((void**)&m,    g_m);
    cudaGetSymbolAddress((void**)&wqkv, g_wqkv);
    cudaGetSymbolAddress((void**)&wo_,  g_wo);
    cudaGetSymbolAddress((void**)&w1_,  g_w1);
    cudaGetSymbolAddress((void**)&w2_,  g_w2);

    cudaFuncSetAttribute(flash_attn, cudaFuncAttributeMaxDynamicSharedMemorySize, FA_SMEM);
    cudaFuncSetAttribute(mma_gemm<0>, cudaFuncAttributeMaxDynamicSharedMemorySize, GEMM_SMEM);
    cudaFuncSetAttribute(mma_gemm<1>, cudaFuncAttributeMaxDynamicSharedMemorySize, GEMM_SMEM);
    cudaFuncSetAttribute(mma_gemm<2>, cudaFuncAttributeMaxDynamicSharedMemorySize, GEMM_SMEM);

    dim3 tb(32, 8);
    transpose_pack1<<<dim3(EE/32, EE/32), tb>>>(wq, wqkv, EE, EE, 0);
    transpose_pack1<<<dim3(EE/32, EE/32), tb>>>(wk, wqkv, EE, EE, EE);
    transpose_pack1<<<dim3(EE/32, EE/32), tb>>>(wv, wqkv, EE, EE, 2*EE);
    transpose_pack1<<<dim3(EE/32, EE/32), tb>>>(wo, wo_, EE, EE, 0);
    transpose_pack1<<<dim3(II/32, EE/32), tb>>>(w1, w1_, EE, II, 0);
    transpose_pack1<<<dim3(EE/32, II/32), tb>>>(w2, w2_, II, EE, 0);
    bias_cat3<<<(NQKV + 255) / 256, 256>>>(bq, bk, bv, bqkv);

    // 1. LN1 -> plain fp16
    ln_h<<<MR, 256>>>(hs, ln1g, ln1b, h1);

    // 2. fused QKV projection (1-pass) -> qkv rows [q|k|v] (ldo = 2304)
    mma_gemm<0><<<dim3(NQKV/128, MR/128), 256, GEMM_SMEM>>>(
        h1, wqkv, bqkv, nullptr, nullptr, qkv, MR, NQKV, EE, EE, EE, NQKV);

    // 3. fused flash attention -> o (plain fp16)
    flash_attn<<<dim3(SS/128, BB*HH), 256, FA_SMEM>>>(qkv, mask, o);

    // 4. O-proj (1-pass) + residual(hs) -> x
    mma_gemm<2><<<dim3(EE/128, MR/128), 256, GEMM_SMEM>>>(
        o, wo_, bo, hs, x, nullptr, MR, EE, EE, EE, EE, EE);

    // 5. LN2 -> plain fp16
    ln_h<<<MR, 256>>>(x, ln2g, ln2b, h2);

    // 6. MLP up + gelu (1-pass) -> m (plain fp16)
    mma_gemm<1><<<dim3(II/128, MR/128), 256, GEMM_SMEM>>>(
        h2, w1_, b1, nullptr, nullptr, m, MR, II, EE, EE, EE, II);

    // 7. MLP down (1-pass) + residual(x) -> out
    mma_gemm<2><<<dim3(EE/128, MR/128), 256, GEMM_SMEM>>>(
        m, w2_, b2, x, out, nullptr, MR, EE, II, II, II, EE);
}

// round 16
// speedup vs baseline: 6.4056x; 1.0554x over previous
#include <cuda_runtime.h>
#include <cuda_fp16.h>
#include <math.h>
#include <stdint.h>

// ---------------------------------------------------------------------------
// SiglipEncoderLayer  B=8 S=1024 E=768 H=12 D=64 I=3072  fp32 in/out
// R16 (= R15 resubmission; first-attempt container flake, sync logic
// re-verified race/deadlock-free).
// Single-barrier GEMM mainloop + load/compute overlap; 3-stage flash ring;
// merged weight transposes. Numerics unchanged from R14.
// ---------------------------------------------------------------------------

#define BB   8
#define SS   1024
#define EE   768
#define HH   12
#define DD   64
#define II   3072
#define MR   (BB*SS)            // 8192
#define NQKV (3*EE)             // 2304
#define EPSF 1e-6f
#define SCALE_F 0.125f

// ---- scratch (device globals, 128B aligned) -------------------------------
__device__ __align__(128) float g_x [MR*EE];
__device__ __align__(128) float g_bqkv[NQKV];

__device__ __align__(128) __half g_h1 [(size_t)MR*EE];
__device__ __align__(128) __half g_h2 [(size_t)MR*EE];
__device__ __align__(128) __half g_qkv[(size_t)MR*NQKV];
__device__ __align__(128) __half g_o  [(size_t)MR*EE];
__device__ __align__(128) __half g_m  [(size_t)MR*II];

__device__ __align__(128) __half g_wqkv[(size_t)NQKV*EE];
__device__ __align__(128) __half g_wo [(size_t)EE*EE];
__device__ __align__(128) __half g_w1 [(size_t)II*EE];
__device__ __align__(128) __half g_w2 [(size_t)EE*II];

// ---------------------------------------------------------------------------
__device__ __forceinline__ uint32_t smem_u32(const void* p) {
    uint32_t a;
    asm("{ .reg .u64 t; cvta.to.shared.u64 t, %1; cvt.u32.u64 %0, t; }"
        : "=r"(a) : "l"(p));
    return a;
}
__device__ __forceinline__ void cp_async16(uint32_t s, const void* g) {
    asm volatile("cp.async.cg.shared.global [%0], [%1], 16;" :: "r"(s), "l"(g) : "memory");
}
#define CP_COMMIT() asm volatile("cp.async.commit_group;" ::: "memory")
#define CP_WAIT(n)  asm volatile("cp.async.wait_group %0;" :: "n"(n) : "memory")

__device__ __forceinline__ void ldsm4(uint32_t* r, uint32_t addr) {
    asm volatile("ldmatrix.sync.aligned.m8n8.x4.shared.b16 {%0,%1,%2,%3}, [%4];"
        : "=r"(r[0]), "=r"(r[1]), "=r"(r[2]), "=r"(r[3]) : "r"(addr));
}
__device__ __forceinline__ void ldsm4t(uint32_t* r, uint32_t addr) {
    asm volatile("ldmatrix.sync.aligned.m8n8.x4.trans.shared.b16 {%0,%1,%2,%3}, [%4];"
        : "=r"(r[0]), "=r"(r[1]), "=r"(r[2]), "=r"(r[3]) : "r"(addr));
}
__device__ __forceinline__ void mma16816(float* d, const uint32_t* a, const uint32_t* b) {
    asm volatile(
        "mma.sync.aligned.m16n8k16.row.col.f32.f16.f16.f32 "
        "{%0,%1,%2,%3}, {%4,%5,%6,%7}, {%8,%9}, {%0,%1,%2,%3};"
        : "+f"(d[0]), "+f"(d[1]), "+f"(d[2]), "+f"(d[3])
        : "r"(a[0]), "r"(a[1]), "r"(a[2]), "r"(a[3]), "r"(b[0]), "r"(b[1]));
}
__device__ __forceinline__ float gelu_tanh(float x) {
    float x3 = x * x * x;
    float t  = tanhf(0.7978845608028654f * (x + 0.044715f * x3));
    return 0.5f * x * (1.0f + t);
}
__device__ __forceinline__ uint32_t pack2h(float x, float y) {
    __half2 H = __halves2half2(__float2half_rn(x), __float2half_rn(y));
    return *reinterpret_cast<uint32_t*>(&H);
}

// ---------------------------------------------------------------------------
// mma.sync GEMM (fp16), 4-stage cp.async ring, ONE barrier per iter.
//   Safety: at iter c the barrier follows compute of iter c-1, so all warps
//   have finished reading slot (c-1)&3 == (c+3)&3 before its refill is issued.
//   MODE 0: opk plain = acc + bias                       (QKV-proj)
//   MODE 1: opk plain = gelu(acc + bias)                 (MLP up)
//   MODE 2: outf fp32 = acc + bias + res                 (O-proj, MLP down)
// ---------------------------------------------------------------------------
#define GEMM_NS    4
#define GEMM_STG   16384
#define GEMM_SMEM  (GEMM_NS * GEMM_STG)

template<int MODE>
__global__ __launch_bounds__(256, 2)
void mma_gemm(const __half* __restrict__ A,
              const __half* __restrict__ W,
              const float* __restrict__ bias, const float* __restrict__ res,
              float* __restrict__ outf, __half* __restrict__ opk,
              int M, int N, int KP, int lda, int ldw, int ldo) {
    extern __shared__ __align__(128) char smbuf[];

    const int tid  = threadIdx.x;
    const int wid  = tid >> 5;
    const int lane = tid & 31;
    const int wm   = wid & 3;
    const int wn   = wid >> 2;
    const int m0   = blockIdx.y * 128;
    const int n0   = blockIdx.x * 128;

    const uint32_t sb = smem_u32(smbuf);

    float acc[2][8][4];
    #pragma unroll
    for (int mf = 0; mf < 2; mf++)
        #pragma unroll
        for (int nf = 0; nf < 8; nf++)
            #pragma unroll
            for (int r = 0; r < 4; r++) acc[mf][nf][r] = 0.f;

    const int nc = KP >> 5;

    auto loadc = [&](int c, int s) {
        const int k0 = c << 5;
        uint32_t as = sb + (uint32_t)s * GEMM_STG;
        uint32_t bs = as + 8192u;
        #pragma unroll
        for (int i = 0; i < 2; i++) {
            int cid = tid + i * 256;
            int row = cid >> 2, ch = cid & 3;
            uint32_t soff = row * 64u + ((uint32_t)(ch ^ (row & 3)) << 4);
            cp_async16(as + soff, A + (size_t)(m0 + row) * lda + k0 + ch * 8);
            cp_async16(bs + soff, W + (size_t)(n0 + row) * ldw + k0 + ch * 8);
        }
    };

    #pragma unroll
    for (int p = 0; p < GEMM_NS - 1; p++) { loadc(p, p); CP_COMMIT(); }

    for (int c = 0; c < nc; c++) {
        CP_WAIT(GEMM_NS - 2);
        __syncthreads();

        // issue next stage load NOW (overlaps with mma below); slot is safe
        const int nxt = c + GEMM_NS - 1;
        if (nxt < nc) loadc(nxt, nxt & (GEMM_NS - 1));
        CP_COMMIT();

        const uint32_t as = sb + (uint32_t)(c & (GEMM_NS - 1)) * GEMM_STG;
        const uint32_t bs = as + 8192u;
        const int j = lane >> 3, r = lane & 7;

        #pragma unroll
        for (int ks = 0; ks < 2; ks++) {
            uint32_t af[2][4];
            #pragma unroll
            for (int mf = 0; mf < 2; mf++) {
                int row = wm * 32 + mf * 16 + (j & 1) * 8 + r;
                int kc  = ks * 2 + (j >> 1);
                ldsm4(af[mf], as + row * 64u + ((uint32_t)(kc ^ (row & 3)) << 4));
            }
            uint32_t bf[8][2];
            #pragma unroll
            for (int tp = 0; tp < 4; tp++) {
                int nrow = wn * 64 + tp * 16 + (j >> 1) * 8 + r;
                int kc   = ks * 2 + (j & 1);
                uint32_t t4[4];
                ldsm4(t4, bs + nrow * 64u + ((uint32_t)(kc ^ (nrow & 3)) << 4));
                bf[2*tp][0]   = t4[0]; bf[2*tp][1]   = t4[1];
                bf[2*tp+1][0] = t4[2]; bf[2*tp+1][1] = t4[3];
            }
            #pragma unroll
            for (int mf = 0; mf < 2; mf++)
                #pragma unroll
                for (int nf = 0; nf < 8; nf++)
                    mma16816(acc[mf][nf], af[mf], bf[nf]);
        }
        // no trailing barrier: next iter's barrier provides the ordering
    }

    const int gi = lane >> 2, ci = lane & 3;
    #pragma unroll
    for (int mf = 0; mf < 2; mf++) {
        int r0 = m0 + wm * 32 + mf * 16 + gi;
        #pragma unroll
        for (int nf = 0; nf < 8; nf++) {
            int col = n0 + wn * 64 + nf * 8 + ci * 2;
            float b0 = bias[col], b1 = bias[col + 1];
            float v00 = acc[mf][nf][0] + b0, v01 = acc[mf][nf][1] + b1;
            float v10 = acc[mf][nf][2] + b0, v11 = acc[mf][nf][3] + b1;
            if (MODE == 0 || MODE == 1) {
                if (MODE == 1) {
                    v00 = gelu_tanh(v00); v01 = gelu_tanh(v01);
                    v10 = gelu_tanh(v10); v11 = gelu_tanh(v11);
                }
                *reinterpret_cast<__half2*>(opk + (size_t)r0 * ldo + col) =
                    __halves2half2(__float2half_rn(v00), __float2half_rn(v01));
                *reinterpret_cast<__half2*>(opk + (size_t)(r0 + 8) * ldo + col) =
                    __halves2half2(__float2half_rn(v10), __float2half_rn(v11));
            } else {
                const float2 r00 = *reinterpret_cast<const float2*>(res + (size_t)r0 * N + col);
                const float2 r10 = *reinterpret_cast<const float2*>(res + (size_t)(r0 + 8) * N + col);
                v00 += r00.x; v01 += r00.y; v10 += r10.x; v11 += r10.y;
                *reinterpret_cast<float2*>(outf + (size_t)r0 * N + col)       = make_float2(v00, v01);
                *reinterpret_cast<float2*>(outf + (size_t)(r0 + 8) * N + col) = make_float2(v10, v11);
            }
        }
    }
}

// ---------------------------------------------------------------------------
// Fused flash attention (plain fp16 1-pass), 3-stage KV ring, one barrier/iter.
//   Stage (it+2)%3 refilled at iter it was last read at iter it-1; the barrier
//   at iter it follows that compute, so the refill is safe without a trailing
//   sync.
// ---------------------------------------------------------------------------
#define FA_STG  32768                   // K,V = 2 x 16KB
#define FA_NS   3
#define FA_SMEM (16384 + FA_NS*FA_STG)  // Q + 3 stages = 112 KB

__global__ __launch_bounds__(256, 1)
void flash_attn(const __half* __restrict__ QKV,
                const float* __restrict__ mask,
                __half* __restrict__ Op) {
    extern __shared__ __align__(128) char fsm[];
    const uint32_t sb = smem_u32(fsm);
    const int tid = threadIdx.x, wid = tid >> 5, lane = tid & 31;
    const int qt = blockIdx.x, bh = blockIdx.y;
    const int b = bh / HH, h = bh - b * HH;
    const int q0 = qt * 128;
    const int j = lane >> 3, r = lane & 7;
    const int gi = lane >> 2, ci = lane & 3;

    const int qoff = h * DD;
    const int koff = EE + h * DD;
    const int voff = 2 * EE + h * DD;

    const uint32_t sQ   = sb;
    const uint32_t stg0 = sb + 16384u;

    {
        const size_t rbase = (size_t)(b * SS + q0);
        #pragma unroll
        for (int i = 0; i < 4; i++) {
            int idx = tid + i * 256;
            int row = idx >> 3, ch = idx & 7;
            uint32_t d = row * 128u + ((uint32_t)(ch ^ (row & 7)) << 4);
            cp_async16(sQ + d, QKV + (rbase + row) * NQKV + qoff + ch * 8);
        }
    }
    auto loadKV = [&](int it, int st) {
        const size_t rbase = (size_t)(b * SS + it * 128);
        uint32_t base = stg0 + (uint32_t)st * FA_STG;
        #pragma unroll
        for (int i = 0; i < 4; i++) {
            int idx = tid + i * 256;
            int row = idx >> 3, ch = idx & 7;
            const __half* g = QKV + (rbase + row) * NQKV + ch * 8;
            uint32_t d = base + row * 128u + ((uint32_t)(ch ^ (row & 7)) << 4);
            cp_async16(d,          g + koff);    // K
            cp_async16(d + 16384u, g + voff);    // V
        }
    };

    loadKV(0, 0);
    CP_COMMIT();
    loadKV(1, 1);
    CP_COMMIT();

    float m0v = -1e30f, m1v = -1e30f, l0 = 0.f, l1 = 0.f;
    float o[8][4];
    #pragma unroll
    for (int nt = 0; nt < 8; nt++)
        #pragma unroll
        for (int t = 0; t < 4; t++) o[nt][t] = 0.f;

    const int NIT = SS / 128;       // 8
    for (int it = 0; it < NIT; it++) {
        CP_WAIT(1);                 // group `it` complete (Q rides with group 0)
        __syncthreads();

        if (it + 2 < NIT) loadKV(it + 2, (it + 2) % FA_NS);
        CP_COMMIT();

        const uint32_t kb = stg0 + (uint32_t)(it % FA_NS) * FA_STG;

        float s[16][4];
        #pragma unroll
        for (int t = 0; t < 16; t++)
            #pragma unroll
            for (int u = 0; u < 4; u++) s[t][u] = 0.f;

        #pragma unroll
        for (int kc = 0; kc < 4; kc++) {
            uint32_t af[4];
            int arow = wid * 16 + (j & 1) * 8 + r;
            int ach  = kc * 2 + (j >> 1);
            ldsm4(af, sQ + arow * 128u + ((uint32_t)(ach ^ (arow & 7)) << 4));
            #pragma unroll
            for (int nt2 = 0; nt2 < 8; nt2++) {
                int brow = nt2 * 16 + (j >> 1) * 8 + r;
                int bch  = kc * 2 + (j & 1);
                uint32_t t4[4];
                ldsm4(t4, kb + brow * 128u + ((uint32_t)(bch ^ (brow & 7)) << 4));
                uint32_t b0[2] = {t4[0], t4[1]}, b1[2] = {t4[2], t4[3]};
                mma16816(s[2*nt2],   af, b0);
                mma16816(s[2*nt2+1], af, b1);
            }
        }

        const float* mr0 = mask + ((size_t)b * SS + (q0 + wid * 16 + gi)) * SS + it * 128;
        const float* mr1 = mr0 + 8 * (size_t)SS;
        float mx0 = -1e30f, mx1 = -1e30f;
        #pragma unroll
        for (int t = 0; t < 16; t++) {
            float2 u0 = *reinterpret_cast<const float2*>(mr0 + t * 8 + ci * 2);
            float2 u1 = *reinterpret_cast<const float2*>(mr1 + t * 8 + ci * 2);
            s[t][0] = s[t][0] * SCALE_F + u0.x;
            s[t][1] = s[t][1] * SCALE_F + u0.y;
            s[t][2] = s[t][2] * SCALE_F + u1.x;
            s[t][3] = s[t][3] * SCALE_F + u1.y;
            mx0 = fmaxf(mx0, fmaxf(s[t][0], s[t][1]));
            mx1 = fmaxf(mx1, fmaxf(s[t][2], s[t][3]));
        }
        mx0 = fmaxf(mx0, __shfl_xor_sync(0xFFFFFFFFu, mx0, 1));
        mx0 = fmaxf(mx0, __shfl_xor_sync(0xFFFFFFFFu, mx0, 2));
        mx1 = fmaxf(mx1, __shfl_xor_sync(0xFFFFFFFFu, mx1, 1));
        mx1 = fmaxf(mx1, __shfl_xor_sync(0xFFFFFFFFu, mx1, 2));
        const float mn0 = fmaxf(m0v, mx0), mn1 = fmaxf(m1v, mx1);
        const float a0 = __expf(m0v - mn0), a1 = __expf(m1v - mn1);
        m0v = mn0; m1v = mn1;

        float ps0 = 0.f, ps1 = 0.f;
        #pragma unroll
        for (int t = 0; t < 16; t++) {
            s[t][0] = __expf(s[t][0] - mn0);
            s[t][1] = __expf(s[t][1] - mn0);
            s[t][2] = __expf(s[t][2] - mn1);
            s[t][3] = __expf(s[t][3] - mn1);
            ps0 += s[t][0] + s[t][1];
            ps1 += s[t][2] + s[t][3];
        }
        ps0 += __shfl_xor_sync(0xFFFFFFFFu, ps0, 1);
        ps0 += __shfl_xor_sync(0xFFFFFFFFu, ps0, 2);
        ps1 += __shfl_xor_sync(0xFFFFFFFFu, ps1, 1);
        ps1 += __shfl_xor_sync(0xFFFFFFFFu, ps1, 2);
        l0 = l0 * a0 + ps0;
        l1 = l1 * a1 + ps1;

        #pragma unroll
        for (int nt = 0; nt < 8; nt++) {
            o[nt][0] *= a0; o[nt][1] *= a0;
            o[nt][2] *= a1; o[nt][3] *= a1;
        }

        const uint32_t vh = kb + 16384u;
        #pragma unroll
        for (int kt = 0; kt < 8; kt++) {
            uint32_t ph[4];
            ph[0] = pack2h(s[2*kt][0],   s[2*kt][1]);
            ph[1] = pack2h(s[2*kt][2],   s[2*kt][3]);
            ph[2] = pack2h(s[2*kt+1][0], s[2*kt+1][1]);
            ph[3] = pack2h(s[2*kt+1][2], s[2*kt+1][3]);
            #pragma unroll
            for (int nt2 = 0; nt2 < 4; nt2++) {
                int vrow = kt * 16 + (j & 1) * 8 + r;
                int vch  = nt2 * 2 + (j >> 1);
                uint32_t sw = vrow * 128u + ((uint32_t)(vch ^ (vrow & 7)) << 4);
                uint32_t t4[4];
                ldsm4t(t4, vh + sw);
                uint32_t b0[2] = {t4[0], t4[1]}, b1[2] = {t4[2], t4[3]};
                mma16816(o[2*nt2],   ph, b0);
                mma16816(o[2*nt2+1], ph, b1);
            }
        }
        // no trailing barrier (3-stage ring makes it safe)
    }

    const float inv0 = 1.f / l0, inv1 = 1.f / l1;
    const int qrow = b * SS + q0 + wid * 16 + gi;
    #pragma unroll
    for (int nt = 0; nt < 8; nt++) {
        int col = h * DD + nt * 8 + ci * 2;
        *reinterpret_cast<__half2*>(Op + (size_t)qrow * EE + col) =
            __halves2half2(__float2half_rn(o[nt][0] * inv0),
                           __float2half_rn(o[nt][1] * inv0));
        *reinterpret_cast<__half2*>(Op + (size_t)(qrow + 8) * EE + col) =
            __halves2half2(__float2half_rn(o[nt][2] * inv1),
                           __float2half_rn(o[nt][3] * inv1));
    }
}

// ---------------------------------------------------------------------------
// merged E x E transposes: z=0..3 -> wq, wk, wv (into wqkv), wo (into wo_)
// ---------------------------------------------------------------------------
__global__ void transpose_eX4(const float* __restrict__ wq,
                              const float* __restrict__ wk,
                              const float* __restrict__ wv,
                              const float* __restrict__ wo,
                              __half* __restrict__ wqkv,
                              __half* __restrict__ wod) {
    __shared__ float t[32][33];
    int tx = threadIdx.x, ty = threadIdx.y;
    int k0 = blockIdx.y * 32, n0 = blockIdx.x * 32;
    int z = blockIdx.z;
    const float* W = (z == 0) ? wq : (z == 1) ? wk : (z == 2) ? wv : wo;
    __half* dst    = (z == 3) ? wod : wqkv;
    int row_off    = (z == 3) ? 0 : z * EE;
    #pragma unroll
    for (int jj = 0; jj < 4; jj++)
        t[ty + jj*8][tx] = W[(size_t)(k0 + ty + jj*8) * EE + n0 + tx];
    __syncthreads();
    #pragma unroll
    for (int jj = 0; jj < 4; jj++) {
        int nn = row_off + n0 + ty + jj*8;
        int kk = k0 + tx;
        dst[(size_t)nn * EE + kk] = __float2half_rn(t[tx][ty + jj*8]);
    }
}

// plain 1-term transpose: W[K,N] -> wp[N][K] fp16 (for w1, w2)
__global__ void transpose_pack1(const float* __restrict__ W,
                                __half* __restrict__ wp,
                                int K, int N) {
    __shared__ float t[32][33];
    int tx = threadIdx.x, ty = threadIdx.y;
    int k0 = blockIdx.y * 32, n0 = blockIdx.x * 32;
    #pragma unroll
    for (int jj = 0; jj < 4; jj++)
        t[ty + jj*8][tx] = W[(size_t)(k0 + ty + jj*8) * N + n0 + tx];
    __syncthreads();
    #pragma unroll
    for (int jj = 0; jj < 4; jj++) {
        int nn = n0 + ty + jj*8;
        int kk = k0 + tx;
        wp[(size_t)nn * K + kk] = __float2half_rn(t[tx][ty + jj*8]);
    }
}

// ---------------------------------------------------------------------------
__global__ void bias_cat3(const float* __restrict__ bq, const float* __restrict__ bk,
                          const float* __restrict__ bv, float* __restrict__ dst) {
    int i = blockIdx.x * 256 + threadIdx.x;
    if (i < NQKV)
        dst[i] = (i < EE) ? bq[i] : (i < 2*EE) ? bk[i - EE] : bv[i - 2*EE];
}

// ---------------------------------------------------------------------------
__global__ void ln_h(const float* __restrict__ x,
                     const float* __restrict__ g,
                     const float* __restrict__ b,
                     __half* __restrict__ pk) {
    int row = blockIdx.x;
    const float* xr = x + (size_t)row * EE;
    float s = 0.f, s2 = 0.f;
    for (int i = threadIdx.x; i < EE; i += 256) {
        float v = xr[i]; s += v; s2 += v * v;
    }
    __shared__ float rs[8], rs2[8];
    #pragma unroll
    for (int o = 16; o > 0; o >>= 1) {
        s  += __shfl_xor_sync(0xFFFFFFFFu, s,  o);
        s2 += __shfl_xor_sync(0xFFFFFFFFu, s2, o);
    }
    if ((threadIdx.x & 31) == 0) { rs[threadIdx.x>>5] = s; rs2[threadIdx.x>>5] = s2; }
    __syncthreads();
    float ts = 0.f, ts2 = 0.f;
    #pragma unroll
    for (int i = 0; i < 8; i++) { ts += rs[i]; ts2 += rs2[i]; }
    float mean = ts * (1.0f / EE);
    float var  = ts2 * (1.0f / EE) - mean * mean;
    float inv  = rsqrtf(var + EPSF);
    size_t rw = (size_t)row * EE;
    for (int i = threadIdx.x; i < EE; i += 256) {
        float y = (xr[i] - mean) * inv * g[i] + b[i];
        pk[rw + i] = __float2half_rn(y);
    }
}

// ---------------------------------------------------------------------------
extern "C" void kernel_launch(void* const* d_in, const int* in_sizes, int n_in,
                              void* d_out, int out_size) {
    const float* hs   = (const float*)d_in[0];
    const float* mask = (const float*)d_in[1];
    const float* wq   = (const float*)d_in[2];
    const float* bq   = (const float*)d_in[3];
    const float* wk   = (const float*)d_in[4];
    const float* bk   = (const float*)d_in[5];
    const float* wv   = (const float*)d_in[6];
    const float* bv   = (const float*)d_in[7];
    const float* wo   = (const float*)d_in[8];
    const float* bo   = (const float*)d_in[9];
    const float* ln1g = (const float*)d_in[10];
    const float* ln1b = (const float*)d_in[11];
    const float* ln2g = (const float*)d_in[12];
    const float* ln2b = (const float*)d_in[13];
    const float* w1   = (const float*)d_in[14];
    const float* b1   = (const float*)d_in[15];
    const float* w2   = (const float*)d_in[16];
    const float* b2   = (const float*)d_in[17];
    float* out = (float*)d_out;

    float *x, *bqkv;
    __half *h1, *h2, *qkv, *o, *m, *wqkv, *wo_, *w1_, *w2_;
    cudaGetSymbolAddress((void**)&x,    g_x);
    cudaGetSymbolAddress((void**)&bqkv, g_bqkv);
    cudaGetSymbolAddress((void**)&h1,   g_h1);
    cudaGetSymbolAddress((void**)&h2,   g_h2);
    cudaGetSymbolAddress((void**)&qkv,  g_qkv);
    cudaGetSymbolAddress((void**)&o,    g_o);
    cudaGetSymbolAddress((void**)&m,    g_m);
    cudaGetSymbolAddress((void**)&wqkv, g_wqkv);
    cudaGetSymbolAddress((void**)&wo_,  g_wo);
    cudaGetSymbolAddress((void**)&w1_,  g_w1);
    cudaGetSymbolAddress((void**)&w2_,  g_w2);

    cudaFuncSetAttribute(flash_attn, cudaFuncAttributeMaxDynamicSharedMemorySize, FA_SMEM);
    cudaFuncSetAttribute(mma_gemm<0>, cudaFuncAttributeMaxDynamicSharedMemorySize, GEMM_SMEM);
    cudaFuncSetAttribute(mma_gemm<1>, cudaFuncAttributeMaxDynamicSharedMemorySize, GEMM_SMEM);
    cudaFuncSetAttribute(mma_gemm<2>, cudaFuncAttributeMaxDynamicSharedMemorySize, GEMM_SMEM);

    dim3 tb(32, 8);
    transpose_eX4<<<dim3(EE/32, EE/32, 4), tb>>>(wq, wk, wv, wo, wqkv, wo_);
    transpose_pack1<<<dim3(II/32, EE/32), tb>>>(w1, w1_, EE, II);
    transpose_pack1<<<dim3(EE/32, II/32), tb>>>(w2, w2_, II, EE);
    bias_cat3<<<(NQKV + 255) / 256, 256>>>(bq, bk, bv, bqkv);

    // 1. LN1 -> plain fp16
    ln_h<<<MR, 256>>>(hs, ln1g, ln1b, h1);

    // 2. fused QKV projection (1-pass) -> qkv rows [q|k|v]
    mma_gemm<0><<<dim3(NQKV/128, MR/128), 256, GEMM_SMEM>>>(
        h1, wqkv, bqkv, nullptr, nullptr, qkv, MR, NQKV, EE, EE, EE, NQKV);

    // 3. fused flash attention -> o (plain fp16)
    flash_attn<<<dim3(SS/128, BB*HH), 256, FA_SMEM>>>(qkv, mask, o);

    // 4. O-proj (1-pass) + residual(hs) -> x
    mma_gemm<2><<<dim3(EE/128, MR/128), 256, GEMM_SMEM>>>(
        o, wo_, bo, hs, x, nullptr, MR, EE, EE, EE, EE, EE);

    // 5. LN2 -> plain fp16
    ln_h<<<MR, 256>>>(x, ln2g, ln2b, h2);

    // 6. MLP up + gelu (1-pass) -> m (plain fp16)
    mma_gemm<1><<<dim3(II/128, MR/128), 256, GEMM_SMEM>>>(
        h2, w1_, b1, nullptr, nullptr, m, MR, II, EE, EE, EE, II);

    // 7. MLP down (1-pass) + residual(x) -> out
    mma_gemm<2><<<dim3(EE/128, MR/128), 256, GEMM_SMEM>>>(
        m, w2_, b2, x, out, nullptr, MR, EE, II, II, II, EE);
}